// round 3
// baseline (speedup 1.0000x reference)
#include <cuda_runtime.h>
#include <math.h>

#define NN 5000
#define NE 80000
#define HD 128
#define NR 64
#define AS 12

#define PI_OVER_CUT 0.6283185307179586f

typedef unsigned long long ull;

__device__ __align__(16) float g_ZP[NN * HD];
__device__ __align__(16) float g_ZQ[NN * HD];
__device__ __align__(16) float g_acc[(size_t)NN * HD * AS];
__device__ __align__(16) float g_ln[NN * HD];
__device__ __align__(16) float g_nrm[NN * HD * 3];
__device__ __align__(16) float g_f[(size_t)NE * 384];   // GEMM output: [e][mat*128+h]
__device__ int g_hist[NN];
__device__ int g_cur[NN];
__device__ int g_perm[NE];

__device__ __forceinline__ void red4(float* p, float a, float b, float c, float d) {
    asm volatile("red.global.add.v4.f32 [%0], {%1,%2,%3,%4};"
                 :: "l"(p), "f"(a), "f"(b), "f"(c), "f"(d) : "memory");
}
__device__ __forceinline__ void red2(float* p, float a, float b) {
    asm volatile("red.global.add.v2.f32 [%0], {%1,%2};"
                 :: "l"(p), "f"(a), "f"(b) : "memory");
}
__device__ __forceinline__ ull pk2(float a, float b) {
    ull r;
    asm("mov.b64 %0, {%1,%2};" : "=l"(r) : "f"(a), "f"(b));
    return r;
}
__device__ __forceinline__ ull fma2(ull a, ull b, ull c) {
    ull d;
    asm("fma.rn.f32x2 %0, %1, %2, %3;" : "=l"(d) : "l"(a), "l"(b), "l"(c));
    return d;
}
__device__ __forceinline__ float silu_f(float x) { return x / (1.0f + expf(-x)); }

// ---------------- kA: zero accumulator + hist array ----------------
__global__ void kA_zero() {
    size_t n = (size_t)NN * HD * AS / 4;
    float4* p = (float4*)g_acc;
    for (size_t i = blockIdx.x * (size_t)blockDim.x + threadIdx.x; i < n;
         i += (size_t)gridDim.x * blockDim.x)
        p[i] = make_float4(0.f, 0.f, 0.f, 0.f);
    for (int i = blockIdx.x * blockDim.x + threadIdx.x; i < NN;
         i += gridDim.x * blockDim.x)
        g_hist[i] = 0;
}

// ---------------- k1: per-node ZP/ZQ + edge histogram ----------------
__global__ void k1_nodepre(const int* __restrict__ z, const float* __restrict__ emb,
                           const float* __restrict__ W_emb2,
                           const int* __restrict__ ei) {
    extern __shared__ float sm[];
    float* sWT = sm;             // [256][129] transposed W_emb2 (padded)
    float* sZ  = sm + 256 * 129;
    int t = threadIdx.x;
    // histogram (g_hist zeroed by kA in previous launch)
    for (int e = blockIdx.x * blockDim.x + t; e < NE; e += gridDim.x * blockDim.x)
        atomicAdd(&g_hist[ei[e]], 1);

    for (int i = t; i < HD * 2 * HD; i += 128) {
        int hh = i >> 8, k = i & 255;
        sWT[k * 129 + hh] = W_emb2[i];
    }
    for (int n = blockIdx.x; n < NN; n += gridDim.x) {
        __syncthreads();
        sZ[t] = emb[(size_t)z[n] * HD + t];
        __syncthreads();
        float zp0 = 0.f, zp1 = 0.f, zq0 = 0.f, zq1 = 0.f;
#pragma unroll 4
        for (int k = 0; k < HD; k += 2) {
            float a = sZ[k], b = sZ[k + 1];
            zp0 += sWT[k * 129 + t] * a;
            zp1 += sWT[(k + 1) * 129 + t] * b;
            zq0 += sWT[(k + 128) * 129 + t] * a;
            zq1 += sWT[(k + 129) * 129 + t] * b;
        }
        g_ZP[(size_t)n * HD + t] = zp0 + zp1;
        g_ZQ[(size_t)n * HD + t] = zq0 + zq1;
    }
}

// ---------------- scan: exclusive prefix over g_hist ----------------
__global__ void ks_scan() {
    __shared__ int wsum[32];
    __shared__ int carry;
    int t = threadIdx.x, lane = t & 31, wid = t >> 5;
    if (t == 0) carry = 0;
    __syncthreads();
    for (int c = 0; c < 5; c++) {
        int idx = c * 1024 + t;
        int v = (idx < NN) ? g_hist[idx] : 0;
        int x = v;
#pragma unroll
        for (int o = 1; o < 32; o <<= 1) {
            int y = __shfl_up_sync(0xffffffffu, x, o);
            if (lane >= o) x += y;
        }
        if (lane == 31) wsum[wid] = x;
        __syncthreads();
        if (wid == 0) {
            int s = wsum[lane];
#pragma unroll
            for (int o = 1; o < 32; o <<= 1) {
                int y = __shfl_up_sync(0xffffffffu, s, o);
                if (lane >= o) s += y;
            }
            wsum[lane] = s;
        }
        __syncthreads();
        int pref = carry + (wid ? wsum[wid - 1] : 0) + x - v;
        if (idx < NN) g_cur[idx] = pref;
        __syncthreads();
        if (t == 0) carry += wsum[31];
        __syncthreads();
    }
}

// ---------------- kg: dense GEMM  g_f[e, y*128+h] = sum_k Wd_y[h,k]*attr[e,k] --------
// grid (625, 3), 512 threads. Block tile: 128 edges x 128 h. Thread: 4e x 8h.
__global__ __launch_bounds__(512, 2) void kg_gemm(
    const float* __restrict__ eattr,
    const float* __restrict__ Wd1, const float* __restrict__ Wd2,
    const float* __restrict__ Wd3) {
    __shared__ float sA[128 * 64];   // e-major
    __shared__ float sW[64 * 132];   // k-major, padded
    const int t = threadIdx.x;
    const int e0 = blockIdx.x * 128;
    const float* W = (blockIdx.y == 0) ? Wd1 : ((blockIdx.y == 1) ? Wd2 : Wd3);

    // stage attr (linear copy, e-major preserved)
    {
        const float4* src = (const float4*)(eattr + (size_t)e0 * NR);
        float4* dst = (float4*)sA;
#pragma unroll
        for (int r = 0; r < 4; r++) dst[t + 512 * r] = src[t + 512 * r];
    }
    // stage W transposed: sW[k*132 + h] = W[h*64 + k]
    {
        const float4* src = (const float4*)W;
#pragma unroll
        for (int r = 0; r < 4; r++) {
            int i = t + 512 * r;           // i in [0,2048)
            float4 w4 = src[i];
            int h = i >> 4, k4 = (i & 15) * 4;
            sW[(k4 + 0) * 132 + h] = w4.x;
            sW[(k4 + 1) * 132 + h] = w4.y;
            sW[(k4 + 2) * 132 + h] = w4.z;
            sW[(k4 + 3) * 132 + h] = w4.w;
        }
    }
    __syncthreads();

    const int h0 = (t & 15) * 8;
    const int eb = (t >> 4) * 4;

    ull acc[4][4];
#pragma unroll
    for (int e = 0; e < 4; e++)
#pragma unroll
        for (int j = 0; j < 4; j++) acc[e][j] = 0ull;

#pragma unroll 4
    for (int k = 0; k < NR; k++) {
        ull w[4];
#pragma unroll
        for (int j = 0; j < 4; j++)
            w[j] = *(const ull*)&sW[k * 132 + h0 + 2 * j];
#pragma unroll
        for (int e = 0; e < 4; e++) {
            float a = sA[(eb + e) * 64 + k];
            ull ap = pk2(a, a);
#pragma unroll
            for (int j = 0; j < 4; j++) acc[e][j] = fma2(w[j], ap, acc[e][j]);
        }
    }

#pragma unroll
    for (int e = 0; e < 4; e++) {
        float* o = &g_f[(size_t)(e0 + eb + e) * 384 + blockIdx.y * 128 + h0];
#pragma unroll
        for (int j = 0; j < 4; j++) *(ull*)(o + 2 * j) = acc[e][j];
    }
}

// ---------------- scatter: build perm (edges sorted by src) ----------------
__global__ void ks_scatter(const int* __restrict__ ei) {
    int e = blockIdx.x * blockDim.x + threadIdx.x;
    if (e < NE) {
        int s = ei[e];
        int p = atomicAdd(&g_cur[s], 1);
        g_perm[p] = e;
    }
}

// ---------------- ke: epilogue — cutoff * Zij, geometry, aggregated REDs ----------
// 512 threads = 4 groups x 128 h, 64 sorted edges per block.
__global__ __launch_bounds__(512) void ke_epi(
    const int* __restrict__ ei, const float* __restrict__ ew,
    const float* __restrict__ evec,
    const float* __restrict__ b_emb2,
    const float* __restrict__ bd1, const float* __restrict__ bd2,
    const float* __restrict__ bd3) {
    __shared__ float sCut[64], sVx[64], sVy[64], sVz[64];
    __shared__ int sSrc[64], sDst[64], sPe[64];
    const int tid = threadIdx.x;
    const int e0 = blockIdx.x * 64;
    if (tid < 64) {
        int pe = g_perm[e0 + tid];
        sPe[tid] = pe;
        sSrc[tid] = ei[pe];
        sDst[tid] = ei[NE + pe];
        float w = ew[pe];
        sCut[tid] = (w < 5.0f) ? 0.5f * (cosf(w * PI_OVER_CUT) + 1.0f) : 0.0f;
        sVx[tid] = evec[3 * pe + 0];
        sVy[tid] = evec[3 * pe + 1];
        sVz[tid] = evec[3 * pe + 2];
    }
    __syncthreads();

    const int h = tid & 127;
    const int grp = tid >> 7;
    const float bemb = b_emb2[h];
    const float b1 = bd1[h], b2 = bd2[h], b3 = bd3[h];

    float racc[10];
#pragma unroll
    for (int c = 0; c < 10; c++) racc[c] = 0.f;
    int cur = sSrc[grp * 16];

#define FLUSH()                                                  \
    do {                                                         \
        float* p_ = &g_acc[((size_t)cur * HD + h) * AS];         \
        red4(p_, racc[0], racc[1], racc[2], racc[3]);            \
        red4(p_ + 4, racc[4], racc[5], racc[6], racc[7]);        \
        red2(p_ + 8, racc[8], racc[9]);                          \
    } while (0)

#pragma unroll 2
    for (int i = 0; i < 16; i++) {
        int e = grp * 16 + i;
        int pe = sPe[e];
        int s = sSrc[e], d = sDst[e];
        const float* fp = &g_f[(size_t)pe * 384 + h];
        float f1 = fp[0], f2 = fp[128], f3 = fp[256];
        float C = sCut[e] * (g_ZP[(size_t)s * HD + h] + g_ZQ[(size_t)d * HD + h] + bemb);
        f1 = (f1 + b1) * C;
        f2 = (f2 + b2) * C;
        f3 = (f3 + b3) * C;
        if (s != cur) {
            FLUSH();
#pragma unroll
            for (int c = 0; c < 10; c++) racc[c] = 0.f;
            cur = s;
        }
        float vx = sVx[e], vy = sVy[e], vz = sVz[e];
        racc[0] += f1;
        racc[1] += f2 * vx; racc[2] += f2 * vy; racc[3] += f2 * vz;
        float f3x = f3 * vx, f3y = f3 * vy, f3z = f3 * vz;
        racc[4] += f3x * vx; racc[5] += f3x * vy; racc[6] += f3x * vz;
        racc[7] += f3y * vy; racc[8] += f3y * vz; racc[9] += f3z * vz;
    }
    FLUSH();
#undef FLUSH
}

// ---------------- k3: tn + LayerNorm ----------------
__global__ void k3_tnln(const float* __restrict__ ln_g, const float* __restrict__ ln_b) {
    __shared__ float sred[4];
    __shared__ float sval;
    int n = blockIdx.x, h = threadIdx.x;
    const float* a = &g_acc[((size_t)n * HD + h) * AS];
    float4 p0 = *(const float4*)a;
    float4 p1 = *(const float4*)(a + 4);
    float2 p2 = *(const float2*)(a + 8);
    float s1 = p0.x, wx = p0.y, wy = p0.z, wz = p0.w;
    float mxx = p1.x, mxy = p1.y, mxz = p1.z, myy = p1.w, myz = p2.x, mzz = p2.y;
    float tr3 = (mxx + myy + mzz) * (1.0f / 3.0f);
    float dxx = s1 + mxx - tr3, dyy = s1 + myy - tr3, dzz = s1 + mzz - tr3;
    float t01 = mxy - wz, t10 = mxy + wz, t02 = mxz + wy;
    float t20 = mxz - wy, t12 = myz - wx, t21 = myz + wx;
    float tn = dxx * dxx + dyy * dyy + dzz * dzz + t01 * t01 + t10 * t10 +
               t02 * t02 + t20 * t20 + t12 * t12 + t21 * t21;

    float v = tn;
#pragma unroll
    for (int o = 16; o; o >>= 1) v += __shfl_xor_sync(0xffffffffu, v, o);
    if ((h & 31) == 0) sred[h >> 5] = v;
    __syncthreads();
    if (h == 0) sval = (sred[0] + sred[1] + sred[2] + sred[3]) * (1.0f / HD);
    __syncthreads();
    float mu = sval;
    float dv = tn - mu;
    v = dv * dv;
#pragma unroll
    for (int o = 16; o; o >>= 1) v += __shfl_xor_sync(0xffffffffu, v, o);
    __syncthreads();
    if ((h & 31) == 0) sred[h >> 5] = v;
    __syncthreads();
    if (h == 0) sval = rsqrtf((sred[0] + sred[1] + sred[2] + sred[3]) * (1.0f / HD) + 1e-5f);
    __syncthreads();
    g_ln[(size_t)n * HD + h] = dv * sval * ln_g[h] + ln_b[h];
}

// ---------------- k4: MLP (8 nodes / block) ----------------
__global__ __launch_bounds__(128) void k4_mlp(
    const float* __restrict__ Ws1, const float* __restrict__ bs1,
    const float* __restrict__ Ws2, const float* __restrict__ bs2) {
    __shared__ float sX[8 * HD];
    __shared__ float sY1[8 * 2 * HD];
    __shared__ float sW[16 * 385];
    int t = threadIdx.x;
    int nb = blockIdx.x * 8;
    for (int i = t; i < 8 * HD; i += 128) sX[i] = g_ln[(size_t)nb * HD + i];
    __syncthreads();

    float acc[8][2];
#pragma unroll
    for (int nl = 0; nl < 8; nl++) { acc[nl][0] = 0.f; acc[nl][1] = 0.f; }
    for (int h0 = 0; h0 < HD; h0 += 16) {
        for (int i = t; i < 256 * 16; i += 128) {
            int j = i >> 4, hh = i & 15;
            sW[hh * 385 + j] = Ws1[j * HD + h0 + hh];
        }
        __syncthreads();
#pragma unroll
        for (int hh = 0; hh < 16; hh++) {
            float w0 = sW[hh * 385 + t], w1 = sW[hh * 385 + 128 + t];
#pragma unroll
            for (int nl = 0; nl < 8; nl++) {
                float x = sX[nl * HD + h0 + hh];
                acc[nl][0] += w0 * x; acc[nl][1] += w1 * x;
            }
        }
        __syncthreads();
    }
    {
        float bb0 = bs1[t], bb1 = bs1[t + 128];
#pragma unroll
        for (int nl = 0; nl < 8; nl++) {
            sY1[nl * 256 + t]       = silu_f(acc[nl][0] + bb0);
            sY1[nl * 256 + 128 + t] = silu_f(acc[nl][1] + bb1);
        }
    }
    __syncthreads();

    float a2[8][3];
#pragma unroll
    for (int nl = 0; nl < 8; nl++) { a2[nl][0] = 0.f; a2[nl][1] = 0.f; a2[nl][2] = 0.f; }
    for (int k0 = 0; k0 < 256; k0 += 16) {
        for (int i = t; i < 384 * 16; i += 128) {
            int j = i >> 4, kk = i & 15;
            sW[kk * 385 + j] = Ws2[j * 256 + k0 + kk];
        }
        __syncthreads();
#pragma unroll
        for (int kk = 0; kk < 16; kk++) {
            float w0 = sW[kk * 385 + t], w1 = sW[kk * 385 + 128 + t], w2 = sW[kk * 385 + 256 + t];
#pragma unroll
            for (int nl = 0; nl < 8; nl++) {
                float x = sY1[nl * 256 + k0 + kk];
                a2[nl][0] += w0 * x; a2[nl][1] += w1 * x; a2[nl][2] += w2 * x;
            }
        }
        __syncthreads();
    }
    float c0 = bs2[t], c1 = bs2[t + 128], c2 = bs2[t + 256];
#pragma unroll
    for (int nl = 0; nl < 8; nl++) {
        size_t base = (size_t)(nb + nl) * 384;
        g_nrm[base + t]       = silu_f(a2[nl][0] + c0);
        g_nrm[base + 128 + t] = silu_f(a2[nl][1] + c1);
        g_nrm[base + 256 + t] = silu_f(a2[nl][2] + c2);
    }
}

// ---------------- k5: Wt transforms + output assembly (4 nodes / block) ----------------
__global__ __launch_bounds__(128) void k5_out(
    const float* __restrict__ Wt1, const float* __restrict__ Wt2,
    const float* __restrict__ Wt3, float* __restrict__ out) {
    extern __shared__ float sm[];
    float* sAcc = sm;                // [4][128][12]
    float* sWt  = sm + 4 * HD * AS;  // [16][389]
    int t  = threadIdx.x;
    int nb = blockIdx.x * 4;
    {
        const float4* src = (const float4*)&g_acc[(size_t)nb * HD * AS];
        float4* dst = (float4*)sAcc;
        for (int i = t; i < 4 * HD * 3; i += 128) dst[i] = src[i];
    }
    __syncthreads();

    float acc[4][10];
#pragma unroll
    for (int nl = 0; nl < 4; nl++)
#pragma unroll
        for (int c = 0; c < 10; c++) acc[nl][c] = 0.f;

    for (int h0 = 0; h0 < HD; h0 += 16) {
        for (int i = t; i < 3 * HD * 16; i += 128) {
            int m = i >> 11;
            int r = i & 2047;
            int g = r >> 4, hh = r & 15;
            const float* W = (m == 0) ? Wt1 : ((m == 1) ? Wt2 : Wt3);
            sWt[hh * 389 + m * 128 + g] = W[g * HD + h0 + hh];
        }
        __syncthreads();
#pragma unroll
        for (int hh = 0; hh < 16; hh++) {
            float w1 = sWt[hh * 389 + t], w2 = sWt[hh * 389 + 128 + t], w3 = sWt[hh * 389 + 256 + t];
#pragma unroll
            for (int nl = 0; nl < 4; nl++) {
                const float* ap = &sAcc[(nl * HD + h0 + hh) * AS];
                float4 p0 = *(const float4*)ap;
                float4 p1 = *(const float4*)(ap + 4);
                float2 p2 = *(const float2*)(ap + 8);
                acc[nl][0] += w1 * p0.x;
                acc[nl][1] += w2 * p0.y; acc[nl][2] += w2 * p0.z; acc[nl][3] += w2 * p0.w;
                acc[nl][4] += w3 * p1.x; acc[nl][5] += w3 * p1.y; acc[nl][6] += w3 * p1.z;
                acc[nl][7] += w3 * p1.w; acc[nl][8] += w3 * p2.x; acc[nl][9] += w3 * p2.y;
            }
        }
        __syncthreads();
    }

#pragma unroll
    for (int nl = 0; nl < 4; nl++) {
        int n = nb + nl;
        float n0 = g_nrm[(size_t)n * 384 + t * 3 + 0];
        float n1 = g_nrm[(size_t)n * 384 + t * 3 + 1];
        float n2 = g_nrm[(size_t)n * 384 + t * 3 + 2];
        float s1 = acc[nl][0], wx = acc[nl][1], wy = acc[nl][2], wz = acc[nl][3];
        float mxx = acc[nl][4], mxy = acc[nl][5], mxz = acc[nl][6];
        float myy = acc[nl][7], myz = acc[nl][8], mzz = acc[nl][9];
        float tr3 = (mxx + myy + mzz) * (1.0f / 3.0f);
        float dI = n0 * s1;
        float* o = out + ((size_t)n * HD + t) * 9;
        o[0] = dI + n2 * (mxx - tr3);
        o[1] = -n1 * wz + n2 * mxy;
        o[2] =  n1 * wy + n2 * mxz;
        o[3] =  n1 * wz + n2 * mxy;
        o[4] = dI + n2 * (myy - tr3);
        o[5] = -n1 * wx + n2 * myz;
        o[6] = -n1 * wy + n2 * mxz;
        o[7] =  n1 * wx + n2 * myz;
        o[8] = dI + n2 * (mzz - tr3);
    }
}

#define K1_SMEM ((256 * 129 + 128) * 4)
#define K5_SMEM ((4 * HD * AS + 16 * 389) * 4)

extern "C" void kernel_launch(void* const* d_in, const int* in_sizes, int n_in,
                              void* d_out, int out_size) {
    (void)in_sizes; (void)n_in; (void)out_size;
    const int*   z      = (const int*)d_in[0];
    const int*   ei     = (const int*)d_in[1];
    const float* ew     = (const float*)d_in[2];
    const float* evec   = (const float*)d_in[3];
    const float* eattr  = (const float*)d_in[4];
    const float* emb    = (const float*)d_in[5];
    const float* W_emb2 = (const float*)d_in[6];
    const float* b_emb2 = (const float*)d_in[7];
    const float* Wd1 = (const float*)d_in[8],  *bd1 = (const float*)d_in[9];
    const float* Wd2 = (const float*)d_in[10], *bd2 = (const float*)d_in[11];
    const float* Wd3 = (const float*)d_in[12], *bd3 = (const float*)d_in[13];
    const float* Wt1 = (const float*)d_in[14], *Wt2 = (const float*)d_in[15];
    const float* Wt3 = (const float*)d_in[16];
    const float* Ws1 = (const float*)d_in[17], *bs1 = (const float*)d_in[18];
    const float* Ws2 = (const float*)d_in[19], *bs2 = (const float*)d_in[20];
    const float* ln_g = (const float*)d_in[21], *ln_b = (const float*)d_in[22];
    float* out = (float*)d_out;

    cudaFuncSetAttribute(k1_nodepre, cudaFuncAttributeMaxDynamicSharedMemorySize, K1_SMEM);
    cudaFuncSetAttribute(k5_out,     cudaFuncAttributeMaxDynamicSharedMemorySize, K5_SMEM);

    kA_zero<<<512, 256>>>();                                   // 1
    k1_nodepre<<<160, 128, K1_SMEM>>>(z, emb, W_emb2, ei);     // 2 (also hist)
    ks_scan<<<1, 1024>>>();                                    // 3
    kg_gemm<<<dim3(NE / 128, 3), 512>>>(eattr, Wd1, Wd2, Wd3); // 4  <- profiled
    ks_scatter<<<(NE + 511) / 512, 512>>>(ei);                 // 5
    ke_epi<<<NE / 64, 512>>>(ei, ew, evec, b_emb2, bd1, bd2, bd3); // 6
    k3_tnln<<<NN, 128>>>(ln_g, ln_b);                          // 7
    k4_mlp<<<NN / 8, 128>>>(Ws1, bs1, Ws2, bs2);               // 8
    k5_out<<<NN / 4, 128, K5_SMEM>>>(Wt1, Wt2, Wt3, out);      // 9
}

// round 4
// speedup vs baseline: 1.0636x; 1.0636x over previous
#include <cuda_runtime.h>
#include <math.h>

#define NN 5000
#define NE 80000
#define HD 128
#define NR 64
#define AS 12

#define PI_OVER_CUT 0.6283185307179586f

typedef unsigned long long ull;

__device__ __align__(16) float g_ZP[NN * HD];
__device__ __align__(16) float g_ZQ[NN * HD];
__device__ __align__(16) float g_acc[(size_t)NN * HD * AS];   // zero-init; re-zeroed by kclean
__device__ __align__(16) float g_ln[NN * HD];
__device__ __align__(16) float g_nrm[NN * HD * 3];
__device__ __align__(16) float g_f[(size_t)NE * 384];
__device__ int g_hist[NN];                                    // zero-init; re-zeroed by kclean
__device__ int g_cur[NN];
__device__ int g_perm[NE];

__device__ __forceinline__ void red4(float* p, float a, float b, float c, float d) {
    asm volatile("red.global.add.v4.f32 [%0], {%1,%2,%3,%4};"
                 :: "l"(p), "f"(a), "f"(b), "f"(c), "f"(d) : "memory");
}
__device__ __forceinline__ void red2(float* p, float a, float b) {
    asm volatile("red.global.add.v2.f32 [%0], {%1,%2};"
                 :: "l"(p), "f"(a), "f"(b) : "memory");
}
__device__ __forceinline__ ull pk2(float a, float b) {
    ull r;
    asm("mov.b64 %0, {%1,%2};" : "=l"(r) : "f"(a), "f"(b));
    return r;
}
__device__ __forceinline__ ull fma2(ull a, ull b, ull c) {
    ull d;
    asm("fma.rn.f32x2 %0, %1, %2, %3;" : "=l"(d) : "l"(a), "l"(b), "l"(c));
    return d;
}
__device__ __forceinline__ float silu_f(float x) { return x / (1.0f + expf(-x)); }

// ---------------- k1: histogram + per-node ZP/ZQ (g_hist arrives zeroed) ----------------
__global__ void k1_nodepre(const int* __restrict__ z, const float* __restrict__ emb,
                           const float* __restrict__ W_emb2,
                           const int* __restrict__ ei) {
    extern __shared__ float sm[];
    float* sWT = sm;             // [256][129]
    float* sZ  = sm + 256 * 129;
    int t = threadIdx.x;
    for (int e = blockIdx.x * blockDim.x + t; e < NE; e += gridDim.x * blockDim.x)
        atomicAdd(&g_hist[ei[e]], 1);

    for (int i = t; i < HD * 2 * HD; i += 128) {
        int hh = i >> 8, k = i & 255;
        sWT[k * 129 + hh] = W_emb2[i];
    }
    for (int n = blockIdx.x; n < NN; n += gridDim.x) {
        __syncthreads();
        sZ[t] = emb[(size_t)z[n] * HD + t];
        __syncthreads();
        float zp0 = 0.f, zp1 = 0.f, zq0 = 0.f, zq1 = 0.f;
#pragma unroll 4
        for (int k = 0; k < HD; k += 2) {
            float a = sZ[k], b = sZ[k + 1];
            zp0 += sWT[k * 129 + t] * a;
            zp1 += sWT[(k + 1) * 129 + t] * b;
            zq0 += sWT[(k + 128) * 129 + t] * a;
            zq1 += sWT[(k + 129) * 129 + t] * b;
        }
        g_ZP[(size_t)n * HD + t] = zp0 + zp1;
        g_ZQ[(size_t)n * HD + t] = zq0 + zq1;
    }
}

// ---------------- scan: exclusive prefix over g_hist -> g_cur ----------------
__global__ void ks_scan() {
    __shared__ int wsum[32];
    __shared__ int carry;
    int t = threadIdx.x, lane = t & 31, wid = t >> 5;
    if (t == 0) carry = 0;
    __syncthreads();
    for (int c = 0; c < 5; c++) {
        int idx = c * 1024 + t;
        int v = (idx < NN) ? g_hist[idx] : 0;
        int x = v;
#pragma unroll
        for (int o = 1; o < 32; o <<= 1) {
            int y = __shfl_up_sync(0xffffffffu, x, o);
            if (lane >= o) x += y;
        }
        if (lane == 31) wsum[wid] = x;
        __syncthreads();
        if (wid == 0) {
            int s = wsum[lane];
#pragma unroll
            for (int o = 1; o < 32; o <<= 1) {
                int y = __shfl_up_sync(0xffffffffu, s, o);
                if (lane >= o) s += y;
            }
            wsum[lane] = s;
        }
        __syncthreads();
        int pref = carry + (wid ? wsum[wid - 1] : 0) + x - v;
        if (idx < NN) g_cur[idx] = pref;
        __syncthreads();
        if (t == 0) carry += wsum[31];
        __syncthreads();
    }
}

// ---------------- kg: GEMM (128e x 128h tile, 256 thr, 8e x 8h/thread) + scatter ----
__global__ __launch_bounds__(256, 2) void kg_gemm(
    const float* __restrict__ eattr,
    const float* __restrict__ Wd1, const float* __restrict__ Wd2,
    const float* __restrict__ Wd3, const int* __restrict__ ei) {
    __shared__ float sA[128 * 64];      // e-major, 32KB
    __shared__ float sWA[64 * 64];      // [k][hg*4+j] = W[hg*8+j][k],   16KB
    __shared__ float sWB[64 * 64];      // [k][hg*4+j] = W[hg*8+4+j][k], 16KB
    const int t = threadIdx.x;
    const int e0 = blockIdx.x * 128;
    const float* W = (blockIdx.y == 0) ? Wd1 : ((blockIdx.y == 1) ? Wd2 : Wd3);

    // scatter duty (one y-plane only); ready before ke_epi launch
    if (blockIdx.y == 1) {
        int e = blockIdx.x * 256 + t;
        if (e < NE) {
            int s = ei[e];
            int p = atomicAdd(&g_cur[s], 1);
            g_perm[p] = e;
        }
    }

    {
        const float4* src = (const float4*)(eattr + (size_t)e0 * NR);
        float4* dst = (float4*)sA;
#pragma unroll
        for (int r = 0; r < 8; r++) dst[t + 256 * r] = src[t + 256 * r];
    }
    {
        const float4* src = (const float4*)W;
#pragma unroll
        for (int r = 0; r < 8; r++) {
            int i = t + 256 * r;            // i in [0,2048)
            float4 w4 = src[i];
            int h = i >> 4, k4 = (i & 15) * 4;
            int hg = h >> 3, j = h & 7;
            float* base = (j < 4) ? sWA : sWB;
            int jj = j & 3;
            base[(k4 + 0) * 64 + hg * 4 + jj] = w4.x;
            base[(k4 + 1) * 64 + hg * 4 + jj] = w4.y;
            base[(k4 + 2) * 64 + hg * 4 + jj] = w4.z;
            base[(k4 + 3) * 64 + hg * 4 + jj] = w4.w;
        }
    }
    __syncthreads();

    const int hg = t & 15;
    const int h0 = hg * 8;
    const int eb = (t >> 4) * 8;

    ull acc[8][4];
#pragma unroll
    for (int e = 0; e < 8; e++)
#pragma unroll
        for (int j = 0; j < 4; j++) acc[e][j] = 0ull;

#pragma unroll 2
    for (int k = 0; k < NR; k++) {
        ulonglong2 wa = *(const ulonglong2*)&sWA[k * 64 + hg * 4];
        ulonglong2 wb = *(const ulonglong2*)&sWB[k * 64 + hg * 4];
        const float* arow = &sA[eb * 64 + k];
#pragma unroll
        for (int e = 0; e < 8; e++) {
            float a = arow[e * 64];
            ull ap = pk2(a, a);
            acc[e][0] = fma2(wa.x, ap, acc[e][0]);
            acc[e][1] = fma2(wa.y, ap, acc[e][1]);
            acc[e][2] = fma2(wb.x, ap, acc[e][2]);
            acc[e][3] = fma2(wb.y, ap, acc[e][3]);
        }
    }

#pragma unroll
    for (int e = 0; e < 8; e++) {
        float* o = &g_f[(size_t)(e0 + eb + e) * 384 + blockIdx.y * 128 + h0];
        ulonglong2 v0; v0.x = acc[e][0]; v0.y = acc[e][1];
        ulonglong2 v1; v1.x = acc[e][2]; v1.y = acc[e][3];
        *(ulonglong2*)o = v0;
        *(ulonglong2*)(o + 4) = v1;
    }
}

// ---------------- ke: epilogue (PROFILED SLOT #4) ----------------
__global__ __launch_bounds__(512) void ke_epi(
    const int* __restrict__ ei, const float* __restrict__ ew,
    const float* __restrict__ evec,
    const float* __restrict__ b_emb2,
    const float* __restrict__ bd1, const float* __restrict__ bd2,
    const float* __restrict__ bd3) {
    __shared__ float sCut[64], sVx[64], sVy[64], sVz[64];
    __shared__ int sSrc[64], sDst[64], sPe[64];
    const int tid = threadIdx.x;
    const int e0 = blockIdx.x * 64;
    if (tid < 64) {
        int pe = g_perm[e0 + tid];
        sPe[tid] = pe;
        sSrc[tid] = ei[pe];
        sDst[tid] = ei[NE + pe];
        float w = ew[pe];
        sCut[tid] = (w < 5.0f) ? 0.5f * (cosf(w * PI_OVER_CUT) + 1.0f) : 0.0f;
        sVx[tid] = evec[3 * pe + 0];
        sVy[tid] = evec[3 * pe + 1];
        sVz[tid] = evec[3 * pe + 2];
    }
    __syncthreads();

    const int h = tid & 127;
    const int grp = tid >> 7;
    const float bemb = b_emb2[h];
    const float b1 = bd1[h], b2 = bd2[h], b3 = bd3[h];

    float racc[10];
#pragma unroll
    for (int c = 0; c < 10; c++) racc[c] = 0.f;
    int cur = sSrc[grp * 16];

#define FLUSH()                                                  \
    do {                                                         \
        float* p_ = &g_acc[((size_t)cur * HD + h) * AS];         \
        red4(p_, racc[0], racc[1], racc[2], racc[3]);            \
        red4(p_ + 4, racc[4], racc[5], racc[6], racc[7]);        \
        red2(p_ + 8, racc[8], racc[9]);                          \
    } while (0)

#pragma unroll 2
    for (int i = 0; i < 16; i++) {
        int e = grp * 16 + i;
        int pe = sPe[e];
        int s = sSrc[e], d = sDst[e];
        const float* fp = &g_f[(size_t)pe * 384 + h];
        float f1 = fp[0], f2 = fp[128], f3 = fp[256];
        float C = sCut[e] * (g_ZP[(size_t)s * HD + h] + g_ZQ[(size_t)d * HD + h] + bemb);
        f1 = (f1 + b1) * C;
        f2 = (f2 + b2) * C;
        f3 = (f3 + b3) * C;
        if (s != cur) {
            FLUSH();
#pragma unroll
            for (int c = 0; c < 10; c++) racc[c] = 0.f;
            cur = s;
        }
        float vx = sVx[e], vy = sVy[e], vz = sVz[e];
        racc[0] += f1;
        racc[1] += f2 * vx; racc[2] += f2 * vy; racc[3] += f2 * vz;
        float f3x = f3 * vx, f3y = f3 * vy, f3z = f3 * vz;
        racc[4] += f3x * vx; racc[5] += f3x * vy; racc[6] += f3x * vz;
        racc[7] += f3y * vy; racc[8] += f3y * vz; racc[9] += f3z * vz;
    }
    FLUSH();
#undef FLUSH
}

// ---------------- k3: tn + LayerNorm ----------------
__global__ void k3_tnln(const float* __restrict__ ln_g, const float* __restrict__ ln_b) {
    __shared__ float sred[4];
    __shared__ float sval;
    int n = blockIdx.x, h = threadIdx.x;
    const float* a = &g_acc[((size_t)n * HD + h) * AS];
    float4 p0 = *(const float4*)a;
    float4 p1 = *(const float4*)(a + 4);
    float2 p2 = *(const float2*)(a + 8);
    float s1 = p0.x, wx = p0.y, wy = p0.z, wz = p0.w;
    float mxx = p1.x, mxy = p1.y, mxz = p1.z, myy = p1.w, myz = p2.x, mzz = p2.y;
    float tr3 = (mxx + myy + mzz) * (1.0f / 3.0f);
    float dxx = s1 + mxx - tr3, dyy = s1 + myy - tr3, dzz = s1 + mzz - tr3;
    float t01 = mxy - wz, t10 = mxy + wz, t02 = mxz + wy;
    float t20 = mxz - wy, t12 = myz - wx, t21 = myz + wx;
    float tn = dxx * dxx + dyy * dyy + dzz * dzz + t01 * t01 + t10 * t10 +
               t02 * t02 + t20 * t20 + t12 * t12 + t21 * t21;

    float v = tn;
#pragma unroll
    for (int o = 16; o; o >>= 1) v += __shfl_xor_sync(0xffffffffu, v, o);
    if ((h & 31) == 0) sred[h >> 5] = v;
    __syncthreads();
    if (h == 0) sval = (sred[0] + sred[1] + sred[2] + sred[3]) * (1.0f / HD);
    __syncthreads();
    float mu = sval;
    float dv = tn - mu;
    v = dv * dv;
#pragma unroll
    for (int o = 16; o; o >>= 1) v += __shfl_xor_sync(0xffffffffu, v, o);
    __syncthreads();
    if ((h & 31) == 0) sred[h >> 5] = v;
    __syncthreads();
    if (h == 0) sval = rsqrtf((sred[0] + sred[1] + sred[2] + sred[3]) * (1.0f / HD) + 1e-5f);
    __syncthreads();
    g_ln[(size_t)n * HD + h] = dv * sval * ln_g[h] + ln_b[h];
}

// ---------------- k4: MLP (8 nodes / block) ----------------
__global__ __launch_bounds__(128) void k4_mlp(
    const float* __restrict__ Ws1, const float* __restrict__ bs1,
    const float* __restrict__ Ws2, const float* __restrict__ bs2) {
    __shared__ float sX[8 * HD];
    __shared__ float sY1[8 * 2 * HD];
    __shared__ float sW[16 * 385];
    int t = threadIdx.x;
    int nb = blockIdx.x * 8;
    for (int i = t; i < 8 * HD; i += 128) sX[i] = g_ln[(size_t)nb * HD + i];
    __syncthreads();

    float acc[8][2];
#pragma unroll
    for (int nl = 0; nl < 8; nl++) { acc[nl][0] = 0.f; acc[nl][1] = 0.f; }
    for (int h0 = 0; h0 < HD; h0 += 16) {
        for (int i = t; i < 256 * 16; i += 128) {
            int j = i >> 4, hh = i & 15;
            sW[hh * 385 + j] = Ws1[j * HD + h0 + hh];
        }
        __syncthreads();
#pragma unroll
        for (int hh = 0; hh < 16; hh++) {
            float w0 = sW[hh * 385 + t], w1 = sW[hh * 385 + 128 + t];
#pragma unroll
            for (int nl = 0; nl < 8; nl++) {
                float x = sX[nl * HD + h0 + hh];
                acc[nl][0] += w0 * x; acc[nl][1] += w1 * x;
            }
        }
        __syncthreads();
    }
    {
        float bb0 = bs1[t], bb1 = bs1[t + 128];
#pragma unroll
        for (int nl = 0; nl < 8; nl++) {
            sY1[nl * 256 + t]       = silu_f(acc[nl][0] + bb0);
            sY1[nl * 256 + 128 + t] = silu_f(acc[nl][1] + bb1);
        }
    }
    __syncthreads();

    float a2[8][3];
#pragma unroll
    for (int nl = 0; nl < 8; nl++) { a2[nl][0] = 0.f; a2[nl][1] = 0.f; a2[nl][2] = 0.f; }
    for (int k0 = 0; k0 < 256; k0 += 16) {
        for (int i = t; i < 384 * 16; i += 128) {
            int j = i >> 4, kk = i & 15;
            sW[kk * 385 + j] = Ws2[j * 256 + k0 + kk];
        }
        __syncthreads();
#pragma unroll
        for (int kk = 0; kk < 16; kk++) {
            float w0 = sW[kk * 385 + t], w1 = sW[kk * 385 + 128 + t], w2 = sW[kk * 385 + 256 + t];
#pragma unroll
            for (int nl = 0; nl < 8; nl++) {
                float x = sY1[nl * 256 + k0 + kk];
                a2[nl][0] += w0 * x; a2[nl][1] += w1 * x; a2[nl][2] += w2 * x;
            }
        }
        __syncthreads();
    }
    float c0 = bs2[t], c1 = bs2[t + 128], c2 = bs2[t + 256];
#pragma unroll
    for (int nl = 0; nl < 8; nl++) {
        size_t base = (size_t)(nb + nl) * 384;
        g_nrm[base + t]       = silu_f(a2[nl][0] + c0);
        g_nrm[base + 128 + t] = silu_f(a2[nl][1] + c1);
        g_nrm[base + 256 + t] = silu_f(a2[nl][2] + c2);
    }
}

// ---------------- k5: Wt transforms + output assembly ----------------
__global__ __launch_bounds__(128) void k5_out(
    const float* __restrict__ Wt1, const float* __restrict__ Wt2,
    const float* __restrict__ Wt3, float* __restrict__ out) {
    extern __shared__ float sm[];
    float* sAcc = sm;                // [4][128][12]
    float* sWt  = sm + 4 * HD * AS;  // [16][389]
    int t  = threadIdx.x;
    int nb = blockIdx.x * 4;
    {
        const float4* src = (const float4*)&g_acc[(size_t)nb * HD * AS];
        float4* dst = (float4*)sAcc;
        for (int i = t; i < 4 * HD * 3; i += 128) dst[i] = src[i];
    }
    __syncthreads();

    float acc[4][10];
#pragma unroll
    for (int nl = 0; nl < 4; nl++)
#pragma unroll
        for (int c = 0; c < 10; c++) acc[nl][c] = 0.f;

    for (int h0 = 0; h0 < HD; h0 += 16) {
        for (int i = t; i < 3 * HD * 16; i += 128) {
            int m = i >> 11;
            int r = i & 2047;
            int g = r >> 4, hh = r & 15;
            const float* W = (m == 0) ? Wt1 : ((m == 1) ? Wt2 : Wt3);
            sWt[hh * 389 + m * 128 + g] = W[g * HD + h0 + hh];
        }
        __syncthreads();
#pragma unroll
        for (int hh = 0; hh < 16; hh++) {
            float w1 = sWt[hh * 389 + t], w2 = sWt[hh * 389 + 128 + t], w3 = sWt[hh * 389 + 256 + t];
#pragma unroll
            for (int nl = 0; nl < 4; nl++) {
                const float* ap = &sAcc[(nl * HD + h0 + hh) * AS];
                float4 p0 = *(const float4*)ap;
                float4 p1 = *(const float4*)(ap + 4);
                float2 p2 = *(const float2*)(ap + 8);
                acc[nl][0] += w1 * p0.x;
                acc[nl][1] += w2 * p0.y; acc[nl][2] += w2 * p0.z; acc[nl][3] += w2 * p0.w;
                acc[nl][4] += w3 * p1.x; acc[nl][5] += w3 * p1.y; acc[nl][6] += w3 * p1.z;
                acc[nl][7] += w3 * p1.w; acc[nl][8] += w3 * p2.x; acc[nl][9] += w3 * p2.y;
            }
        }
        __syncthreads();
    }

#pragma unroll
    for (int nl = 0; nl < 4; nl++) {
        int n = nb + nl;
        float n0 = g_nrm[(size_t)n * 384 + t * 3 + 0];
        float n1 = g_nrm[(size_t)n * 384 + t * 3 + 1];
        float n2 = g_nrm[(size_t)n * 384 + t * 3 + 2];
        float s1 = acc[nl][0], wx = acc[nl][1], wy = acc[nl][2], wz = acc[nl][3];
        float mxx = acc[nl][4], mxy = acc[nl][5], mxz = acc[nl][6];
        float myy = acc[nl][7], myz = acc[nl][8], mzz = acc[nl][9];
        float tr3 = (mxx + myy + mzz) * (1.0f / 3.0f);
        float dI = n0 * s1;
        float* o = out + ((size_t)n * HD + t) * 9;
        o[0] = dI + n2 * (mxx - tr3);
        o[1] = -n1 * wz + n2 * mxy;
        o[2] =  n1 * wy + n2 * mxz;
        o[3] =  n1 * wz + n2 * mxy;
        o[4] = dI + n2 * (myy - tr3);
        o[5] = -n1 * wx + n2 * myz;
        o[6] = -n1 * wy + n2 * mxz;
        o[7] =  n1 * wx + n2 * myz;
        o[8] = dI + n2 * (mzz - tr3);
    }
}

// ---------------- kclean: restore zero-state for the next replay ----------------
__global__ void kclean() {
    size_t n = (size_t)NN * HD * AS / 4;
    float4* p = (float4*)g_acc;
    for (size_t i = blockIdx.x * (size_t)blockDim.x + threadIdx.x; i < n;
         i += (size_t)gridDim.x * blockDim.x)
        p[i] = make_float4(0.f, 0.f, 0.f, 0.f);
    for (int i = blockIdx.x * blockDim.x + threadIdx.x; i < NN;
         i += gridDim.x * blockDim.x)
        g_hist[i] = 0;
}

#define K1_SMEM ((256 * 129 + 128) * 4)
#define K5_SMEM ((4 * HD * AS + 16 * 389) * 4)

extern "C" void kernel_launch(void* const* d_in, const int* in_sizes, int n_in,
                              void* d_out, int out_size) {
    (void)in_sizes; (void)n_in; (void)out_size;
    const int*   z      = (const int*)d_in[0];
    const int*   ei     = (const int*)d_in[1];
    const float* ew     = (const float*)d_in[2];
    const float* evec   = (const float*)d_in[3];
    const float* eattr  = (const float*)d_in[4];
    const float* emb    = (const float*)d_in[5];
    const float* W_emb2 = (const float*)d_in[6];
    const float* b_emb2 = (const float*)d_in[7];
    const float* Wd1 = (const float*)d_in[8],  *bd1 = (const float*)d_in[9];
    const float* Wd2 = (const float*)d_in[10], *bd2 = (const float*)d_in[11];
    const float* Wd3 = (const float*)d_in[12], *bd3 = (const float*)d_in[13];
    const float* Wt1 = (const float*)d_in[14], *Wt2 = (const float*)d_in[15];
    const float* Wt3 = (const float*)d_in[16];
    const float* Ws1 = (const float*)d_in[17], *bs1 = (const float*)d_in[18];
    const float* Ws2 = (const float*)d_in[19], *bs2 = (const float*)d_in[20];
    const float* ln_g = (const float*)d_in[21], *ln_b = (const float*)d_in[22];
    float* out = (float*)d_out;

    cudaFuncSetAttribute(k1_nodepre, cudaFuncAttributeMaxDynamicSharedMemorySize, K1_SMEM);
    cudaFuncSetAttribute(k5_out,     cudaFuncAttributeMaxDynamicSharedMemorySize, K5_SMEM);

    k1_nodepre<<<160, 128, K1_SMEM>>>(z, emb, W_emb2, ei);          // 1
    ks_scan<<<1, 1024>>>();                                         // 2
    kg_gemm<<<dim3(NE / 128, 3), 256>>>(eattr, Wd1, Wd2, Wd3, ei);  // 3 (+scatter)
    ke_epi<<<NE / 64, 512>>>(ei, ew, evec, b_emb2, bd1, bd2, bd3);  // 4 <- profiled
    k3_tnln<<<NN, 128>>>(ln_g, ln_b);                               // 5
    k4_mlp<<<NN / 8, 128>>>(Ws1, bs1, Ws2, bs2);                    // 6
    k5_out<<<NN / 4, 128, K5_SMEM>>>(Wt1, Wt2, Wt3, out);           // 7
    kclean<<<512, 256>>>();                                         // 8
}

// round 5
// speedup vs baseline: 1.2404x; 1.1663x over previous
#include <cuda_runtime.h>
#include <math.h>

#define NN 5000
#define NE 80000
#define HD 128
#define NR 64
#define AS 12
#define MZ 128

#define PI_OVER_CUT 0.6283185307179586f

typedef unsigned long long ull;

__device__ __align__(16) float g_ZPt[MZ * HD];   // table: W_L @ emb^T
__device__ __align__(16) float g_ZQt[MZ * HD];   // table: W_R @ emb^T
__device__ __align__(16) float g_acc[(size_t)NN * HD * AS];  // zero-init; re-zeroed by k5
__device__ __align__(16) float g_ln[NN * HD];
__device__ __align__(16) float g_nrm[NN * HD * 3];
__device__ __align__(16) float g_f[(size_t)NE * 384];
__device__ int g_hist[NN];                        // zero-init; re-zeroed by scatter
__device__ int g_cur[NN];
__device__ int g_perm[NE];

__device__ __forceinline__ void red4(float* p, float a, float b, float c, float d) {
    asm volatile("red.global.add.v4.f32 [%0], {%1,%2,%3,%4};"
                 :: "l"(p), "f"(a), "f"(b), "f"(c), "f"(d) : "memory");
}
__device__ __forceinline__ void red2(float* p, float a, float b) {
    asm volatile("red.global.add.v2.f32 [%0], {%1,%2};"
                 :: "l"(p), "f"(a), "f"(b) : "memory");
}
__device__ __forceinline__ ull pk2(float a, float b) {
    ull r;
    asm("mov.b64 %0, {%1,%2};" : "=l"(r) : "f"(a), "f"(b));
    return r;
}
__device__ __forceinline__ void unpk2(ull v, float& a, float& b) {
    asm("mov.b64 {%0,%1}, %2;" : "=f"(a), "=f"(b) : "l"(v));
}
__device__ __forceinline__ ull fma2(ull a, ull b, ull c) {
    ull d;
    asm("fma.rn.f32x2 %0, %1, %2, %3;" : "=l"(d) : "l"(a), "l"(b), "l"(c));
    return d;
}
__device__ __forceinline__ float silu_f(float x) { return x / (1.0f + expf(-x)); }

// ---------------- 1. khist ----------------
__global__ void khist(const int* __restrict__ ei) {
    int e = blockIdx.x * blockDim.x + threadIdx.x;
    if (e < NE) atomicAdd(&g_hist[ei[e]], 1);
}

// ---------------- 2. scan: exclusive prefix over g_hist -> g_cur ----------------
__global__ void ks_scan() {
    __shared__ int wsum[32];
    __shared__ int carry;
    int t = threadIdx.x, lane = t & 31, wid = t >> 5;
    if (t == 0) carry = 0;
    __syncthreads();
    for (int c = 0; c < 5; c++) {
        int idx = c * 1024 + t;
        int v = (idx < NN) ? g_hist[idx] : 0;
        int x = v;
#pragma unroll
        for (int o = 1; o < 32; o <<= 1) {
            int y = __shfl_up_sync(0xffffffffu, x, o);
            if (lane >= o) x += y;
        }
        if (lane == 31) wsum[wid] = x;
        __syncthreads();
        if (wid == 0) {
            int s = wsum[lane];
#pragma unroll
            for (int o = 1; o < 32; o <<= 1) {
                int y = __shfl_up_sync(0xffffffffu, s, o);
                if (lane >= o) s += y;
            }
            wsum[lane] = s;
        }
        __syncthreads();
        int pref = carry + (wid ? wsum[wid - 1] : 0) + x - v;
        if (idx < NN) g_cur[idx] = pref;
        __syncthreads();
        if (t == 0) carry += wsum[31];
        __syncthreads();
    }
}

// ---------------- 3. scatter (also re-zeroes g_hist for next replay) ----------------
__global__ void ks_scatter(const int* __restrict__ ei) {
    int e = blockIdx.x * blockDim.x + threadIdx.x;
    if (e < NE) {
        int s = ei[e];
        int p = atomicAdd(&g_cur[s], 1);
        g_perm[p] = e;
    }
    for (int i = e; i < NN; i += gridDim.x * blockDim.x) g_hist[i] = 0;
}

// ---------------- 4. kg: GEMM (128e x 128h tile, 256 thr, 8e x 8h/thread) --------
// PROFILED SLOT
__global__ __launch_bounds__(256, 2) void kg_gemm(
    const float* __restrict__ eattr,
    const float* __restrict__ Wd1, const float* __restrict__ Wd2,
    const float* __restrict__ Wd3) {
    extern __shared__ float smg[];
    float* sA  = smg;                 // [128 e][64 k]
    float* sWA = smg + 128 * 64;      // [64 k][68] cols hg*4+jj (h%8<4)
    float* sWB = sWA + 64 * 68;       // [64 k][68] cols hg*4+jj (h%8>=4)
    const int t = threadIdx.x;
    const int e0 = blockIdx.x * 128;
    const float* W = (blockIdx.y == 0) ? Wd1 : ((blockIdx.y == 1) ? Wd2 : Wd3);

    {
        const float4* src = (const float4*)(eattr + (size_t)e0 * NR);
        float4* dst = (float4*)sA;
#pragma unroll
        for (int r = 0; r < 8; r++) dst[t + 256 * r] = src[t + 256 * r];
    }
    {
        const float4* src = (const float4*)W;
#pragma unroll
        for (int r = 0; r < 8; r++) {
            int i = t + 256 * r;           // 0..2047
            int h = i & 127, kq = i >> 7;  // kq 0..15
            float4 w4 = src[h * 16 + kq];
            int hg = h >> 3, j = h & 7;
            float* arr = (j < 4) ? sWA : sWB;
            int col = hg * 4 + (j & 3);
            arr[(kq * 4 + 0) * 68 + col] = w4.x;
            arr[(kq * 4 + 1) * 68 + col] = w4.y;
            arr[(kq * 4 + 2) * 68 + col] = w4.z;
            arr[(kq * 4 + 3) * 68 + col] = w4.w;
        }
    }
    __syncthreads();

    const int hg = t & 15;
    const int h0 = hg * 8;
    const int eb = (t >> 4) * 8;

    ull acc[8][4];
#pragma unroll
    for (int e = 0; e < 8; e++)
#pragma unroll
        for (int j = 0; j < 4; j++) acc[e][j] = 0ull;

#pragma unroll 2
    for (int k = 0; k < NR; k++) {
        ulonglong2 wa = *(const ulonglong2*)&sWA[k * 68 + hg * 4];
        ulonglong2 wb = *(const ulonglong2*)&sWB[k * 68 + hg * 4];
        const float* arow = &sA[eb * 64 + k];
#pragma unroll
        for (int e = 0; e < 8; e++) {
            float a = arow[e * 64];
            ull ap = pk2(a, a);
            acc[e][0] = fma2(wa.x, ap, acc[e][0]);
            acc[e][1] = fma2(wa.y, ap, acc[e][1]);
            acc[e][2] = fma2(wb.x, ap, acc[e][2]);
            acc[e][3] = fma2(wb.y, ap, acc[e][3]);
        }
    }
    // layout per h: [h0+0,h0+1] from wa.x path? mapping: col hg*4+jj with j=h&7:
    // sWA cols hold h = hg*8 + {0,1,2,3}; sWB cols hold h = hg*8 + {4,5,6,7}.
#pragma unroll
    for (int e = 0; e < 8; e++) {
        float* o = &g_f[(size_t)(e0 + eb + e) * 384 + blockIdx.y * 128 + h0];
        ulonglong2 v0; v0.x = acc[e][0]; v0.y = acc[e][1];
        ulonglong2 v1; v1.x = acc[e][2]; v1.y = acc[e][3];
        *(ulonglong2*)o = v0;
        *(ulonglong2*)(o + 4) = v1;
    }
}

// ---------------- 5. k1z: ZPt/ZQt tables (z in [0,128)) ----------------
__global__ void k1z_tab(const float* __restrict__ emb, const float* __restrict__ W_emb2) {
    extern __shared__ float sm[];
    float* sWT = sm;               // [256][129]
    float* sE  = sm + 256 * 129;   // [2][128]
    int t = threadIdx.x;
    for (int i = t; i < HD * 2 * HD; i += 128) {
        int hh = i >> 8, k = i & 255;
        sWT[k * 129 + hh] = W_emb2[i];
    }
    for (int i = t; i < 2 * HD; i += 128)
        sE[i] = emb[(size_t)blockIdx.x * 2 * HD + i];
    __syncthreads();
#pragma unroll
    for (int j = 0; j < 2; j++) {
        int zz = blockIdx.x * 2 + j;
        float zp0 = 0.f, zp1 = 0.f, zq0 = 0.f, zq1 = 0.f;
#pragma unroll 4
        for (int k = 0; k < HD; k += 2) {
            float a = sE[j * HD + k], b = sE[j * HD + k + 1];
            zp0 += sWT[k * 129 + t] * a;
            zp1 += sWT[(k + 1) * 129 + t] * b;
            zq0 += sWT[(k + 128) * 129 + t] * a;
            zq1 += sWT[(k + 129) * 129 + t] * b;
        }
        g_ZPt[zz * HD + t] = zp0 + zp1;
        g_ZQt[zz * HD + t] = zq0 + zq1;
    }
}

// ---------------- 6. ke: epilogue ----------------
__global__ __launch_bounds__(512) void ke_epi(
    const int* __restrict__ ei, const float* __restrict__ ew,
    const float* __restrict__ evec, const int* __restrict__ z,
    const float* __restrict__ b_emb2,
    const float* __restrict__ bd1, const float* __restrict__ bd2,
    const float* __restrict__ bd3) {
    __shared__ float sCut[64], sVx[64], sVy[64], sVz[64];
    __shared__ int sSrc[64], sZs[64], sZd[64], sPe[64];
    const int tid = threadIdx.x;
    const int e0 = blockIdx.x * 64;
    if (tid < 64) {
        int pe = g_perm[e0 + tid];
        sPe[tid] = pe;
        int s = ei[pe], d = ei[NE + pe];
        sSrc[tid] = s;
        sZs[tid] = z[s];
        sZd[tid] = z[d];
        float w = ew[pe];
        sCut[tid] = (w < 5.0f) ? 0.5f * (cosf(w * PI_OVER_CUT) + 1.0f) : 0.0f;
        sVx[tid] = evec[3 * pe + 0];
        sVy[tid] = evec[3 * pe + 1];
        sVz[tid] = evec[3 * pe + 2];
    }
    __syncthreads();

    const int h = tid & 127;
    const int grp = tid >> 7;
    const float bemb = b_emb2[h];
    const float b1 = bd1[h], b2 = bd2[h], b3 = bd3[h];

    float racc[10];
#pragma unroll
    for (int c = 0; c < 10; c++) racc[c] = 0.f;
    int cur = sSrc[grp * 16];

#define FLUSH()                                                  \
    do {                                                         \
        float* p_ = &g_acc[((size_t)cur * HD + h) * AS];         \
        red4(p_, racc[0], racc[1], racc[2], racc[3]);            \
        red4(p_ + 4, racc[4], racc[5], racc[6], racc[7]);        \
        red2(p_ + 8, racc[8], racc[9]);                          \
    } while (0)

#pragma unroll 2
    for (int i = 0; i < 16; i++) {
        int e = grp * 16 + i;
        int pe = sPe[e];
        int s = sSrc[e];
        const float* fp = &g_f[(size_t)pe * 384 + h];
        float f1 = fp[0], f2 = fp[128], f3 = fp[256];
        float C = sCut[e] * (g_ZPt[sZs[e] * HD + h] + g_ZQt[sZd[e] * HD + h] + bemb);
        f1 = (f1 + b1) * C;
        f2 = (f2 + b2) * C;
        f3 = (f3 + b3) * C;
        if (s != cur) {
            FLUSH();
#pragma unroll
            for (int c = 0; c < 10; c++) racc[c] = 0.f;
            cur = s;
        }
        float vx = sVx[e], vy = sVy[e], vz = sVz[e];
        racc[0] += f1;
        racc[1] += f2 * vx; racc[2] += f2 * vy; racc[3] += f2 * vz;
        float f3x = f3 * vx, f3y = f3 * vy, f3z = f3 * vz;
        racc[4] += f3x * vx; racc[5] += f3x * vy; racc[6] += f3x * vz;
        racc[7] += f3y * vy; racc[8] += f3y * vz; racc[9] += f3z * vz;
    }
    FLUSH();
#undef FLUSH
}

// ---------------- 7. k3: tn + LayerNorm ----------------
__global__ void k3_tnln(const float* __restrict__ ln_g, const float* __restrict__ ln_b) {
    __shared__ float sred[4];
    __shared__ float sval;
    int n = blockIdx.x, h = threadIdx.x;
    const float* a = &g_acc[((size_t)n * HD + h) * AS];
    float4 p0 = *(const float4*)a;
    float4 p1 = *(const float4*)(a + 4);
    float2 p2 = *(const float2*)(a + 8);
    float s1 = p0.x, wx = p0.y, wy = p0.z, wz = p0.w;
    float mxx = p1.x, mxy = p1.y, mxz = p1.z, myy = p1.w, myz = p2.x, mzz = p2.y;
    float tr3 = (mxx + myy + mzz) * (1.0f / 3.0f);
    float dxx = s1 + mxx - tr3, dyy = s1 + myy - tr3, dzz = s1 + mzz - tr3;
    float t01 = mxy - wz, t10 = mxy + wz, t02 = mxz + wy;
    float t20 = mxz - wy, t12 = myz - wx, t21 = myz + wx;
    float tn = dxx * dxx + dyy * dyy + dzz * dzz + t01 * t01 + t10 * t10 +
               t02 * t02 + t20 * t20 + t12 * t12 + t21 * t21;

    float v = tn;
#pragma unroll
    for (int o = 16; o; o >>= 1) v += __shfl_xor_sync(0xffffffffu, v, o);
    if ((h & 31) == 0) sred[h >> 5] = v;
    __syncthreads();
    if (h == 0) sval = (sred[0] + sred[1] + sred[2] + sred[3]) * (1.0f / HD);
    __syncthreads();
    float mu = sval;
    float dv = tn - mu;
    v = dv * dv;
#pragma unroll
    for (int o = 16; o; o >>= 1) v += __shfl_xor_sync(0xffffffffu, v, o);
    __syncthreads();
    if ((h & 31) == 0) sred[h >> 5] = v;
    __syncthreads();
    if (h == 0) sval = rsqrtf((sred[0] + sred[1] + sred[2] + sred[3]) * (1.0f / HD) + 1e-5f);
    __syncthreads();
    g_ln[(size_t)n * HD + h] = dv * sval * ln_g[h] + ln_b[h];
}

// ---------------- 8. k4: MLP (8 nodes / block, f32x2) ----------------
__global__ __launch_bounds__(128) void k4_mlp(
    const float* __restrict__ Ws1, const float* __restrict__ bs1,
    const float* __restrict__ Ws2, const float* __restrict__ bs2) {
    __shared__ float sX[8 * HD];
    __shared__ float sY1[8 * 2 * HD];
    __shared__ float sW[16 * 385];
    int t = threadIdx.x;
    int nb = blockIdx.x * 8;
    for (int i = t; i < 8 * HD; i += 128) sX[i] = g_ln[(size_t)nb * HD + i];
    __syncthreads();

    ull acc[8];
#pragma unroll
    for (int nl = 0; nl < 8; nl++) acc[nl] = 0ull;
    for (int h0 = 0; h0 < HD; h0 += 16) {
        for (int i = t; i < 256 * 16; i += 128) {
            int j = i >> 4, hh = i & 15;
            sW[hh * 385 + j] = Ws1[j * HD + h0 + hh];
        }
        __syncthreads();
#pragma unroll
        for (int hh = 0; hh < 16; hh++) {
            float w0 = sW[hh * 385 + t], w1 = sW[hh * 385 + 128 + t];
            ull wp = pk2(w0, w1);
#pragma unroll
            for (int nl = 0; nl < 8; nl++) {
                float x = sX[nl * HD + h0 + hh];
                acc[nl] = fma2(wp, pk2(x, x), acc[nl]);
            }
        }
        __syncthreads();
    }
    {
        float bb0 = bs1[t], bb1 = bs1[t + 128];
#pragma unroll
        for (int nl = 0; nl < 8; nl++) {
            float a0, a1;
            unpk2(acc[nl], a0, a1);
            sY1[nl * 256 + t]       = silu_f(a0 + bb0);
            sY1[nl * 256 + 128 + t] = silu_f(a1 + bb1);
        }
    }
    __syncthreads();

    ull a01[8];
    float a2[8];
#pragma unroll
    for (int nl = 0; nl < 8; nl++) { a01[nl] = 0ull; a2[nl] = 0.f; }
    for (int k0 = 0; k0 < 256; k0 += 16) {
        for (int i = t; i < 384 * 16; i += 128) {
            int j = i >> 4, kk = i & 15;
            sW[kk * 385 + j] = Ws2[j * 256 + k0 + kk];
        }
        __syncthreads();
#pragma unroll
        for (int kk = 0; kk < 16; kk++) {
            float w0 = sW[kk * 385 + t], w1 = sW[kk * 385 + 128 + t], w2 = sW[kk * 385 + 256 + t];
            ull wp = pk2(w0, w1);
#pragma unroll
            for (int nl = 0; nl < 8; nl++) {
                float x = sY1[nl * 256 + k0 + kk];
                a01[nl] = fma2(wp, pk2(x, x), a01[nl]);
                a2[nl] += w2 * x;
            }
        }
        __syncthreads();
    }
    float c0 = bs2[t], c1 = bs2[t + 128], c2 = bs2[t + 256];
#pragma unroll
    for (int nl = 0; nl < 8; nl++) {
        float a0, a1;
        unpk2(a01[nl], a0, a1);
        size_t base = (size_t)(nb + nl) * 384;
        g_nrm[base + t]       = silu_f(a0 + c0);
        g_nrm[base + 128 + t] = silu_f(a1 + c1);
        g_nrm[base + 256 + t] = silu_f(a2[nl] + c2);
    }
}

// ---------------- 9. k5: Wt transforms + output (f32x2); re-zeroes g_acc -------
__global__ __launch_bounds__(128) void k5_out(
    const float* __restrict__ Wt1, const float* __restrict__ Wt2,
    const float* __restrict__ Wt3, float* __restrict__ out) {
    extern __shared__ float sm[];
    float* sAcc = sm;                // [4][128][12]
    float* sWt  = sm + 4 * HD * AS;  // [16][389]
    int t  = threadIdx.x;
    int nb = blockIdx.x * 4;
    {
        float4* gsrc = (float4*)&g_acc[(size_t)nb * HD * AS];
        float4* dst = (float4*)sAcc;
        for (int i = t; i < 4 * HD * 3; i += 128) dst[i] = gsrc[i];
        __syncthreads();
        // restore zero-state for next replay (this block owns this range)
        float4 zz = make_float4(0.f, 0.f, 0.f, 0.f);
        for (int i = t; i < 4 * HD * 3; i += 128) gsrc[i] = zz;
    }

    ull acc[4][5];
#pragma unroll
    for (int nl = 0; nl < 4; nl++)
#pragma unroll
        for (int c = 0; c < 5; c++) acc[nl][c] = 0ull;

    for (int h0 = 0; h0 < HD; h0 += 16) {
        for (int i = t; i < 3 * HD * 16; i += 128) {
            int m = i >> 11;
            int r = i & 2047;
            int g = r >> 4, hh = r & 15;
            const float* W = (m == 0) ? Wt1 : ((m == 1) ? Wt2 : Wt3);
            sWt[hh * 389 + m * 128 + g] = W[g * HD + h0 + hh];
        }
        __syncthreads();
#pragma unroll
        for (int hh = 0; hh < 16; hh++) {
            float w1 = sWt[hh * 389 + t], w2 = sWt[hh * 389 + 128 + t], w3 = sWt[hh * 389 + 256 + t];
            ull pw12 = pk2(w1, w2), pw22 = pk2(w2, w2), pw33 = pk2(w3, w3);
#pragma unroll
            for (int nl = 0; nl < 4; nl++) {
                const ull* ap = (const ull*)&sAcc[(nl * HD + h0 + hh) * AS];
                ulonglong2 q0 = *(const ulonglong2*)ap;        // (s1,wx),(wy,wz)
                ulonglong2 q1 = *(const ulonglong2*)(ap + 2);  // (mxx,mxy),(mxz,myy)
                ull q2 = ap[4];                                // (myz,mzz)
                acc[nl][0] = fma2(pw12, q0.x, acc[nl][0]);
                acc[nl][1] = fma2(pw22, q0.y, acc[nl][1]);
                acc[nl][2] = fma2(pw33, q1.x, acc[nl][2]);
                acc[nl][3] = fma2(pw33, q1.y, acc[nl][3]);
                acc[nl][4] = fma2(pw33, q2, acc[nl][4]);
            }
        }
        __syncthreads();
    }

#pragma unroll
    for (int nl = 0; nl < 4; nl++) {
        int n = nb + nl;
        float n0 = g_nrm[(size_t)n * 384 + t * 3 + 0];
        float n1 = g_nrm[(size_t)n * 384 + t * 3 + 1];
        float n2 = g_nrm[(size_t)n * 384 + t * 3 + 2];
        float s1, wx, wy, wz, mxx, mxy, mxz, myy, myz, mzz;
        unpk2(acc[nl][0], s1, wx);
        unpk2(acc[nl][1], wy, wz);
        unpk2(acc[nl][2], mxx, mxy);
        unpk2(acc[nl][3], mxz, myy);
        unpk2(acc[nl][4], myz, mzz);
        float tr3 = (mxx + myy + mzz) * (1.0f / 3.0f);
        float dI = n0 * s1;
        float* o = out + ((size_t)n * HD + t) * 9;
        o[0] = dI + n2 * (mxx - tr3);
        o[1] = -n1 * wz + n2 * mxy;
        o[2] =  n1 * wy + n2 * mxz;
        o[3] =  n1 * wz + n2 * mxy;
        o[4] = dI + n2 * (myy - tr3);
        o[5] = -n1 * wx + n2 * myz;
        o[6] = -n1 * wy + n2 * mxz;
        o[7] =  n1 * wx + n2 * myz;
        o[8] = dI + n2 * (mzz - tr3);
    }
}

#define KG_SMEM ((128 * 64 + 2 * 64 * 68) * 4)
#define K1Z_SMEM ((256 * 129 + 2 * 128) * 4)
#define K5_SMEM ((4 * HD * AS + 16 * 389) * 4)

extern "C" void kernel_launch(void* const* d_in, const int* in_sizes, int n_in,
                              void* d_out, int out_size) {
    (void)in_sizes; (void)n_in; (void)out_size;
    const int*   z      = (const int*)d_in[0];
    const int*   ei     = (const int*)d_in[1];
    const float* ew     = (const float*)d_in[2];
    const float* evec   = (const float*)d_in[3];
    const float* eattr  = (const float*)d_in[4];
    const float* emb    = (const float*)d_in[5];
    const float* W_emb2 = (const float*)d_in[6];
    const float* b_emb2 = (const float*)d_in[7];
    const float* Wd1 = (const float*)d_in[8],  *bd1 = (const float*)d_in[9];
    const float* Wd2 = (const float*)d_in[10], *bd2 = (const float*)d_in[11];
    const float* Wd3 = (const float*)d_in[12], *bd3 = (const float*)d_in[13];
    const float* Wt1 = (const float*)d_in[14], *Wt2 = (const float*)d_in[15];
    const float* Wt3 = (const float*)d_in[16];
    const float* Ws1 = (const float*)d_in[17], *bs1 = (const float*)d_in[18];
    const float* Ws2 = (const float*)d_in[19], *bs2 = (const float*)d_in[20];
    const float* ln_g = (const float*)d_in[21], *ln_b = (const float*)d_in[22];
    float* out = (float*)d_out;

    cudaFuncSetAttribute(kg_gemm, cudaFuncAttributeMaxDynamicSharedMemorySize, KG_SMEM);
    cudaFuncSetAttribute(k1z_tab, cudaFuncAttributeMaxDynamicSharedMemorySize, K1Z_SMEM);
    cudaFuncSetAttribute(k5_out,  cudaFuncAttributeMaxDynamicSharedMemorySize, K5_SMEM);

    khist<<<(NE + 511) / 512, 512>>>(ei);                              // 1
    ks_scan<<<1, 1024>>>();                                            // 2
    ks_scatter<<<(NE + 511) / 512, 512>>>(ei);                         // 3
    kg_gemm<<<dim3(NE / 128, 3), 256, KG_SMEM>>>(eattr, Wd1, Wd2, Wd3);// 4 <- profiled
    k1z_tab<<<64, 128, K1Z_SMEM>>>(emb, W_emb2);                       // 5
    ke_epi<<<NE / 64, 512>>>(ei, ew, evec, z, b_emb2, bd1, bd2, bd3);  // 6
    k3_tnln<<<NN, 128>>>(ln_g, ln_b);                                  // 7
    k4_mlp<<<NN / 8, 128>>>(Ws1, bs1, Ws2, bs2);                       // 8
    k5_out<<<NN / 4, 128, K5_SMEM>>>(Wt1, Wt2, Wt3, out);              // 9
}

// round 6
// speedup vs baseline: 1.4145x; 1.1403x over previous
#include <cuda_runtime.h>
#include <math.h>

#define NN 5000
#define NE 80000
#define HD 128
#define NR 64
#define AS 12
#define MZ 128

#define PI_OVER_CUT 0.6283185307179586f

typedef unsigned long long ull;

__device__ __align__(16) float g_ZPt[MZ * HD];
__device__ __align__(16) float g_ZQt[MZ * HD];
__device__ __align__(16) float g_acc[(size_t)NN * HD * AS];  // zero-init; re-zeroed by k5
__device__ __align__(16) float g_ln[NN * HD];
__device__ __align__(16) float g_y1[NN * 256];
__device__ __align__(16) float g_nrm[NN * HD * 3];
__device__ __align__(16) float g_f[(size_t)NE * 384];
__device__ int g_hist[NN];                        // zero-init; re-zeroed by scatter
__device__ int g_cur[NN];
__device__ int g_perm[NE];

__device__ __forceinline__ void red4(float* p, float a, float b, float c, float d) {
    asm volatile("red.global.add.v4.f32 [%0], {%1,%2,%3,%4};"
                 :: "l"(p), "f"(a), "f"(b), "f"(c), "f"(d) : "memory");
}
__device__ __forceinline__ void red2(float* p, float a, float b) {
    asm volatile("red.global.add.v2.f32 [%0], {%1,%2};"
                 :: "l"(p), "f"(a), "f"(b) : "memory");
}
__device__ __forceinline__ ull pk2(float a, float b) {
    ull r;
    asm("mov.b64 %0, {%1,%2};" : "=l"(r) : "f"(a), "f"(b));
    return r;
}
__device__ __forceinline__ void unpk2(ull v, float& a, float& b) {
    asm("mov.b64 {%0,%1}, %2;" : "=f"(a), "=f"(b) : "l"(v));
}
__device__ __forceinline__ ull fma2(ull a, ull b, ull c) {
    ull d;
    asm("fma.rn.f32x2 %0, %1, %2, %3;" : "=l"(d) : "l"(a), "l"(b), "l"(c));
    return d;
}
__device__ __forceinline__ float silu_f(float x) { return x / (1.0f + expf(-x)); }

// ---------------- khist ----------------
__global__ void khist(const int* __restrict__ ei) {
    int e = blockIdx.x * blockDim.x + threadIdx.x;
    if (e < NE) atomicAdd(&g_hist[ei[e]], 1);
}

// ---------------- scan ----------------
__global__ void ks_scan() {
    __shared__ int wsum[32];
    __shared__ int carry;
    int t = threadIdx.x, lane = t & 31, wid = t >> 5;
    if (t == 0) carry = 0;
    __syncthreads();
    for (int c = 0; c < 5; c++) {
        int idx = c * 1024 + t;
        int v = (idx < NN) ? g_hist[idx] : 0;
        int x = v;
#pragma unroll
        for (int o = 1; o < 32; o <<= 1) {
            int y = __shfl_up_sync(0xffffffffu, x, o);
            if (lane >= o) x += y;
        }
        if (lane == 31) wsum[wid] = x;
        __syncthreads();
        if (wid == 0) {
            int s = wsum[lane];
#pragma unroll
            for (int o = 1; o < 32; o <<= 1) {
                int y = __shfl_up_sync(0xffffffffu, s, o);
                if (lane >= o) s += y;
            }
            wsum[lane] = s;
        }
        __syncthreads();
        int pref = carry + (wid ? wsum[wid - 1] : 0) + x - v;
        if (idx < NN) g_cur[idx] = pref;
        __syncthreads();
        if (t == 0) carry += wsum[31];
        __syncthreads();
    }
}

// ---------------- scatter (re-zeroes g_hist) ----------------
__global__ void ks_scatter(const int* __restrict__ ei) {
    int e = blockIdx.x * blockDim.x + threadIdx.x;
    if (e < NE) {
        int s = ei[e];
        int p = atomicAdd(&g_cur[s], 1);
        g_perm[p] = e;
    }
    for (int i = e; i < NN; i += gridDim.x * blockDim.x) g_hist[i] = 0;
}

// ---------------- k4a: y1 = silu(Ws1 @ ln + bs1)  [256 thr, 8 nodes/blk] ------
// PROFILED (dummy run in slot 4)
__global__ __launch_bounds__(256) void k4a_gemm(
    const float* __restrict__ Ws1, const float* __restrict__ bs1) {
    __shared__ float sXT[HD * 8];        // [hh][nl]
    __shared__ float sW[32 * 257];       // [hh][j] chunk
    const int t = threadIdx.x;
    const int nb = blockIdx.x * 8;
    // stage X transposed
    for (int i = t; i < 8 * HD; i += 256) {
        int nl = i >> 7, hh = i & 127;
        sXT[hh * 8 + nl] = g_ln[(size_t)(nb + nl) * HD + hh];
    }
    ull acc[4];
#pragma unroll
    for (int c = 0; c < 4; c++) acc[c] = 0ull;

    for (int h0 = 0; h0 < HD; h0 += 32) {
        __syncthreads();
        // stage Ws1 chunk transposed: sW[hh][j] = Ws1[j*128 + h0+hh]
#pragma unroll
        for (int r = 0; r < 32; r++) {
            int i = t + 256 * r;
            int j = i >> 5, hh = i & 31;
            sW[hh * 257 + j] = Ws1[j * HD + h0 + hh];
        }
        __syncthreads();
#pragma unroll 4
        for (int hh = 0; hh < 32; hh++) {
            float w = sW[hh * 257 + t];
            ull wp = pk2(w, w);
            const ulonglong2* xp = (const ulonglong2*)&sXT[(h0 + hh) * 8];
            ulonglong2 x0 = xp[0], x1 = xp[1];
            acc[0] = fma2(wp, x0.x, acc[0]);
            acc[1] = fma2(wp, x0.y, acc[1]);
            acc[2] = fma2(wp, x1.x, acc[2]);
            acc[3] = fma2(wp, x1.y, acc[3]);
        }
    }
    float bb = bs1[t];
#pragma unroll
    for (int c = 0; c < 4; c++) {
        float a0, a1;
        unpk2(acc[c], a0, a1);
        g_y1[(size_t)(nb + 2 * c) * 256 + t]     = silu_f(a0 + bb);
        g_y1[(size_t)(nb + 2 * c + 1) * 256 + t] = silu_f(a1 + bb);
    }
}

// ---------------- k4b: nrm = silu(Ws2 @ y1 + bs2)  [384 thr, 8 nodes/blk] ------
__global__ __launch_bounds__(384) void k4b_gemm(
    const float* __restrict__ Ws2, const float* __restrict__ bs2) {
    extern __shared__ float smb[];
    float* sYT = smb;            // [256 kk][8 nl]
    float* sW  = smb + 256 * 8;  // [32 kk][385]
    const int t = threadIdx.x;
    const int nb = blockIdx.x * 8;
    for (int i = t; i < 8 * 256; i += 384) {
        int nl = i >> 8, kk = i & 255;
        sYT[kk * 8 + nl] = g_y1[(size_t)(nb + nl) * 256 + kk];
    }
    ull acc[4];
#pragma unroll
    for (int c = 0; c < 4; c++) acc[c] = 0ull;

    for (int k0 = 0; k0 < 256; k0 += 32) {
        __syncthreads();
#pragma unroll
        for (int r = 0; r < 32; r++) {
            int i = t + 384 * r;
            if (i < 32 * 384) {
                int j = i >> 5, kk = i & 31;
                sW[kk * 385 + j] = Ws2[j * 256 + k0 + kk];
            }
        }
        __syncthreads();
#pragma unroll 4
        for (int kk = 0; kk < 32; kk++) {
            float w = sW[kk * 385 + t];
            ull wp = pk2(w, w);
            const ulonglong2* xp = (const ulonglong2*)&sYT[(k0 + kk) * 8];
            ulonglong2 x0 = xp[0], x1 = xp[1];
            acc[0] = fma2(wp, x0.x, acc[0]);
            acc[1] = fma2(wp, x0.y, acc[1]);
            acc[2] = fma2(wp, x1.x, acc[2]);
            acc[3] = fma2(wp, x1.y, acc[3]);
        }
    }
    float bb = bs2[t];
#pragma unroll
    for (int c = 0; c < 4; c++) {
        float a0, a1;
        unpk2(acc[c], a0, a1);
        g_nrm[(size_t)(nb + 2 * c) * 384 + t]     = silu_f(a0 + bb);
        g_nrm[(size_t)(nb + 2 * c + 1) * 384 + t] = silu_f(a1 + bb);
    }
}

// ---------------- kg: GEMM (unchanged, measured 100.8us) ----------------
__global__ __launch_bounds__(256, 2) void kg_gemm(
    const float* __restrict__ eattr,
    const float* __restrict__ Wd1, const float* __restrict__ Wd2,
    const float* __restrict__ Wd3) {
    extern __shared__ float smg[];
    float* sA  = smg;
    float* sWA = smg + 128 * 64;
    float* sWB = sWA + 64 * 68;
    const int t = threadIdx.x;
    const int e0 = blockIdx.x * 128;
    const float* W = (blockIdx.y == 0) ? Wd1 : ((blockIdx.y == 1) ? Wd2 : Wd3);

    {
        const float4* src = (const float4*)(eattr + (size_t)e0 * NR);
        float4* dst = (float4*)sA;
#pragma unroll
        for (int r = 0; r < 8; r++) dst[t + 256 * r] = src[t + 256 * r];
    }
    {
        const float4* src = (const float4*)W;
#pragma unroll
        for (int r = 0; r < 8; r++) {
            int i = t + 256 * r;
            int h = i & 127, kq = i >> 7;
            float4 w4 = src[h * 16 + kq];
            int hg = h >> 3, j = h & 7;
            float* arr = (j < 4) ? sWA : sWB;
            int col = hg * 4 + (j & 3);
            arr[(kq * 4 + 0) * 68 + col] = w4.x;
            arr[(kq * 4 + 1) * 68 + col] = w4.y;
            arr[(kq * 4 + 2) * 68 + col] = w4.z;
            arr[(kq * 4 + 3) * 68 + col] = w4.w;
        }
    }
    __syncthreads();

    const int hg = t & 15;
    const int h0 = hg * 8;
    const int eb = (t >> 4) * 8;

    ull acc[8][4];
#pragma unroll
    for (int e = 0; e < 8; e++)
#pragma unroll
        for (int j = 0; j < 4; j++) acc[e][j] = 0ull;

#pragma unroll 2
    for (int k = 0; k < NR; k++) {
        ulonglong2 wa = *(const ulonglong2*)&sWA[k * 68 + hg * 4];
        ulonglong2 wb = *(const ulonglong2*)&sWB[k * 68 + hg * 4];
        const float* arow = &sA[eb * 64 + k];
#pragma unroll
        for (int e = 0; e < 8; e++) {
            float a = arow[e * 64];
            ull ap = pk2(a, a);
            acc[e][0] = fma2(wa.x, ap, acc[e][0]);
            acc[e][1] = fma2(wa.y, ap, acc[e][1]);
            acc[e][2] = fma2(wb.x, ap, acc[e][2]);
            acc[e][3] = fma2(wb.y, ap, acc[e][3]);
        }
    }
#pragma unroll
    for (int e = 0; e < 8; e++) {
        float* o = &g_f[(size_t)(e0 + eb + e) * 384 + blockIdx.y * 128 + h0];
        ulonglong2 v0; v0.x = acc[e][0]; v0.y = acc[e][1];
        ulonglong2 v1; v1.x = acc[e][2]; v1.y = acc[e][3];
        *(ulonglong2*)o = v0;
        *(ulonglong2*)(o + 4) = v1;
    }
}

// ---------------- k1z: ZPt/ZQt tables ----------------
__global__ void k1z_tab(const float* __restrict__ emb, const float* __restrict__ W_emb2) {
    extern __shared__ float sm[];
    float* sWT = sm;
    float* sE  = sm + 256 * 129;
    int t = threadIdx.x;
    for (int i = t; i < HD * 2 * HD; i += 128) {
        int hh = i >> 8, k = i & 255;
        sWT[k * 129 + hh] = W_emb2[i];
    }
    for (int i = t; i < 2 * HD; i += 128)
        sE[i] = emb[(size_t)blockIdx.x * 2 * HD + i];
    __syncthreads();
#pragma unroll
    for (int j = 0; j < 2; j++) {
        int zz = blockIdx.x * 2 + j;
        float zp0 = 0.f, zp1 = 0.f, zq0 = 0.f, zq1 = 0.f;
#pragma unroll 4
        for (int k = 0; k < HD; k += 2) {
            float a = sE[j * HD + k], b = sE[j * HD + k + 1];
            zp0 += sWT[k * 129 + t] * a;
            zp1 += sWT[(k + 1) * 129 + t] * b;
            zq0 += sWT[(k + 128) * 129 + t] * a;
            zq1 += sWT[(k + 129) * 129 + t] * b;
        }
        g_ZPt[zz * HD + t] = zp0 + zp1;
        g_ZQt[zz * HD + t] = zq0 + zq1;
    }
}

// ---------------- ke: epilogue (unchanged, measured ~42us) ----------------
__global__ __launch_bounds__(512) void ke_epi(
    const int* __restrict__ ei, const float* __restrict__ ew,
    const float* __restrict__ evec, const int* __restrict__ z,
    const float* __restrict__ b_emb2,
    const float* __restrict__ bd1, const float* __restrict__ bd2,
    const float* __restrict__ bd3) {
    __shared__ float sCut[64], sVx[64], sVy[64], sVz[64];
    __shared__ int sSrc[64], sZs[64], sZd[64], sPe[64];
    const int tid = threadIdx.x;
    const int e0 = blockIdx.x * 64;
    if (tid < 64) {
        int pe = g_perm[e0 + tid];
        sPe[tid] = pe;
        int s = ei[pe], d = ei[NE + pe];
        sSrc[tid] = s;
        sZs[tid] = z[s];
        sZd[tid] = z[d];
        float w = ew[pe];
        sCut[tid] = (w < 5.0f) ? 0.5f * (cosf(w * PI_OVER_CUT) + 1.0f) : 0.0f;
        sVx[tid] = evec[3 * pe + 0];
        sVy[tid] = evec[3 * pe + 1];
        sVz[tid] = evec[3 * pe + 2];
    }
    __syncthreads();

    const int h = tid & 127;
    const int grp = tid >> 7;
    const float bemb = b_emb2[h];
    const float b1 = bd1[h], b2 = bd2[h], b3 = bd3[h];

    float racc[10];
#pragma unroll
    for (int c = 0; c < 10; c++) racc[c] = 0.f;
    int cur = sSrc[grp * 16];

#define FLUSH()                                                  \
    do {                                                         \
        float* p_ = &g_acc[((size_t)cur * HD + h) * AS];         \
        red4(p_, racc[0], racc[1], racc[2], racc[3]);            \
        red4(p_ + 4, racc[4], racc[5], racc[6], racc[7]);        \
        red2(p_ + 8, racc[8], racc[9]);                          \
    } while (0)

#pragma unroll 2
    for (int i = 0; i < 16; i++) {
        int e = grp * 16 + i;
        int pe = sPe[e];
        int s = sSrc[e];
        const float* fp = &g_f[(size_t)pe * 384 + h];
        float f1 = fp[0], f2 = fp[128], f3 = fp[256];
        float C = sCut[e] * (g_ZPt[sZs[e] * HD + h] + g_ZQt[sZd[e] * HD + h] + bemb);
        f1 = (f1 + b1) * C;
        f2 = (f2 + b2) * C;
        f3 = (f3 + b3) * C;
        if (s != cur) {
            FLUSH();
#pragma unroll
            for (int c = 0; c < 10; c++) racc[c] = 0.f;
            cur = s;
        }
        float vx = sVx[e], vy = sVy[e], vz = sVz[e];
        racc[0] += f1;
        racc[1] += f2 * vx; racc[2] += f2 * vy; racc[3] += f2 * vz;
        float f3x = f3 * vx, f3y = f3 * vy, f3z = f3 * vz;
        racc[4] += f3x * vx; racc[5] += f3x * vy; racc[6] += f3x * vz;
        racc[7] += f3y * vy; racc[8] += f3y * vz; racc[9] += f3z * vz;
    }
    FLUSH();
#undef FLUSH
}

// ---------------- k3: tn + LayerNorm (unchanged) ----------------
__global__ void k3_tnln(const float* __restrict__ ln_g, const float* __restrict__ ln_b) {
    __shared__ float sred[4];
    __shared__ float sval;
    int n = blockIdx.x, h = threadIdx.x;
    const float* a = &g_acc[((size_t)n * HD + h) * AS];
    float4 p0 = *(const float4*)a;
    float4 p1 = *(const float4*)(a + 4);
    float2 p2 = *(const float2*)(a + 8);
    float s1 = p0.x, wx = p0.y, wy = p0.z, wz = p0.w;
    float mxx = p1.x, mxy = p1.y, mxz = p1.z, myy = p1.w, myz = p2.x, mzz = p2.y;
    float tr3 = (mxx + myy + mzz) * (1.0f / 3.0f);
    float dxx = s1 + mxx - tr3, dyy = s1 + myy - tr3, dzz = s1 + mzz - tr3;
    float t01 = mxy - wz, t10 = mxy + wz, t02 = mxz + wy;
    float t20 = mxz - wy, t12 = myz - wx, t21 = myz + wx;
    float tn = dxx * dxx + dyy * dyy + dzz * dzz + t01 * t01 + t10 * t10 +
               t02 * t02 + t20 * t20 + t12 * t12 + t21 * t21;

    float v = tn;
#pragma unroll
    for (int o = 16; o; o >>= 1) v += __shfl_xor_sync(0xffffffffu, v, o);
    if ((h & 31) == 0) sred[h >> 5] = v;
    __syncthreads();
    if (h == 0) sval = (sred[0] + sred[1] + sred[2] + sred[3]) * (1.0f / HD);
    __syncthreads();
    float mu = sval;
    float dv = tn - mu;
    v = dv * dv;
#pragma unroll
    for (int o = 16; o; o >>= 1) v += __shfl_xor_sync(0xffffffffu, v, o);
    __syncthreads();
    if ((h & 31) == 0) sred[h >> 5] = v;
    __syncthreads();
    if (h == 0) sval = rsqrtf((sred[0] + sred[1] + sred[2] + sred[3]) * (1.0f / HD) + 1e-5f);
    __syncthreads();
    g_ln[(size_t)n * HD + h] = dv * sval * ln_g[h] + ln_b[h];
}

// ---------------- k5: Wt transforms + output (256 thr, 8 nodes/blk) -------
__global__ __launch_bounds__(256) void k5_out(
    const float* __restrict__ Wt1, const float* __restrict__ Wt2,
    const float* __restrict__ Wt3, float* __restrict__ out) {
    extern __shared__ float sm[];
    float* sAcc = sm;                // [8][128][12]
    float* sWt  = sm + 8 * HD * AS;  // [16][389]
    int t  = threadIdx.x;
    int nb = blockIdx.x * 8;
    {
        float4* gsrc = (float4*)&g_acc[(size_t)nb * HD * AS];
        float4* dst = (float4*)sAcc;
        for (int i = t; i < 8 * HD * 3; i += 256) dst[i] = gsrc[i];
        __syncthreads();
        float4 zz = make_float4(0.f, 0.f, 0.f, 0.f);
        for (int i = t; i < 8 * HD * 3; i += 256) gsrc[i] = zz;
    }

    const int g = t & 127;
    const int half = t >> 7;   // node group: nl in [half*4, half*4+4)

    ull acc[4][5];
#pragma unroll
    for (int nl = 0; nl < 4; nl++)
#pragma unroll
        for (int c = 0; c < 5; c++) acc[nl][c] = 0ull;

    for (int h0 = 0; h0 < HD; h0 += 16) {
        __syncthreads();
        for (int i = t; i < 3 * HD * 16; i += 256) {
            int m = i >> 11;
            int r = i & 2047;
            int gg = r >> 4, hh = r & 15;
            const float* W = (m == 0) ? Wt1 : ((m == 1) ? Wt2 : Wt3);
            sWt[hh * 389 + m * 128 + gg] = W[gg * HD + h0 + hh];
        }
        __syncthreads();
#pragma unroll
        for (int hh = 0; hh < 16; hh++) {
            float w1 = sWt[hh * 389 + g], w2 = sWt[hh * 389 + 128 + g], w3 = sWt[hh * 389 + 256 + g];
            ull pw12 = pk2(w1, w2), pw22 = pk2(w2, w2), pw33 = pk2(w3, w3);
#pragma unroll
            for (int nl = 0; nl < 4; nl++) {
                const ull* ap = (const ull*)&sAcc[((half * 4 + nl) * HD + h0 + hh) * AS];
                ulonglong2 q0 = *(const ulonglong2*)ap;
                ulonglong2 q1 = *(const ulonglong2*)(ap + 2);
                ull q2 = ap[4];
                acc[nl][0] = fma2(pw12, q0.x, acc[nl][0]);
                acc[nl][1] = fma2(pw22, q0.y, acc[nl][1]);
                acc[nl][2] = fma2(pw33, q1.x, acc[nl][2]);
                acc[nl][3] = fma2(pw33, q1.y, acc[nl][3]);
                acc[nl][4] = fma2(pw33, q2, acc[nl][4]);
            }
        }
    }

#pragma unroll
    for (int nl = 0; nl < 4; nl++) {
        int n = nb + half * 4 + nl;
        float n0 = g_nrm[(size_t)n * 384 + g * 3 + 0];
        float n1 = g_nrm[(size_t)n * 384 + g * 3 + 1];
        float n2 = g_nrm[(size_t)n * 384 + g * 3 + 2];
        float s1, wx, wy, wz, mxx, mxy, mxz, myy, myz, mzz;
        unpk2(acc[nl][0], s1, wx);
        unpk2(acc[nl][1], wy, wz);
        unpk2(acc[nl][2], mxx, mxy);
        unpk2(acc[nl][3], mxz, myy);
        unpk2(acc[nl][4], myz, mzz);
        float tr3 = (mxx + myy + mzz) * (1.0f / 3.0f);
        float dI = n0 * s1;
        float* o = out + ((size_t)n * HD + g) * 9;
        o[0] = dI + n2 * (mxx - tr3);
        o[1] = -n1 * wz + n2 * mxy;
        o[2] =  n1 * wy + n2 * mxz;
        o[3] =  n1 * wz + n2 * mxy;
        o[4] = dI + n2 * (myy - tr3);
        o[5] = -n1 * wx + n2 * myz;
        o[6] = -n1 * wy + n2 * mxz;
        o[7] =  n1 * wx + n2 * myz;
        o[8] = dI + n2 * (mzz - tr3);
    }
}

#define KG_SMEM ((128 * 64 + 2 * 64 * 68) * 4)
#define K1Z_SMEM ((256 * 129 + 2 * 128) * 4)
#define K4B_SMEM ((256 * 8 + 32 * 385) * 4)
#define K5_SMEM ((8 * HD * AS + 16 * 389) * 4)

extern "C" void kernel_launch(void* const* d_in, const int* in_sizes, int n_in,
                              void* d_out, int out_size) {
    (void)in_sizes; (void)n_in; (void)out_size;
    const int*   z      = (const int*)d_in[0];
    const int*   ei     = (const int*)d_in[1];
    const float* ew     = (const float*)d_in[2];
    const float* evec   = (const float*)d_in[3];
    const float* eattr  = (const float*)d_in[4];
    const float* emb    = (const float*)d_in[5];
    const float* W_emb2 = (const float*)d_in[6];
    const float* b_emb2 = (const float*)d_in[7];
    const float* Wd1 = (const float*)d_in[8],  *bd1 = (const float*)d_in[9];
    const float* Wd2 = (const float*)d_in[10], *bd2 = (const float*)d_in[11];
    const float* Wd3 = (const float*)d_in[12], *bd3 = (const float*)d_in[13];
    const float* Wt1 = (const float*)d_in[14], *Wt2 = (const float*)d_in[15];
    const float* Wt3 = (const float*)d_in[16];
    const float* Ws1 = (const float*)d_in[17], *bs1 = (const float*)d_in[18];
    const float* Ws2 = (const float*)d_in[19], *bs2 = (const float*)d_in[20];
    const float* ln_g = (const float*)d_in[21], *ln_b = (const float*)d_in[22];
    float* out = (float*)d_out;

    cudaFuncSetAttribute(kg_gemm,  cudaFuncAttributeMaxDynamicSharedMemorySize, KG_SMEM);
    cudaFuncSetAttribute(k1z_tab,  cudaFuncAttributeMaxDynamicSharedMemorySize, K1Z_SMEM);
    cudaFuncSetAttribute(k4b_gemm, cudaFuncAttributeMaxDynamicSharedMemorySize, K4B_SMEM);
    cudaFuncSetAttribute(k5_out,   cudaFuncAttributeMaxDynamicSharedMemorySize, K5_SMEM);

    khist<<<(NE + 511) / 512, 512>>>(ei);                               // 1
    ks_scan<<<1, 1024>>>();                                             // 2
    ks_scatter<<<(NE + 511) / 512, 512>>>(ei);                          // 3
    k4a_gemm<<<NN / 8, 256>>>(Ws1, bs1);                                // 4 <- PROFILED (dummy)
    kg_gemm<<<dim3(NE / 128, 3), 256, KG_SMEM>>>(eattr, Wd1, Wd2, Wd3); // 5
    k1z_tab<<<64, 128, K1Z_SMEM>>>(emb, W_emb2);                        // 6
    ke_epi<<<NE / 64, 512>>>(ei, ew, evec, z, b_emb2, bd1, bd2, bd3);   // 7
    k3_tnln<<<NN, 128>>>(ln_g, ln_b);                                   // 8
    k4a_gemm<<<NN / 8, 256>>>(Ws1, bs1);                                // 9 (real)
    k4b_gemm<<<NN / 8, 384, K4B_SMEM>>>(Ws2, bs2);                      // 10
    k5_out<<<NN / 8, 256, K5_SMEM>>>(Wt1, Wt2, Wt3, out);               // 11
}

// round 7
// speedup vs baseline: 1.6524x; 1.1682x over previous
#include <cuda_runtime.h>
#include <cuda_fp16.h>
#include <math.h>

#define NN 5000
#define NE 80000
#define HD 128
#define NR 64
#define AS 12
#define MZ 128

#define PI_OVER_CUT 0.6283185307179586f

typedef unsigned long long ull;

__device__ __align__(16) float g_WT[256 * 256];      // [k][j] transposed W_emb2 (k<128 used)
__device__ __align__(16) float g_ZPt[MZ * HD];
__device__ __align__(16) float g_ZQt[MZ * HD];
__device__ __align__(16) float g_acc[(size_t)NN * HD * AS];  // zero-init; re-zeroed by k5
__device__ __align__(16) float g_ln[NN * HD];
__device__ __align__(16) float g_y1[NN * 256];
__device__ __align__(16) float g_nrm[NN * HD * 3];
__device__ __align__(16) __half g_fh[(size_t)NE * 384];
__device__ int g_hist[NN];                           // zero-init; re-zeroed by scatter
__device__ int g_cur[NN];
__device__ int g_perm[NE];

__device__ __forceinline__ void red4(float* p, float a, float b, float c, float d) {
    asm volatile("red.global.add.v4.f32 [%0], {%1,%2,%3,%4};"
                 :: "l"(p), "f"(a), "f"(b), "f"(c), "f"(d) : "memory");
}
__device__ __forceinline__ void red2(float* p, float a, float b) {
    asm volatile("red.global.add.v2.f32 [%0], {%1,%2};"
                 :: "l"(p), "f"(a), "f"(b) : "memory");
}
__device__ __forceinline__ ull pk2(float a, float b) {
    ull r;
    asm("mov.b64 %0, {%1,%2};" : "=l"(r) : "f"(a), "f"(b));
    return r;
}
__device__ __forceinline__ void unpk2(ull v, float& a, float& b) {
    asm("mov.b64 {%0,%1}, %2;" : "=f"(a), "=f"(b) : "l"(v));
}
__device__ __forceinline__ ull fma2(ull a, ull b, ull c) {
    ull d;
    asm("fma.rn.f32x2 %0, %1, %2, %3;" : "=l"(d) : "l"(a), "l"(b), "l"(c));
    return d;
}
__device__ __forceinline__ float silu_f(float x) { return x / (1.0f + expf(-x)); }

// ---------------- 1. khist ----------------
__global__ void khist(const int* __restrict__ ei) {
    int e = blockIdx.x * blockDim.x + threadIdx.x;
    if (e < NE) atomicAdd(&g_hist[ei[e]], 1);
}

// ---------------- 2. scan ----------------
__global__ void ks_scan() {
    __shared__ int wsum[32];
    __shared__ int carry;
    int t = threadIdx.x, lane = t & 31, wid = t >> 5;
    if (t == 0) carry = 0;
    __syncthreads();
    for (int c = 0; c < 5; c++) {
        int idx = c * 1024 + t;
        int v = (idx < NN) ? g_hist[idx] : 0;
        int x = v;
#pragma unroll
        for (int o = 1; o < 32; o <<= 1) {
            int y = __shfl_up_sync(0xffffffffu, x, o);
            if (lane >= o) x += y;
        }
        if (lane == 31) wsum[wid] = x;
        __syncthreads();
        if (wid == 0) {
            int s = wsum[lane];
#pragma unroll
            for (int o = 1; o < 32; o <<= 1) {
                int y = __shfl_up_sync(0xffffffffu, s, o);
                if (lane >= o) s += y;
            }
            wsum[lane] = s;
        }
        __syncthreads();
        int pref = carry + (wid ? wsum[wid - 1] : 0) + x - v;
        if (idx < NN) g_cur[idx] = pref;
        __syncthreads();
        if (t == 0) carry += wsum[31];
        __syncthreads();
    }
}

// ---------------- 3. scatter (re-zeroes g_hist) ----------------
__global__ void ks_scatter(const int* __restrict__ ei) {
    int e = blockIdx.x * blockDim.x + threadIdx.x;
    if (e < NE) {
        int s = ei[e];
        int p = atomicAdd(&g_cur[s], 1);
        g_perm[p] = e;
    }
    for (int i = e; i < NN; i += gridDim.x * blockDim.x) g_hist[i] = 0;
}

// ---------------- 4. kg: GEMM (retiled k-loop, fp16 out) — PROFILED ----------------
__global__ __launch_bounds__(256, 2) void kg_gemm(
    const float* __restrict__ eattr,
    const float* __restrict__ Wd1, const float* __restrict__ Wd2,
    const float* __restrict__ Wd3) {
    extern __shared__ float smg[];
    float* sA  = smg;                 // [128 e][64 k]
    float* sWA = smg + 128 * 64;      // [64 k][68]
    float* sWB = sWA + 64 * 68;       // [64 k][68]
    const int t = threadIdx.x;
    const int e0 = blockIdx.x * 128;
    const float* W = (blockIdx.y == 0) ? Wd1 : ((blockIdx.y == 1) ? Wd2 : Wd3);

    {
        const float4* src = (const float4*)(eattr + (size_t)e0 * NR);
        float4* dst = (float4*)sA;
#pragma unroll
        for (int r = 0; r < 8; r++) dst[t + 256 * r] = src[t + 256 * r];
    }
    {
        const float4* src = (const float4*)W;
#pragma unroll
        for (int r = 0; r < 8; r++) {
            int i = t + 256 * r;
            int h = i & 127, kq = i >> 7;
            float4 w4 = src[h * 16 + kq];
            int hg = h >> 3, j = h & 7;
            float* arr = (j < 4) ? sWA : sWB;
            int col = hg * 4 + (j & 3);
            arr[(kq * 4 + 0) * 68 + col] = w4.x;
            arr[(kq * 4 + 1) * 68 + col] = w4.y;
            arr[(kq * 4 + 2) * 68 + col] = w4.z;
            arr[(kq * 4 + 3) * 68 + col] = w4.w;
        }
    }
    __syncthreads();

    const int hg = t & 15;
    const int h0 = hg * 8;
    const int eb = (t >> 4) * 8;

    ull acc[8][4];
#pragma unroll
    for (int e = 0; e < 8; e++)
#pragma unroll
        for (int j = 0; j < 4; j++) acc[e][j] = 0ull;

    for (int k0 = 0; k0 < NR; k0 += 4) {
        float4 a4[8];
#pragma unroll
        for (int e = 0; e < 8; e++)
            a4[e] = *(const float4*)&sA[(eb + e) * 64 + k0];
#pragma unroll
        for (int kk = 0; kk < 4; kk++) {
            ulonglong2 wa = *(const ulonglong2*)&sWA[(k0 + kk) * 68 + hg * 4];
            ulonglong2 wb = *(const ulonglong2*)&sWB[(k0 + kk) * 68 + hg * 4];
#pragma unroll
            for (int e = 0; e < 8; e++) {
                float a = (kk == 0) ? a4[e].x : (kk == 1) ? a4[e].y
                          : (kk == 2) ? a4[e].z : a4[e].w;
                ull ap = pk2(a, a);
                acc[e][0] = fma2(wa.x, ap, acc[e][0]);
                acc[e][1] = fma2(wa.y, ap, acc[e][1]);
                acc[e][2] = fma2(wb.x, ap, acc[e][2]);
                acc[e][3] = fma2(wb.y, ap, acc[e][3]);
            }
        }
    }

#pragma unroll
    for (int e = 0; e < 8; e++) {
        size_t idx = (size_t)(e0 + eb + e) * 384 + blockIdx.y * 128 + h0;
        unsigned p[4];
#pragma unroll
        for (int j = 0; j < 4; j++) {
            float a0, a1;
            unpk2(acc[e][j], a0, a1);
            __half2 hv = __floats2half2_rn(a0, a1);
            p[j] = *(unsigned*)&hv;
        }
        uint4 u = make_uint4(p[0], p[1], p[2], p[3]);
        *(uint4*)(&g_fh[idx]) = u;
    }
}

// ---------------- 5. kT: transpose W_emb2 into gather-friendly layout ----------------
// g_WT[k][j]: j<128 -> W[j][k] (ZP); j>=128 -> W[j-128][128+k] (ZQ)
__global__ void kT_trans(const float* __restrict__ W) {
    __shared__ float s[32][33];
    int tx = threadIdx.x, ty = threadIdx.y;
    int c0 = blockIdx.x * 32, h0 = blockIdx.y * 32;
    s[ty][tx] = W[(h0 + ty) * 256 + c0 + tx];
    __syncthreads();
    int k0 = (c0 < 128) ? c0 : c0 - 128;
    int j0 = (c0 < 128) ? h0 : 128 + h0;
    g_WT[(k0 + ty) * 256 + j0 + tx] = s[tx][ty];
}

// ---------------- 6. k1z: ZPt/ZQt tables via coalesced L2-resident reads ----------------
__global__ __launch_bounds__(256) void k1z_tab(const float* __restrict__ emb) {
    __shared__ float sE[128];
    int zz = blockIdx.x, t = threadIdx.x;
    if (t < 128) sE[t] = emb[(size_t)zz * HD + t];
    __syncthreads();
    float a0 = 0.f, a1 = 0.f;
#pragma unroll 8
    for (int k = 0; k < 128; k += 2) {
        a0 += g_WT[k * 256 + t] * sE[k];
        a1 += g_WT[(k + 1) * 256 + t] * sE[k + 1];
    }
    float acc = a0 + a1;
    if (t < 128) g_ZPt[zz * HD + t] = acc;
    else         g_ZQt[zz * HD + t - 128] = acc;
}

// ---------------- 7. ke: epilogue (fp16 g_fh reads) ----------------
__global__ __launch_bounds__(512) void ke_epi(
    const int* __restrict__ ei, const float* __restrict__ ew,
    const float* __restrict__ evec, const int* __restrict__ z,
    const float* __restrict__ b_emb2,
    const float* __restrict__ bd1, const float* __restrict__ bd2,
    const float* __restrict__ bd3) {
    __shared__ float sCut[64], sVx[64], sVy[64], sVz[64];
    __shared__ int sSrc[64], sZs[64], sZd[64], sPe[64];
    const int tid = threadIdx.x;
    const int e0 = blockIdx.x * 64;
    if (tid < 64) {
        int pe = g_perm[e0 + tid];
        sPe[tid] = pe;
        int s = ei[pe], d = ei[NE + pe];
        sSrc[tid] = s;
        sZs[tid] = z[s];
        sZd[tid] = z[d];
        float w = ew[pe];
        sCut[tid] = (w < 5.0f) ? 0.5f * (cosf(w * PI_OVER_CUT) + 1.0f) : 0.0f;
        sVx[tid] = evec[3 * pe + 0];
        sVy[tid] = evec[3 * pe + 1];
        sVz[tid] = evec[3 * pe + 2];
    }
    __syncthreads();

    const int h = tid & 127;
    const int grp = tid >> 7;
    const float bemb = b_emb2[h];
    const float b1 = bd1[h], b2 = bd2[h], b3 = bd3[h];

    float racc[10];
#pragma unroll
    for (int c = 0; c < 10; c++) racc[c] = 0.f;
    int cur = sSrc[grp * 16];

#define FLUSH()                                                  \
    do {                                                         \
        float* p_ = &g_acc[((size_t)cur * HD + h) * AS];         \
        red4(p_, racc[0], racc[1], racc[2], racc[3]);            \
        red4(p_ + 4, racc[4], racc[5], racc[6], racc[7]);        \
        red2(p_ + 8, racc[8], racc[9]);                          \
    } while (0)

#pragma unroll 2
    for (int i = 0; i < 16; i++) {
        int e = grp * 16 + i;
        int pe = sPe[e];
        int s = sSrc[e];
        const __half* fp = &g_fh[(size_t)pe * 384 + h];
        float f1 = __half2float(fp[0]);
        float f2 = __half2float(fp[128]);
        float f3 = __half2float(fp[256]);
        float C = sCut[e] * (g_ZPt[sZs[e] * HD + h] + g_ZQt[sZd[e] * HD + h] + bemb);
        f1 = (f1 + b1) * C;
        f2 = (f2 + b2) * C;
        f3 = (f3 + b3) * C;
        if (s != cur) {
            FLUSH();
#pragma unroll
            for (int c = 0; c < 10; c++) racc[c] = 0.f;
            cur = s;
        }
        float vx = sVx[e], vy = sVy[e], vz = sVz[e];
        racc[0] += f1;
        racc[1] += f2 * vx; racc[2] += f2 * vy; racc[3] += f2 * vz;
        float f3x = f3 * vx, f3y = f3 * vy, f3z = f3 * vz;
        racc[4] += f3x * vx; racc[5] += f3x * vy; racc[6] += f3x * vz;
        racc[7] += f3y * vy; racc[8] += f3y * vz; racc[9] += f3z * vz;
    }
    FLUSH();
#undef FLUSH
}

// ---------------- 8. k3: tn + LayerNorm ----------------
__global__ void k3_tnln(const float* __restrict__ ln_g, const float* __restrict__ ln_b) {
    __shared__ float sred[4];
    __shared__ float sval;
    int n = blockIdx.x, h = threadIdx.x;
    const float* a = &g_acc[((size_t)n * HD + h) * AS];
    float4 p0 = *(const float4*)a;
    float4 p1 = *(const float4*)(a + 4);
    float2 p2 = *(const float2*)(a + 8);
    float s1 = p0.x, wx = p0.y, wy = p0.z, wz = p0.w;
    float mxx = p1.x, mxy = p1.y, mxz = p1.z, myy = p1.w, myz = p2.x, mzz = p2.y;
    float tr3 = (mxx + myy + mzz) * (1.0f / 3.0f);
    float dxx = s1 + mxx - tr3, dyy = s1 + myy - tr3, dzz = s1 + mzz - tr3;
    float t01 = mxy - wz, t10 = mxy + wz, t02 = mxz + wy;
    float t20 = mxz - wy, t12 = myz - wx, t21 = myz + wx;
    float tn = dxx * dxx + dyy * dyy + dzz * dzz + t01 * t01 + t10 * t10 +
               t02 * t02 + t20 * t20 + t12 * t12 + t21 * t21;

    float v = tn;
#pragma unroll
    for (int o = 16; o; o >>= 1) v += __shfl_xor_sync(0xffffffffu, v, o);
    if ((h & 31) == 0) sred[h >> 5] = v;
    __syncthreads();
    if (h == 0) sval = (sred[0] + sred[1] + sred[2] + sred[3]) * (1.0f / HD);
    __syncthreads();
    float mu = sval;
    float dv = tn - mu;
    v = dv * dv;
#pragma unroll
    for (int o = 16; o; o >>= 1) v += __shfl_xor_sync(0xffffffffu, v, o);
    __syncthreads();
    if ((h & 31) == 0) sred[h >> 5] = v;
    __syncthreads();
    if (h == 0) sval = rsqrtf((sred[0] + sred[1] + sred[2] + sred[3]) * (1.0f / HD) + 1e-5f);
    __syncthreads();
    g_ln[(size_t)n * HD + h] = dv * sval * ln_g[h] + ln_b[h];
}

// ---------------- 9. k4a ----------------
__global__ __launch_bounds__(256) void k4a_gemm(
    const float* __restrict__ Ws1, const float* __restrict__ bs1) {
    __shared__ float sXT[HD * 8];
    __shared__ float sW[32 * 257];
    const int t = threadIdx.x;
    const int nb = blockIdx.x * 8;
    for (int i = t; i < 8 * HD; i += 256) {
        int nl = i >> 7, hh = i & 127;
        sXT[hh * 8 + nl] = g_ln[(size_t)(nb + nl) * HD + hh];
    }
    ull acc[4];
#pragma unroll
    for (int c = 0; c < 4; c++) acc[c] = 0ull;

    for (int h0 = 0; h0 < HD; h0 += 32) {
        __syncthreads();
#pragma unroll
        for (int r = 0; r < 32; r++) {
            int i = t + 256 * r;
            int j = i >> 5, hh = i & 31;
            sW[hh * 257 + j] = Ws1[j * HD + h0 + hh];
        }
        __syncthreads();
#pragma unroll 4
        for (int hh = 0; hh < 32; hh++) {
            float w = sW[hh * 257 + t];
            ull wp = pk2(w, w);
            const ulonglong2* xp = (const ulonglong2*)&sXT[(h0 + hh) * 8];
            ulonglong2 x0 = xp[0], x1 = xp[1];
            acc[0] = fma2(wp, x0.x, acc[0]);
            acc[1] = fma2(wp, x0.y, acc[1]);
            acc[2] = fma2(wp, x1.x, acc[2]);
            acc[3] = fma2(wp, x1.y, acc[3]);
        }
    }
    float bb = bs1[t];
#pragma unroll
    for (int c = 0; c < 4; c++) {
        float a0, a1;
        unpk2(acc[c], a0, a1);
        g_y1[(size_t)(nb + 2 * c) * 256 + t]     = silu_f(a0 + bb);
        g_y1[(size_t)(nb + 2 * c + 1) * 256 + t] = silu_f(a1 + bb);
    }
}

// ---------------- 10. k4b ----------------
__global__ __launch_bounds__(384) void k4b_gemm(
    const float* __restrict__ Ws2, const float* __restrict__ bs2) {
    extern __shared__ float smb[];
    float* sYT = smb;
    float* sW  = smb + 256 * 8;
    const int t = threadIdx.x;
    const int nb = blockIdx.x * 8;
    for (int i = t; i < 8 * 256; i += 384) {
        int nl = i >> 8, kk = i & 255;
        sYT[kk * 8 + nl] = g_y1[(size_t)(nb + nl) * 256 + kk];
    }
    ull acc[4];
#pragma unroll
    for (int c = 0; c < 4; c++) acc[c] = 0ull;

    for (int k0 = 0; k0 < 256; k0 += 32) {
        __syncthreads();
#pragma unroll
        for (int r = 0; r < 32; r++) {
            int i = t + 384 * r;
            if (i < 32 * 384) {
                int j = i >> 5, kk = i & 31;
                sW[kk * 385 + j] = Ws2[j * 256 + k0 + kk];
            }
        }
        __syncthreads();
#pragma unroll 4
        for (int kk = 0; kk < 32; kk++) {
            float w = sW[kk * 385 + t];
            ull wp = pk2(w, w);
            const ulonglong2* xp = (const ulonglong2*)&sYT[(k0 + kk) * 8];
            ulonglong2 x0 = xp[0], x1 = xp[1];
            acc[0] = fma2(wp, x0.x, acc[0]);
            acc[1] = fma2(wp, x0.y, acc[1]);
            acc[2] = fma2(wp, x1.x, acc[2]);
            acc[3] = fma2(wp, x1.y, acc[3]);
        }
    }
    float bb = bs2[t];
#pragma unroll
    for (int c = 0; c < 4; c++) {
        float a0, a1;
        unpk2(acc[c], a0, a1);
        g_nrm[(size_t)(nb + 2 * c) * 384 + t]     = silu_f(a0 + bb);
        g_nrm[(size_t)(nb + 2 * c + 1) * 384 + t] = silu_f(a1 + bb);
    }
}

// ---------------- 11. k5: Wt transforms + output; re-zeroes g_acc ----------------
__global__ __launch_bounds__(256) void k5_out(
    const float* __restrict__ Wt1, const float* __restrict__ Wt2,
    const float* __restrict__ Wt3, float* __restrict__ out) {
    extern __shared__ float sm[];
    float* sAcc = sm;                // [8][128][12]
    float* sWt  = sm + 8 * HD * AS;  // [16][389]
    int t  = threadIdx.x;
    int nb = blockIdx.x * 8;
    {
        float4* gsrc = (float4*)&g_acc[(size_t)nb * HD * AS];
        float4* dst = (float4*)sAcc;
        for (int i = t; i < 8 * HD * 3; i += 256) dst[i] = gsrc[i];
        __syncthreads();
        float4 zz = make_float4(0.f, 0.f, 0.f, 0.f);
        for (int i = t; i < 8 * HD * 3; i += 256) gsrc[i] = zz;
    }

    const int g = t & 127;
    const int half = t >> 7;

    ull acc[4][5];
#pragma unroll
    for (int nl = 0; nl < 4; nl++)
#pragma unroll
        for (int c = 0; c < 5; c++) acc[nl][c] = 0ull;

    for (int h0 = 0; h0 < HD; h0 += 16) {
        __syncthreads();
        for (int i = t; i < 3 * HD * 16; i += 256) {
            int m = i >> 11;
            int r = i & 2047;
            int gg = r >> 4, hh = r & 15;
            const float* W = (m == 0) ? Wt1 : ((m == 1) ? Wt2 : Wt3);
            sWt[hh * 389 + m * 128 + gg] = W[gg * HD + h0 + hh];
        }
        __syncthreads();
#pragma unroll
        for (int hh = 0; hh < 16; hh++) {
            float w1 = sWt[hh * 389 + g], w2 = sWt[hh * 389 + 128 + g], w3 = sWt[hh * 389 + 256 + g];
            ull pw12 = pk2(w1, w2), pw22 = pk2(w2, w2), pw33 = pk2(w3, w3);
#pragma unroll
            for (int nl = 0; nl < 4; nl++) {
                const ull* ap = (const ull*)&sAcc[((half * 4 + nl) * HD + h0 + hh) * AS];
                ulonglong2 q0 = *(const ulonglong2*)ap;
                ulonglong2 q1 = *(const ulonglong2*)(ap + 2);
                ull q2 = ap[4];
                acc[nl][0] = fma2(pw12, q0.x, acc[nl][0]);
                acc[nl][1] = fma2(pw22, q0.y, acc[nl][1]);
                acc[nl][2] = fma2(pw33, q1.x, acc[nl][2]);
                acc[nl][3] = fma2(pw33, q1.y, acc[nl][3]);
                acc[nl][4] = fma2(pw33, q2, acc[nl][4]);
            }
        }
    }

#pragma unroll
    for (int nl = 0; nl < 4; nl++) {
        int n = nb + half * 4 + nl;
        float n0 = g_nrm[(size_t)n * 384 + g * 3 + 0];
        float n1 = g_nrm[(size_t)n * 384 + g * 3 + 1];
        float n2 = g_nrm[(size_t)n * 384 + g * 3 + 2];
        float s1, wx, wy, wz, mxx, mxy, mxz, myy, myz, mzz;
        unpk2(acc[nl][0], s1, wx);
        unpk2(acc[nl][1], wy, wz);
        unpk2(acc[nl][2], mxx, mxy);
        unpk2(acc[nl][3], mxz, myy);
        unpk2(acc[nl][4], myz, mzz);
        float tr3 = (mxx + myy + mzz) * (1.0f / 3.0f);
        float dI = n0 * s1;
        float* o = out + ((size_t)n * HD + g) * 9;
        o[0] = dI + n2 * (mxx - tr3);
        o[1] = -n1 * wz + n2 * mxy;
        o[2] =  n1 * wy + n2 * mxz;
        o[3] =  n1 * wz + n2 * mxy;
        o[4] = dI + n2 * (myy - tr3);
        o[5] = -n1 * wx + n2 * myz;
        o[6] = -n1 * wy + n2 * mxz;
        o[7] =  n1 * wx + n2 * myz;
        o[8] = dI + n2 * (mzz - tr3);
    }
}

#define KG_SMEM ((128 * 64 + 2 * 64 * 68) * 4)
#define K4B_SMEM ((256 * 8 + 32 * 385) * 4)
#define K5_SMEM ((8 * HD * AS + 16 * 389) * 4)

extern "C" void kernel_launch(void* const* d_in, const int* in_sizes, int n_in,
                              void* d_out, int out_size) {
    (void)in_sizes; (void)n_in; (void)out_size;
    const int*   z      = (const int*)d_in[0];
    const int*   ei     = (const int*)d_in[1];
    const float* ew     = (const float*)d_in[2];
    const float* evec   = (const float*)d_in[3];
    const float* eattr  = (const float*)d_in[4];
    const float* emb    = (const float*)d_in[5];
    const float* W_emb2 = (const float*)d_in[6];
    const float* b_emb2 = (const float*)d_in[7];
    const float* Wd1 = (const float*)d_in[8],  *bd1 = (const float*)d_in[9];
    const float* Wd2 = (const float*)d_in[10], *bd2 = (const float*)d_in[11];
    const float* Wd3 = (const float*)d_in[12], *bd3 = (const float*)d_in[13];
    const float* Wt1 = (const float*)d_in[14], *Wt2 = (const float*)d_in[15];
    const float* Wt3 = (const float*)d_in[16];
    const float* Ws1 = (const float*)d_in[17], *bs1 = (const float*)d_in[18];
    const float* Ws2 = (const float*)d_in[19], *bs2 = (const float*)d_in[20];
    const float* ln_g = (const float*)d_in[21], *ln_b = (const float*)d_in[22];
    float* out = (float*)d_out;

    cudaFuncSetAttribute(kg_gemm,  cudaFuncAttributeMaxDynamicSharedMemorySize, KG_SMEM);
    cudaFuncSetAttribute(k4b_gemm, cudaFuncAttributeMaxDynamicSharedMemorySize, K4B_SMEM);
    cudaFuncSetAttribute(k5_out,   cudaFuncAttributeMaxDynamicSharedMemorySize, K5_SMEM);

    khist<<<(NE + 511) / 512, 512>>>(ei);                               // 1
    ks_scan<<<1, 1024>>>();                                             // 2
    ks_scatter<<<(NE + 511) / 512, 512>>>(ei);                          // 3
    kg_gemm<<<dim3(NE / 128, 3), 256, KG_SMEM>>>(eattr, Wd1, Wd2, Wd3); // 4 <- PROFILED
    kT_trans<<<dim3(8, 4), dim3(32, 32)>>>(W_emb2);                     // 5
    k1z_tab<<<MZ, 256>>>(emb);                                          // 6
    ke_epi<<<NE / 64, 512>>>(ei, ew, evec, z, b_emb2, bd1, bd2, bd3);   // 7
    k3_tnln<<<NN, 128>>>(ln_g, ln_b);                                   // 8
    k4a_gemm<<<NN / 8, 256>>>(Ws1, bs1);                                // 9
    k4b_gemm<<<NN / 8, 384, K4B_SMEM>>>(Ws2, bs2);                      // 10
    k5_out<<<NN / 8, 256, K5_SMEM>>>(Wt1, Wt2, Wt3, out);               // 11
}

// round 8
// speedup vs baseline: 1.7870x; 1.0815x over previous
#include <cuda_runtime.h>
#include <cuda_fp16.h>
#include <math.h>

#define NN 5000
#define NE 80000
#define HD 128
#define NR 64
#define AS 12
#define MZ 128

#define PI_OVER_CUT 0.6283185307179586f

typedef unsigned long long ull;

__device__ __align__(16) float g_WT[256 * 256];
__device__ __align__(16) float g_ZPt[MZ * HD];
__device__ __align__(16) float g_ZQt[MZ * HD];
__device__ __align__(16) float g_acc[(size_t)NN * HD * AS];  // zero-init; re-zeroed by k5
__device__ __align__(16) float g_ln[NN * HD];
__device__ __align__(16) float g_y1[NN * 256];
__device__ __align__(16) float g_nrm[NN * HD * 3];
__device__ __align__(16) __half g_fh[(size_t)NE * 384];
__device__ int g_hist[NN];                           // zero-init; re-zeroed by scatter
__device__ int g_cur[NN];
__device__ int g_perm[NE];

__device__ __forceinline__ void red4(float* p, float a, float b, float c, float d) {
    asm volatile("red.global.add.v4.f32 [%0], {%1,%2,%3,%4};"
                 :: "l"(p), "f"(a), "f"(b), "f"(c), "f"(d) : "memory");
}
__device__ __forceinline__ void red2(float* p, float a, float b) {
    asm volatile("red.global.add.v2.f32 [%0], {%1,%2};"
                 :: "l"(p), "f"(a), "f"(b) : "memory");
}
__device__ __forceinline__ ull pk2(float a, float b) {
    ull r;
    asm("mov.b64 %0, {%1,%2};" : "=l"(r) : "f"(a), "f"(b));
    return r;
}
__device__ __forceinline__ void unpk2(ull v, float& a, float& b) {
    asm("mov.b64 {%0,%1}, %2;" : "=f"(a), "=f"(b) : "l"(v));
}
__device__ __forceinline__ ull fma2(ull a, ull b, ull c) {
    ull d;
    asm("fma.rn.f32x2 %0, %1, %2, %3;" : "=l"(d) : "l"(a), "l"(b), "l"(c));
    return d;
}
__device__ __forceinline__ float silu_f(float x) { return x / (1.0f + expf(-x)); }

// ---------------- khist ----------------
__global__ void khist(const int* __restrict__ ei) {
    int e = blockIdx.x * blockDim.x + threadIdx.x;
    if (e < NE) atomicAdd(&g_hist[ei[e]], 1);
}

// ---------------- scan ----------------
__global__ void ks_scan() {
    __shared__ int wsum[32];
    __shared__ int carry;
    int t = threadIdx.x, lane = t & 31, wid = t >> 5;
    if (t == 0) carry = 0;
    __syncthreads();
    for (int c = 0; c < 5; c++) {
        int idx = c * 1024 + t;
        int v = (idx < NN) ? g_hist[idx] : 0;
        int x = v;
#pragma unroll
        for (int o = 1; o < 32; o <<= 1) {
            int y = __shfl_up_sync(0xffffffffu, x, o);
            if (lane >= o) x += y;
        }
        if (lane == 31) wsum[wid] = x;
        __syncthreads();
        if (wid == 0) {
            int s = wsum[lane];
#pragma unroll
            for (int o = 1; o < 32; o <<= 1) {
                int y = __shfl_up_sync(0xffffffffu, s, o);
                if (lane >= o) s += y;
            }
            wsum[lane] = s;
        }
        __syncthreads();
        int pref = carry + (wid ? wsum[wid - 1] : 0) + x - v;
        if (idx < NN) g_cur[idx] = pref;
        __syncthreads();
        if (t == 0) carry += wsum[31];
        __syncthreads();
    }
}

// ---------------- scatter (re-zeroes g_hist) ----------------
__global__ void ks_scatter(const int* __restrict__ ei) {
    int e = blockIdx.x * blockDim.x + threadIdx.x;
    if (e < NE) {
        int s = ei[e];
        int p = atomicAdd(&g_cur[s], 1);
        g_perm[p] = e;
    }
    for (int i = e; i < NN; i += gridDim.x * blockDim.x) g_hist[i] = 0;
}

// ---------------- k4b: nrm = silu(Ws2 @ y1 + bs2) [20 nodes/blk, 384 thr] ----
// PROFILED (dummy run at slot 4)
__global__ __launch_bounds__(384) void k4b_gemm(
    const float* __restrict__ Ws2, const float* __restrict__ bs2) {
    extern __shared__ float smb[];
    float* sYT = smb;            // [256 kk][20 nl]
    float* sW  = smb + 256 * 20; // [32 kk][385]
    const int t = threadIdx.x;
    const int nb = blockIdx.x * 20;
    for (int i = t; i < 20 * 256; i += 384) {
        int nl = i >> 8, kk = i & 255;
        sYT[kk * 20 + nl] = g_y1[(size_t)(nb + nl) * 256 + kk];
    }
    ull acc[10];
#pragma unroll
    for (int c = 0; c < 10; c++) acc[c] = 0ull;

    for (int k0 = 0; k0 < 256; k0 += 32) {
        __syncthreads();
#pragma unroll
        for (int r = 0; r < 32; r++) {
            int i = t + 384 * r;
            int j = i >> 5, kk = i & 31;
            sW[kk * 385 + j] = Ws2[j * 256 + k0 + kk];
        }
        __syncthreads();
#pragma unroll 4
        for (int kk = 0; kk < 32; kk++) {
            float w = sW[kk * 385 + t];
            ull wp = pk2(w, w);
            const ulonglong2* xp = (const ulonglong2*)&sYT[(k0 + kk) * 20];
            ulonglong2 x0 = xp[0], x1 = xp[1];
            ulonglong2 x2 = xp[2], x3 = xp[3];
            ulonglong2 x4 = xp[4];
            acc[0] = fma2(wp, x0.x, acc[0]);
            acc[1] = fma2(wp, x0.y, acc[1]);
            acc[2] = fma2(wp, x1.x, acc[2]);
            acc[3] = fma2(wp, x1.y, acc[3]);
            acc[4] = fma2(wp, x2.x, acc[4]);
            acc[5] = fma2(wp, x2.y, acc[5]);
            acc[6] = fma2(wp, x3.x, acc[6]);
            acc[7] = fma2(wp, x3.y, acc[7]);
            acc[8] = fma2(wp, x4.x, acc[8]);
            acc[9] = fma2(wp, x4.y, acc[9]);
        }
    }
    float bb = bs2[t];
#pragma unroll
    for (int c = 0; c < 10; c++) {
        float a0, a1;
        unpk2(acc[c], a0, a1);
        g_nrm[(size_t)(nb + 2 * c) * 384 + t]     = silu_f(a0 + bb);
        g_nrm[(size_t)(nb + 2 * c + 1) * 384 + t] = silu_f(a1 + bb);
    }
}

// ---------------- kg: GEMM (fp16 out) ----------------
__global__ __launch_bounds__(256, 2) void kg_gemm(
    const float* __restrict__ eattr,
    const float* __restrict__ Wd1, const float* __restrict__ Wd2,
    const float* __restrict__ Wd3) {
    extern __shared__ float smg[];
    float* sA  = smg;
    float* sWA = smg + 128 * 64;
    float* sWB = sWA + 64 * 68;
    const int t = threadIdx.x;
    const int e0 = blockIdx.x * 128;
    const float* W = (blockIdx.y == 0) ? Wd1 : ((blockIdx.y == 1) ? Wd2 : Wd3);

    {
        const float4* src = (const float4*)(eattr + (size_t)e0 * NR);
        float4* dst = (float4*)sA;
#pragma unroll
        for (int r = 0; r < 8; r++) dst[t + 256 * r] = src[t + 256 * r];
    }
    {
        const float4* src = (const float4*)W;
#pragma unroll
        for (int r = 0; r < 8; r++) {
            int i = t + 256 * r;
            int h = i & 127, kq = i >> 7;
            float4 w4 = src[h * 16 + kq];
            int hg = h >> 3, j = h & 7;
            float* arr = (j < 4) ? sWA : sWB;
            int col = hg * 4 + (j & 3);
            arr[(kq * 4 + 0) * 68 + col] = w4.x;
            arr[(kq * 4 + 1) * 68 + col] = w4.y;
            arr[(kq * 4 + 2) * 68 + col] = w4.z;
            arr[(kq * 4 + 3) * 68 + col] = w4.w;
        }
    }
    __syncthreads();

    const int hg = t & 15;
    const int h0 = hg * 8;
    const int eb = (t >> 4) * 8;

    ull acc[8][4];
#pragma unroll
    for (int e = 0; e < 8; e++)
#pragma unroll
        for (int j = 0; j < 4; j++) acc[e][j] = 0ull;

    for (int k0 = 0; k0 < NR; k0 += 4) {
        float4 a4[8];
#pragma unroll
        for (int e = 0; e < 8; e++)
            a4[e] = *(const float4*)&sA[(eb + e) * 64 + k0];
#pragma unroll
        for (int kk = 0; kk < 4; kk++) {
            ulonglong2 wa = *(const ulonglong2*)&sWA[(k0 + kk) * 68 + hg * 4];
            ulonglong2 wb = *(const ulonglong2*)&sWB[(k0 + kk) * 68 + hg * 4];
#pragma unroll
            for (int e = 0; e < 8; e++) {
                float a = (kk == 0) ? a4[e].x : (kk == 1) ? a4[e].y
                          : (kk == 2) ? a4[e].z : a4[e].w;
                ull ap = pk2(a, a);
                acc[e][0] = fma2(wa.x, ap, acc[e][0]);
                acc[e][1] = fma2(wa.y, ap, acc[e][1]);
                acc[e][2] = fma2(wb.x, ap, acc[e][2]);
                acc[e][3] = fma2(wb.y, ap, acc[e][3]);
            }
        }
    }

#pragma unroll
    for (int e = 0; e < 8; e++) {
        size_t idx = (size_t)(e0 + eb + e) * 384 + blockIdx.y * 128 + h0;
        unsigned p[4];
#pragma unroll
        for (int j = 0; j < 4; j++) {
            float a0, a1;
            unpk2(acc[e][j], a0, a1);
            __half2 hv = __floats2half2_rn(a0, a1);
            p[j] = *(unsigned*)&hv;
        }
        uint4 u = make_uint4(p[0], p[1], p[2], p[3]);
        *(uint4*)(&g_fh[idx]) = u;
    }
}

// ---------------- kT: transpose W_emb2 ----------------
__global__ void kT_trans(const float* __restrict__ W) {
    __shared__ float s[32][33];
    int tx = threadIdx.x, ty = threadIdx.y;
    int c0 = blockIdx.x * 32, h0 = blockIdx.y * 32;
    s[ty][tx] = W[(h0 + ty) * 256 + c0 + tx];
    __syncthreads();
    int k0 = (c0 < 128) ? c0 : c0 - 128;
    int j0 = (c0 < 128) ? h0 : 128 + h0;
    g_WT[(k0 + ty) * 256 + j0 + tx] = s[tx][ty];
}

// ---------------- k1z: ZPt/ZQt tables ----------------
__global__ __launch_bounds__(256) void k1z_tab(const float* __restrict__ emb) {
    __shared__ float sE[128];
    int zz = blockIdx.x, t = threadIdx.x;
    if (t < 128) sE[t] = emb[(size_t)zz * HD + t];
    __syncthreads();
    float a0 = 0.f, a1 = 0.f;
#pragma unroll 8
    for (int k = 0; k < 128; k += 2) {
        a0 += g_WT[k * 256 + t] * sE[k];
        a1 += g_WT[(k + 1) * 256 + t] * sE[k + 1];
    }
    float acc = a0 + a1;
    if (t < 128) g_ZPt[zz * HD + t] = acc;
    else         g_ZQt[zz * HD + t - 128] = acc;
}

// ---------------- ke: epilogue ----------------
__global__ __launch_bounds__(512) void ke_epi(
    const int* __restrict__ ei, const float* __restrict__ ew,
    const float* __restrict__ evec, const int* __restrict__ z,
    const float* __restrict__ b_emb2,
    const float* __restrict__ bd1, const float* __restrict__ bd2,
    const float* __restrict__ bd3) {
    __shared__ float sCut[64], sVx[64], sVy[64], sVz[64];
    __shared__ int sSrc[64], sZs[64], sZd[64], sPe[64];
    const int tid = threadIdx.x;
    const int e0 = blockIdx.x * 64;
    if (tid < 64) {
        int pe = g_perm[e0 + tid];
        sPe[tid] = pe;
        int s = ei[pe], d = ei[NE + pe];
        sSrc[tid] = s;
        sZs[tid] = z[s];
        sZd[tid] = z[d];
        float w = ew[pe];
        sCut[tid] = (w < 5.0f) ? 0.5f * (cosf(w * PI_OVER_CUT) + 1.0f) : 0.0f;
        sVx[tid] = evec[3 * pe + 0];
        sVy[tid] = evec[3 * pe + 1];
        sVz[tid] = evec[3 * pe + 2];
    }
    __syncthreads();

    const int h = tid & 127;
    const int grp = tid >> 7;
    const float bemb = b_emb2[h];
    const float b1 = bd1[h], b2 = bd2[h], b3 = bd3[h];

    float racc[10];
#pragma unroll
    for (int c = 0; c < 10; c++) racc[c] = 0.f;
    int cur = sSrc[grp * 16];

#define FLUSH()                                                  \
    do {                                                         \
        float* p_ = &g_acc[((size_t)cur * HD + h) * AS];         \
        red4(p_, racc[0], racc[1], racc[2], racc[3]);            \
        red4(p_ + 4, racc[4], racc[5], racc[6], racc[7]);        \
        red2(p_ + 8, racc[8], racc[9]);                          \
    } while (0)

#pragma unroll 2
    for (int i = 0; i < 16; i++) {
        int e = grp * 16 + i;
        int pe = sPe[e];
        int s = sSrc[e];
        const __half* fp = &g_fh[(size_t)pe * 384 + h];
        float f1 = __half2float(fp[0]);
        float f2 = __half2float(fp[128]);
        float f3 = __half2float(fp[256]);
        float C = sCut[e] * (g_ZPt[sZs[e] * HD + h] + g_ZQt[sZd[e] * HD + h] + bemb);
        f1 = (f1 + b1) * C;
        f2 = (f2 + b2) * C;
        f3 = (f3 + b3) * C;
        if (s != cur) {
            FLUSH();
#pragma unroll
            for (int c = 0; c < 10; c++) racc[c] = 0.f;
            cur = s;
        }
        float vx = sVx[e], vy = sVy[e], vz = sVz[e];
        racc[0] += f1;
        racc[1] += f2 * vx; racc[2] += f2 * vy; racc[3] += f2 * vz;
        float f3x = f3 * vx, f3y = f3 * vy, f3z = f3 * vz;
        racc[4] += f3x * vx; racc[5] += f3x * vy; racc[6] += f3x * vz;
        racc[7] += f3y * vy; racc[8] += f3y * vz; racc[9] += f3z * vz;
    }
    FLUSH();
#undef FLUSH
}

// ---------------- k3: tn + LayerNorm ----------------
__global__ void k3_tnln(const float* __restrict__ ln_g, const float* __restrict__ ln_b) {
    __shared__ float sred[4];
    __shared__ float sval;
    int n = blockIdx.x, h = threadIdx.x;
    const float* a = &g_acc[((size_t)n * HD + h) * AS];
    float4 p0 = *(const float4*)a;
    float4 p1 = *(const float4*)(a + 4);
    float2 p2 = *(const float2*)(a + 8);
    float s1 = p0.x, wx = p0.y, wy = p0.z, wz = p0.w;
    float mxx = p1.x, mxy = p1.y, mxz = p1.z, myy = p1.w, myz = p2.x, mzz = p2.y;
    float tr3 = (mxx + myy + mzz) * (1.0f / 3.0f);
    float dxx = s1 + mxx - tr3, dyy = s1 + myy - tr3, dzz = s1 + mzz - tr3;
    float t01 = mxy - wz, t10 = mxy + wz, t02 = mxz + wy;
    float t20 = mxz - wy, t12 = myz - wx, t21 = myz + wx;
    float tn = dxx * dxx + dyy * dyy + dzz * dzz + t01 * t01 + t10 * t10 +
               t02 * t02 + t20 * t20 + t12 * t12 + t21 * t21;

    float v = tn;
#pragma unroll
    for (int o = 16; o; o >>= 1) v += __shfl_xor_sync(0xffffffffu, v, o);
    if ((h & 31) == 0) sred[h >> 5] = v;
    __syncthreads();
    if (h == 0) sval = (sred[0] + sred[1] + sred[2] + sred[3]) * (1.0f / HD);
    __syncthreads();
    float mu = sval;
    float dv = tn - mu;
    v = dv * dv;
#pragma unroll
    for (int o = 16; o; o >>= 1) v += __shfl_xor_sync(0xffffffffu, v, o);
    __syncthreads();
    if ((h & 31) == 0) sred[h >> 5] = v;
    __syncthreads();
    if (h == 0) sval = rsqrtf((sred[0] + sred[1] + sred[2] + sred[3]) * (1.0f / HD) + 1e-5f);
    __syncthreads();
    g_ln[(size_t)n * HD + h] = dv * sval * ln_g[h] + ln_b[h];
}

// ---------------- k4a: y1 = silu(Ws1 @ ln + bs1) [20 nodes/blk, 256 thr] ----
__global__ __launch_bounds__(256) void k4a_gemm(
    const float* __restrict__ Ws1, const float* __restrict__ bs1) {
    __shared__ float sXT[HD * 20];       // [hh][nl]
    __shared__ float sW[32 * 257];
    const int t = threadIdx.x;
    const int nb = blockIdx.x * 20;
    for (int i = t; i < 20 * HD; i += 256) {
        int nl = i >> 7, hh = i & 127;
        sXT[hh * 20 + nl] = g_ln[(size_t)(nb + nl) * HD + hh];
    }
    ull acc[10];
#pragma unroll
    for (int c = 0; c < 10; c++) acc[c] = 0ull;

    for (int h0 = 0; h0 < HD; h0 += 32) {
        __syncthreads();
#pragma unroll
        for (int r = 0; r < 32; r++) {
            int i = t + 256 * r;
            int j = i >> 5, hh = i & 31;
            sW[hh * 257 + j] = Ws1[j * HD + h0 + hh];
        }
        __syncthreads();
#pragma unroll 4
        for (int hh = 0; hh < 32; hh++) {
            float w = sW[hh * 257 + t];
            ull wp = pk2(w, w);
            const ulonglong2* xp = (const ulonglong2*)&sXT[(h0 + hh) * 20];
            ulonglong2 x0 = xp[0], x1 = xp[1];
            ulonglong2 x2 = xp[2], x3 = xp[3];
            ulonglong2 x4 = xp[4];
            acc[0] = fma2(wp, x0.x, acc[0]);
            acc[1] = fma2(wp, x0.y, acc[1]);
            acc[2] = fma2(wp, x1.x, acc[2]);
            acc[3] = fma2(wp, x1.y, acc[3]);
            acc[4] = fma2(wp, x2.x, acc[4]);
            acc[5] = fma2(wp, x2.y, acc[5]);
            acc[6] = fma2(wp, x3.x, acc[6]);
            acc[7] = fma2(wp, x3.y, acc[7]);
            acc[8] = fma2(wp, x4.x, acc[8]);
            acc[9] = fma2(wp, x4.y, acc[9]);
        }
    }
    float bb = bs1[t];
#pragma unroll
    for (int c = 0; c < 10; c++) {
        float a0, a1;
        unpk2(acc[c], a0, a1);
        g_y1[(size_t)(nb + 2 * c) * 256 + t]     = silu_f(a0 + bb);
        g_y1[(size_t)(nb + 2 * c + 1) * 256 + t] = silu_f(a1 + bb);
    }
}

// ---------------- k5: Wt transforms + output (2g x 2nl tile); re-zeroes g_acc ----
__global__ __launch_bounds__(256) void k5_out(
    const float* __restrict__ Wt1, const float* __restrict__ Wt2,
    const float* __restrict__ Wt3, float* __restrict__ out) {
    extern __shared__ float sm[];
    float* sAcc = sm;                // [8][128][12]
    float* sWt  = sm + 8 * HD * AS;  // [16][390]
    int t  = threadIdx.x;
    int nb = blockIdx.x * 8;
    {
        float4* gsrc = (float4*)&g_acc[(size_t)nb * HD * AS];
        float4* dst = (float4*)sAcc;
        for (int i = t; i < 8 * HD * 3; i += 256) dst[i] = gsrc[i];
        __syncthreads();
        float4 zz = make_float4(0.f, 0.f, 0.f, 0.f);
        for (int i = t; i < 8 * HD * 3; i += 256) gsrc[i] = zz;
    }

    const int g0 = (t & 63) * 2;
    const int n0 = (t >> 6) * 2;

    ull acc[2][2][5];
#pragma unroll
    for (int gi = 0; gi < 2; gi++)
#pragma unroll
        for (int ni = 0; ni < 2; ni++)
#pragma unroll
            for (int c = 0; c < 5; c++) acc[gi][ni][c] = 0ull;

    for (int h0 = 0; h0 < HD; h0 += 16) {
        __syncthreads();
        for (int i = t; i < 3 * HD * 16; i += 256) {
            int m = i >> 11;
            int r = i & 2047;
            int gg = r >> 4, hh = r & 15;
            const float* W = (m == 0) ? Wt1 : ((m == 1) ? Wt2 : Wt3);
            sWt[hh * 390 + m * 128 + gg] = W[gg * HD + h0 + hh];
        }
        __syncthreads();
#pragma unroll
        for (int hh = 0; hh < 16; hh++) {
            const float* wrow = &sWt[hh * 390];
            float2 w1 = *(const float2*)&wrow[g0];
            float2 w2 = *(const float2*)&wrow[128 + g0];
            float2 w3 = *(const float2*)&wrow[256 + g0];
            ull pw12a = pk2(w1.x, w2.x), pw22a = pk2(w2.x, w2.x), pw33a = pk2(w3.x, w3.x);
            ull pw12b = pk2(w1.y, w2.y), pw22b = pk2(w2.y, w2.y), pw33b = pk2(w3.y, w3.y);
#pragma unroll
            for (int ni = 0; ni < 2; ni++) {
                const ull* ap = (const ull*)&sAcc[((n0 + ni) * HD + h0 + hh) * AS];
                ulonglong2 q0 = *(const ulonglong2*)ap;
                ulonglong2 q1 = *(const ulonglong2*)(ap + 2);
                ull q2 = ap[4];
                acc[0][ni][0] = fma2(pw12a, q0.x, acc[0][ni][0]);
                acc[0][ni][1] = fma2(pw22a, q0.y, acc[0][ni][1]);
                acc[0][ni][2] = fma2(pw33a, q1.x, acc[0][ni][2]);
                acc[0][ni][3] = fma2(pw33a, q1.y, acc[0][ni][3]);
                acc[0][ni][4] = fma2(pw33a, q2,   acc[0][ni][4]);
                acc[1][ni][0] = fma2(pw12b, q0.x, acc[1][ni][0]);
                acc[1][ni][1] = fma2(pw22b, q0.y, acc[1][ni][1]);
                acc[1][ni][2] = fma2(pw33b, q1.x, acc[1][ni][2]);
                acc[1][ni][3] = fma2(pw33b, q1.y, acc[1][ni][3]);
                acc[1][ni][4] = fma2(pw33b, q2,   acc[1][ni][4]);
            }
        }
    }

#pragma unroll
    for (int gi = 0; gi < 2; gi++)
#pragma unroll
    for (int ni = 0; ni < 2; ni++) {
        int n = nb + n0 + ni;
        int g = g0 + gi;
        float nr0 = g_nrm[(size_t)n * 384 + g * 3 + 0];
        float nr1 = g_nrm[(size_t)n * 384 + g * 3 + 1];
        float nr2 = g_nrm[(size_t)n * 384 + g * 3 + 2];
        float s1, wx, wy, wz, mxx, mxy, mxz, myy, myz, mzz;
        unpk2(acc[gi][ni][0], s1, wx);
        unpk2(acc[gi][ni][1], wy, wz);
        unpk2(acc[gi][ni][2], mxx, mxy);
        unpk2(acc[gi][ni][3], mxz, myy);
        unpk2(acc[gi][ni][4], myz, mzz);
        float tr3 = (mxx + myy + mzz) * (1.0f / 3.0f);
        float dI = nr0 * s1;
        float* o = out + ((size_t)n * HD + g) * 9;
        o[0] = dI + nr2 * (mxx - tr3);
        o[1] = -nr1 * wz + nr2 * mxy;
        o[2] =  nr1 * wy + nr2 * mxz;
        o[3] =  nr1 * wz + nr2 * mxy;
        o[4] = dI + nr2 * (myy - tr3);
        o[5] = -nr1 * wx + nr2 * myz;
        o[6] = -nr1 * wy + nr2 * mxz;
        o[7] =  nr1 * wx + nr2 * myz;
        o[8] = dI + nr2 * (mzz - tr3);
    }
}

#define KG_SMEM ((128 * 64 + 2 * 64 * 68) * 4)
#define K4B_SMEM ((256 * 20 + 32 * 385) * 4)
#define K5_SMEM ((8 * HD * AS + 16 * 390) * 4)

extern "C" void kernel_launch(void* const* d_in, const int* in_sizes, int n_in,
                              void* d_out, int out_size) {
    (void)in_sizes; (void)n_in; (void)out_size;
    const int*   z      = (const int*)d_in[0];
    const int*   ei     = (const int*)d_in[1];
    const float* ew     = (const float*)d_in[2];
    const float* evec   = (const float*)d_in[3];
    const float* eattr  = (const float*)d_in[4];
    const float* emb    = (const float*)d_in[5];
    const float* W_emb2 = (const float*)d_in[6];
    const float* b_emb2 = (const float*)d_in[7];
    const float* Wd1 = (const float*)d_in[8],  *bd1 = (const float*)d_in[9];
    const float* Wd2 = (const float*)d_in[10], *bd2 = (const float*)d_in[11];
    const float* Wd3 = (const float*)d_in[12], *bd3 = (const float*)d_in[13];
    const float* Wt1 = (const float*)d_in[14], *Wt2 = (const float*)d_in[15];
    const float* Wt3 = (const float*)d_in[16];
    const float* Ws1 = (const float*)d_in[17], *bs1 = (const float*)d_in[18];
    const float* Ws2 = (const float*)d_in[19], *bs2 = (const float*)d_in[20];
    const float* ln_g = (const float*)d_in[21], *ln_b = (const float*)d_in[22];
    float* out = (float*)d_out;

    cudaFuncSetAttribute(kg_gemm,  cudaFuncAttributeMaxDynamicSharedMemorySize, KG_SMEM);
    cudaFuncSetAttribute(k4b_gemm, cudaFuncAttributeMaxDynamicSharedMemorySize, K4B_SMEM);
    cudaFuncSetAttribute(k5_out,   cudaFuncAttributeMaxDynamicSharedMemorySize, K5_SMEM);

    khist<<<(NE + 511) / 512, 512>>>(ei);                               // 1
    ks_scan<<<1, 1024>>>();                                             // 2
    ks_scatter<<<(NE + 511) / 512, 512>>>(ei);                          // 3
    k4b_gemm<<<NN / 20, 384, K4B_SMEM>>>(Ws2, bs2);                     // 4 <- PROFILED (dummy)
    kg_gemm<<<dim3(NE / 128, 3), 256, KG_SMEM>>>(eattr, Wd1, Wd2, Wd3); // 5
    kT_trans<<<dim3(8, 4), dim3(32, 32)>>>(W_emb2);                     // 6
    k1z_tab<<<MZ, 256>>>(emb);                                          // 7
    ke_epi<<<NE / 64, 512>>>(ei, ew, evec, z, b_emb2, bd1, bd2, bd3);   // 8
    k3_tnln<<<NN, 128>>>(ln_g, ln_b);                                   // 9
    k4a_gemm<<<NN / 20, 256>>>(Ws1, bs1);                               // 10
    k4b_gemm<<<NN / 20, 384, K4B_SMEM>>>(Ws2, bs2);                     // 11
    k5_out<<<NN / 8, 256, K5_SMEM>>>(Wt1, Wt2, Wt3, out);               // 12
}

// round 9
// speedup vs baseline: 2.2601x; 1.2647x over previous
#include <cuda_runtime.h>
#include <cuda_fp16.h>
#include <math.h>

#define NN 5000
#define NE 80000
#define HD 128
#define NR 64
#define AS 12
#define MZ 128

#define PI_OVER_CUT 0.6283185307179586f

typedef unsigned long long ull;

__device__ __align__(16) float g_WT[256 * 256];
__device__ __align__(16) float g_ZPt[MZ * HD];
__device__ __align__(16) float g_ZQt[MZ * HD];
__device__ __align__(16) float g_acc[(size_t)NN * HD * AS];  // zero-init; re-zeroed by k5
__device__ __align__(16) float g_ln[NN * HD];
__device__ __align__(16) float g_y1[NN * 256];
__device__ __align__(16) float g_nrm[NN * HD * 3];
__device__ __align__(16) __half g_fh[(size_t)NE * 384];
__device__ int g_hist[NN];                           // zero-init; re-zeroed by scatter
__device__ int g_cur[NN];
__device__ int g_perm[NE];

__device__ __forceinline__ void red4(float* p, float a, float b, float c, float d) {
    asm volatile("red.global.add.v4.f32 [%0], {%1,%2,%3,%4};"
                 :: "l"(p), "f"(a), "f"(b), "f"(c), "f"(d) : "memory");
}
__device__ __forceinline__ void red2(float* p, float a, float b) {
    asm volatile("red.global.add.v2.f32 [%0], {%1,%2};"
                 :: "l"(p), "f"(a), "f"(b) : "memory");
}
__device__ __forceinline__ ull pk2(float a, float b) {
    ull r;
    asm("mov.b64 %0, {%1,%2};" : "=l"(r) : "f"(a), "f"(b));
    return r;
}
__device__ __forceinline__ void unpk2(ull v, float& a, float& b) {
    asm("mov.b64 {%0,%1}, %2;" : "=f"(a), "=f"(b) : "l"(v));
}
__device__ __forceinline__ ull fma2(ull a, ull b, ull c) {
    ull d;
    asm("fma.rn.f32x2 %0, %1, %2, %3;" : "=l"(d) : "l"(a), "l"(b), "l"(c));
    return d;
}
__device__ __forceinline__ float silu_f(float x) { return x / (1.0f + expf(-x)); }

// ---------------- khist ----------------
__global__ void khist(const int* __restrict__ ei) {
    int e = blockIdx.x * blockDim.x + threadIdx.x;
    if (e < NE) atomicAdd(&g_hist[ei[e]], 1);
}

// ---------------- scan ----------------
__global__ void ks_scan() {
    __shared__ int wsum[32];
    __shared__ int carry;
    int t = threadIdx.x, lane = t & 31, wid = t >> 5;
    if (t == 0) carry = 0;
    __syncthreads();
    for (int c = 0; c < 5; c++) {
        int idx = c * 1024 + t;
        int v = (idx < NN) ? g_hist[idx] : 0;
        int x = v;
#pragma unroll
        for (int o = 1; o < 32; o <<= 1) {
            int y = __shfl_up_sync(0xffffffffu, x, o);
            if (lane >= o) x += y;
        }
        if (lane == 31) wsum[wid] = x;
        __syncthreads();
        if (wid == 0) {
            int s = wsum[lane];
#pragma unroll
            for (int o = 1; o < 32; o <<= 1) {
                int y = __shfl_up_sync(0xffffffffu, s, o);
                if (lane >= o) s += y;
            }
            wsum[lane] = s;
        }
        __syncthreads();
        int pref = carry + (wid ? wsum[wid - 1] : 0) + x - v;
        if (idx < NN) g_cur[idx] = pref;
        __syncthreads();
        if (t == 0) carry += wsum[31];
        __syncthreads();
    }
}

// ---------------- scatter (re-zeroes g_hist) ----------------
__global__ void ks_scatter(const int* __restrict__ ei) {
    int e = blockIdx.x * blockDim.x + threadIdx.x;
    if (e < NE) {
        int s = ei[e];
        int p = atomicAdd(&g_cur[s], 1);
        g_perm[p] = e;
    }
    for (int i = e; i < NN; i += gridDim.x * blockDim.x) g_hist[i] = 0;
}

// ---------------- kg: GEMM (fp16 out) — PROFILED ----------------
__global__ __launch_bounds__(256, 2) void kg_gemm(
    const float* __restrict__ eattr,
    const float* __restrict__ Wd1, const float* __restrict__ Wd2,
    const float* __restrict__ Wd3) {
    extern __shared__ float smg[];
    float* sA  = smg;
    float* sWA = smg + 128 * 64;
    float* sWB = sWA + 64 * 68;
    const int t = threadIdx.x;
    const int e0 = blockIdx.x * 128;
    const float* W = (blockIdx.y == 0) ? Wd1 : ((blockIdx.y == 1) ? Wd2 : Wd3);

    {
        const float4* src = (const float4*)(eattr + (size_t)e0 * NR);
        float4* dst = (float4*)sA;
#pragma unroll
        for (int r = 0; r < 8; r++) dst[t + 256 * r] = src[t + 256 * r];
    }
    {
        const float4* src = (const float4*)W;
#pragma unroll
        for (int r = 0; r < 8; r++) {
            int i = t + 256 * r;
            int h = i & 127, kq = i >> 7;
            float4 w4 = src[h * 16 + kq];
            int hg = h >> 3, j = h & 7;
            float* arr = (j < 4) ? sWA : sWB;
            int col = hg * 4 + (j & 3);
            arr[(kq * 4 + 0) * 68 + col] = w4.x;
            arr[(kq * 4 + 1) * 68 + col] = w4.y;
            arr[(kq * 4 + 2) * 68 + col] = w4.z;
            arr[(kq * 4 + 3) * 68 + col] = w4.w;
        }
    }
    __syncthreads();

    const int hg = t & 15;
    const int h0 = hg * 8;
    const int eb = (t >> 4) * 8;

    ull acc[8][4];
#pragma unroll
    for (int e = 0; e < 8; e++)
#pragma unroll
        for (int j = 0; j < 4; j++) acc[e][j] = 0ull;

    for (int k0 = 0; k0 < NR; k0 += 4) {
        float4 a4[8];
#pragma unroll
        for (int e = 0; e < 8; e++)
            a4[e] = *(const float4*)&sA[(eb + e) * 64 + k0];
#pragma unroll
        for (int kk = 0; kk < 4; kk++) {
            ulonglong2 wa = *(const ulonglong2*)&sWA[(k0 + kk) * 68 + hg * 4];
            ulonglong2 wb = *(const ulonglong2*)&sWB[(k0 + kk) * 68 + hg * 4];
#pragma unroll
            for (int e = 0; e < 8; e++) {
                float a = (kk == 0) ? a4[e].x : (kk == 1) ? a4[e].y
                          : (kk == 2) ? a4[e].z : a4[e].w;
                ull ap = pk2(a, a);
                acc[e][0] = fma2(wa.x, ap, acc[e][0]);
                acc[e][1] = fma2(wa.y, ap, acc[e][1]);
                acc[e][2] = fma2(wb.x, ap, acc[e][2]);
                acc[e][3] = fma2(wb.y, ap, acc[e][3]);
            }
        }
    }

#pragma unroll
    for (int e = 0; e < 8; e++) {
        size_t idx = (size_t)(e0 + eb + e) * 384 + blockIdx.y * 128 + h0;
        unsigned p[4];
#pragma unroll
        for (int j = 0; j < 4; j++) {
            float a0, a1;
            unpk2(acc[e][j], a0, a1);
            __half2 hv = __floats2half2_rn(a0, a1);
            p[j] = *(unsigned*)&hv;
        }
        uint4 u = make_uint4(p[0], p[1], p[2], p[3]);
        *(uint4*)(&g_fh[idx]) = u;
    }
}

// ---------------- kT: transpose W_emb2 ----------------
__global__ void kT_trans(const float* __restrict__ W) {
    __shared__ float s[32][33];
    int tx = threadIdx.x, ty = threadIdx.y;
    int c0 = blockIdx.x * 32, h0 = blockIdx.y * 32;
    s[ty][tx] = W[(h0 + ty) * 256 + c0 + tx];
    __syncthreads();
    int k0 = (c0 < 128) ? c0 : c0 - 128;
    int j0 = (c0 < 128) ? h0 : 128 + h0;
    g_WT[(k0 + ty) * 256 + j0 + tx] = s[tx][ty];
}

// ---------------- k1z: ZPt/ZQt tables ----------------
__global__ __launch_bounds__(256) void k1z_tab(const float* __restrict__ emb) {
    __shared__ float sE[128];
    int zz = blockIdx.x, t = threadIdx.x;
    if (t < 128) sE[t] = emb[(size_t)zz * HD + t];
    __syncthreads();
    float a0 = 0.f, a1 = 0.f;
#pragma unroll 8
    for (int k = 0; k < 128; k += 2) {
        a0 += g_WT[k * 256 + t] * sE[k];
        a1 += g_WT[(k + 1) * 256 + t] * sE[k + 1];
    }
    float acc = a0 + a1;
    if (t < 128) g_ZPt[zz * HD + t] = acc;
    else         g_ZQt[zz * HD + t - 128] = acc;
}

// ---------------- ke: epilogue ----------------
__global__ __launch_bounds__(512) void ke_epi(
    const int* __restrict__ ei, const float* __restrict__ ew,
    const float* __restrict__ evec, const int* __restrict__ z,
    const float* __restrict__ b_emb2,
    const float* __restrict__ bd1, const float* __restrict__ bd2,
    const float* __restrict__ bd3) {
    __shared__ float sCut[64], sVx[64], sVy[64], sVz[64];
    __shared__ int sSrc[64], sZs[64], sZd[64], sPe[64];
    const int tid = threadIdx.x;
    const int e0 = blockIdx.x * 64;
    if (tid < 64) {
        int pe = g_perm[e0 + tid];
        sPe[tid] = pe;
        int s = ei[pe], d = ei[NE + pe];
        sSrc[tid] = s;
        sZs[tid] = z[s];
        sZd[tid] = z[d];
        float w = ew[pe];
        sCut[tid] = (w < 5.0f) ? 0.5f * (cosf(w * PI_OVER_CUT) + 1.0f) : 0.0f;
        sVx[tid] = evec[3 * pe + 0];
        sVy[tid] = evec[3 * pe + 1];
        sVz[tid] = evec[3 * pe + 2];
    }
    __syncthreads();

    const int h = tid & 127;
    const int grp = tid >> 7;
    const float bemb = b_emb2[h];
    const float b1 = bd1[h], b2 = bd2[h], b3 = bd3[h];

    float racc[10];
#pragma unroll
    for (int c = 0; c < 10; c++) racc[c] = 0.f;
    int cur = sSrc[grp * 16];

#define FLUSH()                                                  \
    do {                                                         \
        float* p_ = &g_acc[((size_t)cur * HD + h) * AS];         \
        red4(p_, racc[0], racc[1], racc[2], racc[3]);            \
        red4(p_ + 4, racc[4], racc[5], racc[6], racc[7]);        \
        red2(p_ + 8, racc[8], racc[9]);                          \
    } while (0)

#pragma unroll 2
    for (int i = 0; i < 16; i++) {
        int e = grp * 16 + i;
        int pe = sPe[e];
        int s = sSrc[e];
        const __half* fp = &g_fh[(size_t)pe * 384 + h];
        float f1 = __half2float(fp[0]);
        float f2 = __half2float(fp[128]);
        float f3 = __half2float(fp[256]);
        float C = sCut[e] * (g_ZPt[sZs[e] * HD + h] + g_ZQt[sZd[e] * HD + h] + bemb);
        f1 = (f1 + b1) * C;
        f2 = (f2 + b2) * C;
        f3 = (f3 + b3) * C;
        if (s != cur) {
            FLUSH();
#pragma unroll
            for (int c = 0; c < 10; c++) racc[c] = 0.f;
            cur = s;
        }
        float vx = sVx[e], vy = sVy[e], vz = sVz[e];
        racc[0] += f1;
        racc[1] += f2 * vx; racc[2] += f2 * vy; racc[3] += f2 * vz;
        float f3x = f3 * vx, f3y = f3 * vy, f3z = f3 * vz;
        racc[4] += f3x * vx; racc[5] += f3x * vy; racc[6] += f3x * vz;
        racc[7] += f3y * vy; racc[8] += f3y * vz; racc[9] += f3z * vz;
    }
    FLUSH();
#undef FLUSH
}

// ---------------- k3: tn + LayerNorm ----------------
__global__ void k3_tnln(const float* __restrict__ ln_g, const float* __restrict__ ln_b) {
    __shared__ float sred[4];
    __shared__ float sval;
    int n = blockIdx.x, h = threadIdx.x;
    const float* a = &g_acc[((size_t)n * HD + h) * AS];
    float4 p0 = *(const float4*)a;
    float4 p1 = *(const float4*)(a + 4);
    float2 p2 = *(const float2*)(a + 8);
    float s1 = p0.x, wx = p0.y, wy = p0.z, wz = p0.w;
    float mxx = p1.x, mxy = p1.y, mxz = p1.z, myy = p1.w, myz = p2.x, mzz = p2.y;
    float tr3 = (mxx + myy + mzz) * (1.0f / 3.0f);
    float dxx = s1 + mxx - tr3, dyy = s1 + myy - tr3, dzz = s1 + mzz - tr3;
    float t01 = mxy - wz, t10 = mxy + wz, t02 = mxz + wy;
    float t20 = mxz - wy, t12 = myz - wx, t21 = myz + wx;
    float tn = dxx * dxx + dyy * dyy + dzz * dzz + t01 * t01 + t10 * t10 +
               t02 * t02 + t20 * t20 + t12 * t12 + t21 * t21;

    float v = tn;
#pragma unroll
    for (int o = 16; o; o >>= 1) v += __shfl_xor_sync(0xffffffffu, v, o);
    if ((h & 31) == 0) sred[h >> 5] = v;
    __syncthreads();
    if (h == 0) sval = (sred[0] + sred[1] + sred[2] + sred[3]) * (1.0f / HD);
    __syncthreads();
    float mu = sval;
    float dv = tn - mu;
    v = dv * dv;
#pragma unroll
    for (int o = 16; o; o >>= 1) v += __shfl_xor_sync(0xffffffffu, v, o);
    __syncthreads();
    if ((h & 31) == 0) sred[h >> 5] = v;
    __syncthreads();
    if (h == 0) sval = rsqrtf((sred[0] + sred[1] + sred[2] + sred[3]) * (1.0f / HD) + 1e-5f);
    __syncthreads();
    g_ln[(size_t)n * HD + h] = dv * sval * ln_g[h] + ln_b[h];
}

// ---------------- k4a: y1 = silu(Ws1 @ ln + bs1) [20 nodes/blk, 16-h chunks] ----
__global__ __launch_bounds__(256, 3) void k4a_gemm(
    const float* __restrict__ Ws1, const float* __restrict__ bs1) {
    __shared__ float sXT[HD * 20];       // [hh][nl]
    __shared__ float sW[16 * 257];
    const int t = threadIdx.x;
    const int nb = blockIdx.x * 20;
    for (int i = t; i < 20 * HD; i += 256) {
        int nl = i >> 7, hh = i & 127;
        sXT[hh * 20 + nl] = g_ln[(size_t)(nb + nl) * HD + hh];
    }
    ull acc[10];
#pragma unroll
    for (int c = 0; c < 10; c++) acc[c] = 0ull;

    for (int h0 = 0; h0 < HD; h0 += 16) {
        __syncthreads();
#pragma unroll
        for (int r = 0; r < 16; r++) {
            int i = t + 256 * r;
            int j = i >> 4, hh = i & 15;
            sW[hh * 257 + j] = Ws1[j * HD + h0 + hh];
        }
        __syncthreads();
#pragma unroll 4
        for (int hh = 0; hh < 16; hh++) {
            float w = sW[hh * 257 + t];
            ull wp = pk2(w, w);
            const ulonglong2* xp = (const ulonglong2*)&sXT[(h0 + hh) * 20];
            ulonglong2 x0 = xp[0], x1 = xp[1];
            ulonglong2 x2 = xp[2], x3 = xp[3];
            ulonglong2 x4 = xp[4];
            acc[0] = fma2(wp, x0.x, acc[0]);
            acc[1] = fma2(wp, x0.y, acc[1]);
            acc[2] = fma2(wp, x1.x, acc[2]);
            acc[3] = fma2(wp, x1.y, acc[3]);
            acc[4] = fma2(wp, x2.x, acc[4]);
            acc[5] = fma2(wp, x2.y, acc[5]);
            acc[6] = fma2(wp, x3.x, acc[6]);
            acc[7] = fma2(wp, x3.y, acc[7]);
            acc[8] = fma2(wp, x4.x, acc[8]);
            acc[9] = fma2(wp, x4.y, acc[9]);
        }
    }
    float bb = bs1[t];
#pragma unroll
    for (int c = 0; c < 10; c++) {
        float a0, a1;
        unpk2(acc[c], a0, a1);
        g_y1[(size_t)(nb + 2 * c) * 256 + t]     = silu_f(a0 + bb);
        g_y1[(size_t)(nb + 2 * c + 1) * 256 + t] = silu_f(a1 + bb);
    }
}

// ---------------- k4b: nrm = silu(Ws2 @ y1 + bs2) [20 nodes/blk, 16-k chunks] ----
__global__ __launch_bounds__(384, 2) void k4b_gemm(
    const float* __restrict__ Ws2, const float* __restrict__ bs2) {
    extern __shared__ float smb[];
    float* sYT = smb;            // [256 kk][20 nl]
    float* sW  = smb + 256 * 20; // [16 kk][385]
    const int t = threadIdx.x;
    const int nb = blockIdx.x * 20;
    for (int i = t; i < 20 * 256; i += 384) {
        int nl = i >> 8, kk = i & 255;
        sYT[kk * 20 + nl] = g_y1[(size_t)(nb + nl) * 256 + kk];
    }
    ull acc[10];
#pragma unroll
    for (int c = 0; c < 10; c++) acc[c] = 0ull;

    for (int k0 = 0; k0 < 256; k0 += 16) {
        __syncthreads();
#pragma unroll
        for (int r = 0; r < 16; r++) {
            int i = t + 384 * r;
            int j = i >> 4, kk = i & 15;
            sW[kk * 385 + j] = Ws2[j * 256 + k0 + kk];
        }
        __syncthreads();
#pragma unroll 4
        for (int kk = 0; kk < 16; kk++) {
            float w = sW[kk * 385 + t];
            ull wp = pk2(w, w);
            const ulonglong2* xp = (const ulonglong2*)&sYT[(k0 + kk) * 20];
            ulonglong2 x0 = xp[0], x1 = xp[1];
            ulonglong2 x2 = xp[2], x3 = xp[3];
            ulonglong2 x4 = xp[4];
            acc[0] = fma2(wp, x0.x, acc[0]);
            acc[1] = fma2(wp, x0.y, acc[1]);
            acc[2] = fma2(wp, x1.x, acc[2]);
            acc[3] = fma2(wp, x1.y, acc[3]);
            acc[4] = fma2(wp, x2.x, acc[4]);
            acc[5] = fma2(wp, x2.y, acc[5]);
            acc[6] = fma2(wp, x3.x, acc[6]);
            acc[7] = fma2(wp, x3.y, acc[7]);
            acc[8] = fma2(wp, x4.x, acc[8]);
            acc[9] = fma2(wp, x4.y, acc[9]);
        }
    }
    float bb = bs2[t];
#pragma unroll
    for (int c = 0; c < 10; c++) {
        float a0, a1;
        unpk2(acc[c], a0, a1);
        g_nrm[(size_t)(nb + 2 * c) * 384 + t]     = silu_f(a0 + bb);
        g_nrm[(size_t)(nb + 2 * c + 1) * 384 + t] = silu_f(a1 + bb);
    }
}

// ---------------- k5: Wt transforms + output (2g x 2nl tile, 8-hh chunks) ----
__global__ __launch_bounds__(256, 2) void k5_out(
    const float* __restrict__ Wt1, const float* __restrict__ Wt2,
    const float* __restrict__ Wt3, float* __restrict__ out) {
    extern __shared__ float sm[];
    float* sAcc = sm;                // [8][128][12]
    float* sWt  = sm + 8 * HD * AS;  // [8][390]
    int t  = threadIdx.x;
    int nb = blockIdx.x * 8;
    {
        float4* gsrc = (float4*)&g_acc[(size_t)nb * HD * AS];
        float4* dst = (float4*)sAcc;
        for (int i = t; i < 8 * HD * 3; i += 256) dst[i] = gsrc[i];
        __syncthreads();
        float4 zz = make_float4(0.f, 0.f, 0.f, 0.f);
        for (int i = t; i < 8 * HD * 3; i += 256) gsrc[i] = zz;
    }

    const int g0 = (t & 63) * 2;
    const int n0 = (t >> 6) * 2;

    ull acc[2][2][5];
#pragma unroll
    for (int gi = 0; gi < 2; gi++)
#pragma unroll
        for (int ni = 0; ni < 2; ni++)
#pragma unroll
            for (int c = 0; c < 5; c++) acc[gi][ni][c] = 0ull;

    for (int h0 = 0; h0 < HD; h0 += 8) {
        __syncthreads();
#pragma unroll
        for (int r = 0; r < 12; r++) {
            int i = t + 256 * r;
            int m = i >> 10;
            int rr = i & 1023;
            int gg = rr >> 3, hh = rr & 7;
            const float* W = (m == 0) ? Wt1 : ((m == 1) ? Wt2 : Wt3);
            sWt[hh * 390 + m * 128 + gg] = W[gg * HD + h0 + hh];
        }
        __syncthreads();
#pragma unroll
        for (int hh = 0; hh < 8; hh++) {
            const float* wrow = &sWt[hh * 390];
            float2 w1 = *(const float2*)&wrow[g0];
            float2 w2 = *(const float2*)&wrow[128 + g0];
            float2 w3 = *(const float2*)&wrow[256 + g0];
            ull pw12a = pk2(w1.x, w2.x), pw22a = pk2(w2.x, w2.x), pw33a = pk2(w3.x, w3.x);
            ull pw12b = pk2(w1.y, w2.y), pw22b = pk2(w2.y, w2.y), pw33b = pk2(w3.y, w3.y);
#pragma unroll
            for (int ni = 0; ni < 2; ni++) {
                const ull* ap = (const ull*)&sAcc[((n0 + ni) * HD + h0 + hh) * AS];
                ulonglong2 q0 = *(const ulonglong2*)ap;
                ulonglong2 q1 = *(const ulonglong2*)(ap + 2);
                ull q2 = ap[4];
                acc[0][ni][0] = fma2(pw12a, q0.x, acc[0][ni][0]);
                acc[0][ni][1] = fma2(pw22a, q0.y, acc[0][ni][1]);
                acc[0][ni][2] = fma2(pw33a, q1.x, acc[0][ni][2]);
                acc[0][ni][3] = fma2(pw33a, q1.y, acc[0][ni][3]);
                acc[0][ni][4] = fma2(pw33a, q2,   acc[0][ni][4]);
                acc[1][ni][0] = fma2(pw12b, q0.x, acc[1][ni][0]);
                acc[1][ni][1] = fma2(pw22b, q0.y, acc[1][ni][1]);
                acc[1][ni][2] = fma2(pw33b, q1.x, acc[1][ni][2]);
                acc[1][ni][3] = fma2(pw33b, q1.y, acc[1][ni][3]);
                acc[1][ni][4] = fma2(pw33b, q2,   acc[1][ni][4]);
            }
        }
    }

#pragma unroll
    for (int gi = 0; gi < 2; gi++)
#pragma unroll
    for (int ni = 0; ni < 2; ni++) {
        int n = nb + n0 + ni;
        int g = g0 + gi;
        float nr0 = g_nrm[(size_t)n * 384 + g * 3 + 0];
        float nr1 = g_nrm[(size_t)n * 384 + g * 3 + 1];
        float nr2 = g_nrm[(size_t)n * 384 + g * 3 + 2];
        float s1, wx, wy, wz, mxx, mxy, mxz, myy, myz, mzz;
        unpk2(acc[gi][ni][0], s1, wx);
        unpk2(acc[gi][ni][1], wy, wz);
        unpk2(acc[gi][ni][2], mxx, mxy);
        unpk2(acc[gi][ni][3], mxz, myy);
        unpk2(acc[gi][ni][4], myz, mzz);
        float tr3 = (mxx + myy + mzz) * (1.0f / 3.0f);
        float dI = nr0 * s1;
        float* o = out + ((size_t)n * HD + g) * 9;
        o[0] = dI + nr2 * (mxx - tr3);
        o[1] = -nr1 * wz + nr2 * mxy;
        o[2] =  nr1 * wy + nr2 * mxz;
        o[3] =  nr1 * wz + nr2 * mxy;
        o[4] = dI + nr2 * (myy - tr3);
        o[5] = -nr1 * wx + nr2 * myz;
        o[6] = -nr1 * wy + nr2 * mxz;
        o[7] =  nr1 * wx + nr2 * myz;
        o[8] = dI + nr2 * (mzz - tr3);
    }
}

#define KG_SMEM ((128 * 64 + 2 * 64 * 68) * 4)
#define K4B_SMEM ((256 * 20 + 16 * 385) * 4)
#define K5_SMEM ((8 * HD * AS + 8 * 390) * 4)

extern "C" void kernel_launch(void* const* d_in, const int* in_sizes, int n_in,
                              void* d_out, int out_size) {
    (void)in_sizes; (void)n_in; (void)out_size;
    const int*   z      = (const int*)d_in[0];
    const int*   ei     = (const int*)d_in[1];
    const float* ew     = (const float*)d_in[2];
    const float* evec   = (const float*)d_in[3];
    const float* eattr  = (const float*)d_in[4];
    const float* emb    = (const float*)d_in[5];
    const float* W_emb2 = (const float*)d_in[6];
    const float* b_emb2 = (const float*)d_in[7];
    const float* Wd1 = (const float*)d_in[8],  *bd1 = (const float*)d_in[9];
    const float* Wd2 = (const float*)d_in[10], *bd2 = (const float*)d_in[11];
    const float* Wd3 = (const float*)d_in[12], *bd3 = (const float*)d_in[13];
    const float* Wt1 = (const float*)d_in[14], *Wt2 = (const float*)d_in[15];
    const float* Wt3 = (const float*)d_in[16];
    const float* Ws1 = (const float*)d_in[17], *bs1 = (const float*)d_in[18];
    const float* Ws2 = (const float*)d_in[19], *bs2 = (const float*)d_in[20];
    const float* ln_g = (const float*)d_in[21], *ln_b = (const float*)d_in[22];
    float* out = (float*)d_out;

    cudaFuncSetAttribute(kg_gemm,  cudaFuncAttributeMaxDynamicSharedMemorySize, KG_SMEM);
    cudaFuncSetAttribute(k4b_gemm, cudaFuncAttributeMaxDynamicSharedMemorySize, K4B_SMEM);
    cudaFuncSetAttribute(k5_out,   cudaFuncAttributeMaxDynamicSharedMemorySize, K5_SMEM);

    khist<<<(NE + 511) / 512, 512>>>(ei);                               // 1
    ks_scan<<<1, 1024>>>();                                             // 2
    ks_scatter<<<(NE + 511) / 512, 512>>>(ei);                          // 3
    kg_gemm<<<dim3(NE / 128, 3), 256, KG_SMEM>>>(eattr, Wd1, Wd2, Wd3); // 4 <- PROFILED
    kT_trans<<<dim3(8, 4), dim3(32, 32)>>>(W_emb2);                     // 5
    k1z_tab<<<MZ, 256>>>(emb);                                          // 6
    ke_epi<<<NE / 64, 512>>>(ei, ew, evec, z, b_emb2, bd1, bd2, bd3);   // 7
    k3_tnln<<<NN, 128>>>(ln_g, ln_b);                                   // 8
    k4a_gemm<<<NN / 20, 256>>>(Ws1, bs1);                               // 9
    k4b_gemm<<<NN / 20, 384, K4B_SMEM>>>(Ws2, bs2);                     // 10
    k5_out<<<NN / 8, 256, K5_SMEM>>>(Wt1, Wt2, Wt3, out);               // 11
}

// round 11
// speedup vs baseline: 2.6446x; 1.1702x over previous
#include <cuda_runtime.h>
#include <cuda_fp16.h>
#include <math.h>
#include <stdint.h>

#define NN 5000
#define NE 80000
#define HD 128
#define NR 64
#define AS 12
#define MZ 128

#define PI_OVER_CUT 0.6283185307179586f

typedef unsigned long long ull;

__device__ __align__(16) float g_WT[256 * 256];
__device__ __align__(16) float g_ZPt[MZ * HD];
__device__ __align__(16) float g_ZQt[MZ * HD];
__device__ __align__(16) float g_acc[(size_t)NN * HD * AS];  // zero-init; re-zeroed by k5
__device__ __align__(16) float g_ln[NN * HD];
__device__ __align__(16) float g_y1[NN * 256];
__device__ __align__(16) float g_nrm[NN * HD * 3];
__device__ __align__(16) __half g_fh[(size_t)NE * 384];
__device__ int g_hist[NN];                           // zero-init; re-zeroed by scatter
__device__ int g_cur[NN];
__device__ int g_perm[NE];

__device__ __forceinline__ void red4(float* p, float a, float b, float c, float d) {
    asm volatile("red.global.add.v4.f32 [%0], {%1,%2,%3,%4};"
                 :: "l"(p), "f"(a), "f"(b), "f"(c), "f"(d) : "memory");
}
__device__ __forceinline__ void red2(float* p, float a, float b) {
    asm volatile("red.global.add.v2.f32 [%0], {%1,%2};"
                 :: "l"(p), "f"(a), "f"(b) : "memory");
}
__device__ __forceinline__ ull pk2(float a, float b) {
    ull r;
    asm("mov.b64 %0, {%1,%2};" : "=l"(r) : "f"(a), "f"(b));
    return r;
}
__device__ __forceinline__ void unpk2(ull v, float& a, float& b) {
    asm("mov.b64 {%0,%1}, %2;" : "=f"(a), "=f"(b) : "l"(v));
}
__device__ __forceinline__ ull fma2(ull a, ull b, ull c) {
    ull d;
    asm("fma.rn.f32x2 %0, %1, %2, %3;" : "=l"(d) : "l"(a), "l"(b), "l"(c));
    return d;
}
__device__ __forceinline__ float silu_f(float x) { return x / (1.0f + expf(-x)); }
__device__ __forceinline__ uint32_t smem_u32(const void* p) {
    uint32_t a;
    asm("{ .reg .u64 tmp; cvta.to.shared.u64 tmp, %1; cvt.u32.u64 %0, tmp; }"
        : "=r"(a) : "l"(p));
    return a;
}

// ---------------- khist ----------------
__global__ void khist(const int* __restrict__ ei) {
    int e = blockIdx.x * blockDim.x + threadIdx.x;
    if (e < NE) atomicAdd(&g_hist[ei[e]], 1);
}

// ---------------- scan ----------------
__global__ void ks_scan() {
    __shared__ int wsum[32];
    __shared__ int carry;
    int t = threadIdx.x, lane = t & 31, wid = t >> 5;
    if (t == 0) carry = 0;
    __syncthreads();
    for (int c = 0; c < 5; c++) {
        int idx = c * 1024 + t;
        int v = (idx < NN) ? g_hist[idx] : 0;
        int x = v;
#pragma unroll
        for (int o = 1; o < 32; o <<= 1) {
            int y = __shfl_up_sync(0xffffffffu, x, o);
            if (lane >= o) x += y;
        }
        if (lane == 31) wsum[wid] = x;
        __syncthreads();
        if (wid == 0) {
            int s = wsum[lane];
#pragma unroll
            for (int o = 1; o < 32; o <<= 1) {
                int y = __shfl_up_sync(0xffffffffu, s, o);
                if (lane >= o) s += y;
            }
            wsum[lane] = s;
        }
        __syncthreads();
        int pref = carry + (wid ? wsum[wid - 1] : 0) + x - v;
        if (idx < NN) g_cur[idx] = pref;
        __syncthreads();
        if (t == 0) carry += wsum[31];
        __syncthreads();
    }
}

// ---------------- scatter (re-zeroes g_hist) ----------------
__global__ void ks_scatter(const int* __restrict__ ei) {
    int e = blockIdx.x * blockDim.x + threadIdx.x;
    if (e < NE) {
        int s = ei[e];
        int p = atomicAdd(&g_cur[s], 1);
        g_perm[p] = e;
    }
    for (int i = e; i < NN; i += gridDim.x * blockDim.x) g_hist[i] = 0;
}

// ---------------- kg_hmma: mma.sync GEMM  g_fh[e, y*128+h] — PROFILED ----------------
// grid (625, 3), 256 threads. Block tile: 128 edges x 128 h, K = 64.
// Warp w computes edges [w*16, w*16+16) x all 128 h via m16n8k16 HMMA.
#define SROW 72   // halves per smem row (64 + 8 pad); 144B stride, ldmatrix conflict-free
__global__ __launch_bounds__(256) void kg_hmma(
    const float* __restrict__ eattr,
    const float* __restrict__ Wd1, const float* __restrict__ Wd2,
    const float* __restrict__ Wd3) {
    __shared__ __half sA[128 * SROW];
    __shared__ __half sW[128 * SROW];
    const int t = threadIdx.x;
    const int warp = t >> 5, lane = t & 31;
    const int e0 = blockIdx.x * 128;
    const int y = blockIdx.y;
    const float* W = (y == 0) ? Wd1 : ((y == 1) ? Wd2 : Wd3);

    // stage A (128 e x 64 k) and W (128 h x 64 k) as fp16, padded rows
    {
        const float2* srcA = (const float2*)(eattr + (size_t)e0 * NR);
        const float2* srcW = (const float2*)W;
#pragma unroll
        for (int r = 0; r < 16; r++) {
            int i = t + 256 * r;               // 0..4095 (float2 units)
            int row = i >> 5, c2 = i & 31;
            *(__half2*)&sA[row * SROW + c2 * 2] = __float22half2_rn(srcA[i]);
            *(__half2*)&sW[row * SROW + c2 * 2] = __float22half2_rn(srcW[i]);
        }
    }
    __syncthreads();

    const uint32_t sAb = smem_u32(sA);
    const uint32_t sWb = smem_u32(sW);

    // A fragments for 4 k-steps (16 regs)
    uint32_t af[4][4];
#pragma unroll
    for (int ks = 0; ks < 4; ks++) {
        uint32_t addr = sAb +
            2 * ((uint32_t)(warp * 16 + (lane & 15)) * SROW + ks * 16 + (lane >> 4) * 8);
        asm volatile("ldmatrix.sync.aligned.m8n8.x4.shared.b16 {%0,%1,%2,%3}, [%4];"
                     : "=r"(af[ks][0]), "=r"(af[ks][1]), "=r"(af[ks][2]), "=r"(af[ks][3])
                     : "r"(addr));
    }

    float d[16][4];
#pragma unroll
    for (int n = 0; n < 16; n++)
#pragma unroll
        for (int c = 0; c < 4; c++) d[n][c] = 0.f;

#pragma unroll
    for (int n = 0; n < 16; n++) {
#pragma unroll
        for (int ks = 0; ks < 4; ks++) {
            uint32_t b0, b1;
            uint32_t addr = sWb +
                2 * ((uint32_t)(n * 8 + (lane & 7)) * SROW + ks * 16 + ((lane >> 3) & 1) * 8);
            asm volatile("ldmatrix.sync.aligned.m8n8.x2.shared.b16 {%0,%1}, [%2];"
                         : "=r"(b0), "=r"(b1) : "r"(addr));
            asm volatile(
                "mma.sync.aligned.m16n8k16.row.col.f32.f16.f16.f32 "
                "{%0,%1,%2,%3}, {%4,%5,%6,%7}, {%8,%9}, {%0,%1,%2,%3};"
                : "+f"(d[n][0]), "+f"(d[n][1]), "+f"(d[n][2]), "+f"(d[n][3])
                : "r"(af[ks][0]), "r"(af[ks][1]), "r"(af[ks][2]), "r"(af[ks][3]),
                  "r"(b0), "r"(b1));
        }
    }

    // epilogue: lane holds rows (lane>>2) and (lane>>2)+8, cols (lane&3)*2,+1 per n-tile
    {
        int r0 = lane >> 2, cb = (lane & 3) * 2;
        size_t base0 = (size_t)(e0 + warp * 16 + r0) * 384 + y * 128;
        size_t base1 = (size_t)(e0 + warp * 16 + r0 + 8) * 384 + y * 128;
#pragma unroll
        for (int n = 0; n < 16; n++) {
            *(__half2*)&g_fh[base0 + n * 8 + cb] = __floats2half2_rn(d[n][0], d[n][1]);
            *(__half2*)&g_fh[base1 + n * 8 + cb] = __floats2half2_rn(d[n][2], d[n][3]);
        }
    }
}

// ---------------- kT: transpose W_emb2 ----------------
__global__ void kT_trans(const float* __restrict__ W) {
    __shared__ float s[32][33];
    int tx = threadIdx.x, ty = threadIdx.y;
    int c0 = blockIdx.x * 32, h0 = blockIdx.y * 32;
    s[ty][tx] = W[(h0 + ty) * 256 + c0 + tx];
    __syncthreads();
    int k0 = (c0 < 128) ? c0 : c0 - 128;
    int j0 = (c0 < 128) ? h0 : 128 + h0;
    g_WT[(k0 + ty) * 256 + j0 + tx] = s[tx][ty];
}

// ---------------- k1z: ZPt/ZQt tables ----------------
__global__ __launch_bounds__(256) void k1z_tab(const float* __restrict__ emb) {
    __shared__ float sE[128];
    int zz = blockIdx.x, t = threadIdx.x;
    if (t < 128) sE[t] = emb[(size_t)zz * HD + t];
    __syncthreads();
    float a0 = 0.f, a1 = 0.f;
#pragma unroll 8
    for (int k = 0; k < 128; k += 2) {
        a0 += g_WT[k * 256 + t] * sE[k];
        a1 += g_WT[(k + 1) * 256 + t] * sE[k + 1];
    }
    float acc = a0 + a1;
    if (t < 128) g_ZPt[zz * HD + t] = acc;
    else         g_ZQt[zz * HD + t - 128] = acc;
}

// ---------------- ke: epilogue ----------------
__global__ __launch_bounds__(512) void ke_epi(
    const int* __restrict__ ei, const float* __restrict__ ew,
    const float* __restrict__ evec, const int* __restrict__ z,
    const float* __restrict__ b_emb2,
    const float* __restrict__ bd1, const float* __restrict__ bd2,
    const float* __restrict__ bd3) {
    __shared__ float sCut[64], sVx[64], sVy[64], sVz[64];
    __shared__ int sSrc[64], sZs[64], sZd[64], sPe[64];
    const int tid = threadIdx.x;
    const int e0 = blockIdx.x * 64;
    if (tid < 64) {
        int pe = g_perm[e0 + tid];
        sPe[tid] = pe;
        int s = ei[pe], d = ei[NE + pe];
        sSrc[tid] = s;
        sZs[tid] = z[s];
        sZd[tid] = z[d];
        float w = ew[pe];
        sCut[tid] = (w < 5.0f) ? 0.5f * (cosf(w * PI_OVER_CUT) + 1.0f) : 0.0f;
        sVx[tid] = evec[3 * pe + 0];
        sVy[tid] = evec[3 * pe + 1];
        sVz[tid] = evec[3 * pe + 2];
    }
    __syncthreads();

    const int h = tid & 127;
    const int grp = tid >> 7;
    const float bemb = b_emb2[h];
    const float b1 = bd1[h], b2 = bd2[h], b3 = bd3[h];

    float racc[10];
#pragma unroll
    for (int c = 0; c < 10; c++) racc[c] = 0.f;
    int cur = sSrc[grp * 16];

#define FLUSH()                                                  \
    do {                                                         \
        float* p_ = &g_acc[((size_t)cur * HD + h) * AS];         \
        red4(p_, racc[0], racc[1], racc[2], racc[3]);            \
        red4(p_ + 4, racc[4], racc[5], racc[6], racc[7]);        \
        red2(p_ + 8, racc[8], racc[9]);                          \
    } while (0)

#pragma unroll 2
    for (int i = 0; i < 16; i++) {
        int e = grp * 16 + i;
        int pe = sPe[e];
        int s = sSrc[e];
        const __half* fp = &g_fh[(size_t)pe * 384 + h];
        float f1 = __half2float(fp[0]);
        float f2 = __half2float(fp[128]);
        float f3 = __half2float(fp[256]);
        float C = sCut[e] * (g_ZPt[sZs[e] * HD + h] + g_ZQt[sZd[e] * HD + h] + bemb);
        f1 = (f1 + b1) * C;
        f2 = (f2 + b2) * C;
        f3 = (f3 + b3) * C;
        if (s != cur) {
            FLUSH();
#pragma unroll
            for (int c = 0; c < 10; c++) racc[c] = 0.f;
            cur = s;
        }
        float vx = sVx[e], vy = sVy[e], vz = sVz[e];
        racc[0] += f1;
        racc[1] += f2 * vx; racc[2] += f2 * vy; racc[3] += f2 * vz;
        float f3x = f3 * vx, f3y = f3 * vy, f3z = f3 * vz;
        racc[4] += f3x * vx; racc[5] += f3x * vy; racc[6] += f3x * vz;
        racc[7] += f3y * vy; racc[8] += f3y * vz; racc[9] += f3z * vz;
    }
    FLUSH();
#undef FLUSH
}

// ---------------- k3: tn + LayerNorm ----------------
__global__ void k3_tnln(const float* __restrict__ ln_g, const float* __restrict__ ln_b) {
    __shared__ float sred[4];
    __shared__ float sval;
    int n = blockIdx.x, h = threadIdx.x;
    const float* a = &g_acc[((size_t)n * HD + h) * AS];
    float4 p0 = *(const float4*)a;
    float4 p1 = *(const float4*)(a + 4);
    float2 p2 = *(const float2*)(a + 8);
    float s1 = p0.x, wx = p0.y, wy = p0.z, wz = p0.w;
    float mxx = p1.x, mxy = p1.y, mxz = p1.z, myy = p1.w, myz = p2.x, mzz = p2.y;
    float tr3 = (mxx + myy + mzz) * (1.0f / 3.0f);
    float dxx = s1 + mxx - tr3, dyy = s1 + myy - tr3, dzz = s1 + mzz - tr3;
    float t01 = mxy - wz, t10 = mxy + wz, t02 = mxz + wy;
    float t20 = mxz - wy, t12 = myz - wx, t21 = myz + wx;
    float tn = dxx * dxx + dyy * dyy + dzz * dzz + t01 * t01 + t10 * t10 +
               t02 * t02 + t20 * t20 + t12 * t12 + t21 * t21;

    float v = tn;
#pragma unroll
    for (int o = 16; o; o >>= 1) v += __shfl_xor_sync(0xffffffffu, v, o);
    if ((h & 31) == 0) sred[h >> 5] = v;
    __syncthreads();
    if (h == 0) sval = (sred[0] + sred[1] + sred[2] + sred[3]) * (1.0f / HD);
    __syncthreads();
    float mu = sval;
    float dv = tn - mu;
    v = dv * dv;
#pragma unroll
    for (int o = 16; o; o >>= 1) v += __shfl_xor_sync(0xffffffffu, v, o);
    __syncthreads();
    if ((h & 31) == 0) sred[h >> 5] = v;
    __syncthreads();
    if (h == 0) sval = rsqrtf((sred[0] + sred[1] + sred[2] + sred[3]) * (1.0f / HD) + 1e-5f);
    __syncthreads();
    g_ln[(size_t)n * HD + h] = dv * sval * ln_g[h] + ln_b[h];
}

// ---------------- k4a: y1 = silu(Ws1 @ ln + bs1) [20 nodes/blk] ----
__global__ __launch_bounds__(256, 3) void k4a_gemm(
    const float* __restrict__ Ws1, const float* __restrict__ bs1) {
    __shared__ float sXT[HD * 20];
    __shared__ float sW[16 * 257];
    const int t = threadIdx.x;
    const int nb = blockIdx.x * 20;
    for (int i = t; i < 20 * HD; i += 256) {
        int nl = i >> 7, hh = i & 127;
        sXT[hh * 20 + nl] = g_ln[(size_t)(nb + nl) * HD + hh];
    }
    ull acc[10];
#pragma unroll
    for (int c = 0; c < 10; c++) acc[c] = 0ull;

    for (int h0 = 0; h0 < HD; h0 += 16) {
        __syncthreads();
#pragma unroll
        for (int r = 0; r < 16; r++) {
            int i = t + 256 * r;
            int j = i >> 4, hh = i & 15;
            sW[hh * 257 + j] = Ws1[j * HD + h0 + hh];
        }
        __syncthreads();
#pragma unroll 4
        for (int hh = 0; hh < 16; hh++) {
            float w = sW[hh * 257 + t];
            ull wp = pk2(w, w);
            const ulonglong2* xp = (const ulonglong2*)&sXT[(h0 + hh) * 20];
            ulonglong2 x0 = xp[0], x1 = xp[1];
            ulonglong2 x2 = xp[2], x3 = xp[3];
            ulonglong2 x4 = xp[4];
            acc[0] = fma2(wp, x0.x, acc[0]);
            acc[1] = fma2(wp, x0.y, acc[1]);
            acc[2] = fma2(wp, x1.x, acc[2]);
            acc[3] = fma2(wp, x1.y, acc[3]);
            acc[4] = fma2(wp, x2.x, acc[4]);
            acc[5] = fma2(wp, x2.y, acc[5]);
            acc[6] = fma2(wp, x3.x, acc[6]);
            acc[7] = fma2(wp, x3.y, acc[7]);
            acc[8] = fma2(wp, x4.x, acc[8]);
            acc[9] = fma2(wp, x4.y, acc[9]);
        }
    }
    float bb = bs1[t];
#pragma unroll
    for (int c = 0; c < 10; c++) {
        float a0, a1;
        unpk2(acc[c], a0, a1);
        g_y1[(size_t)(nb + 2 * c) * 256 + t]     = silu_f(a0 + bb);
        g_y1[(size_t)(nb + 2 * c + 1) * 256 + t] = silu_f(a1 + bb);
    }
}

// ---------------- k4b: nrm = silu(Ws2 @ y1 + bs2) [20 nodes/blk] ----
__global__ __launch_bounds__(384, 2) void k4b_gemm(
    const float* __restrict__ Ws2, const float* __restrict__ bs2) {
    extern __shared__ float smb[];
    float* sYT = smb;
    float* sW  = smb + 256 * 20;
    const int t = threadIdx.x;
    const int nb = blockIdx.x * 20;
    for (int i = t; i < 20 * 256; i += 384) {
        int nl = i >> 8, kk = i & 255;
        sYT[kk * 20 + nl] = g_y1[(size_t)(nb + nl) * 256 + kk];
    }
    ull acc[10];
#pragma unroll
    for (int c = 0; c < 10; c++) acc[c] = 0ull;

    for (int k0 = 0; k0 < 256; k0 += 16) {
        __syncthreads();
#pragma unroll
        for (int r = 0; r < 16; r++) {
            int i = t + 384 * r;
            int j = i >> 4, kk = i & 15;
            sW[kk * 385 + j] = Ws2[j * 256 + k0 + kk];
        }
        __syncthreads();
#pragma unroll 4
        for (int kk = 0; kk < 16; kk++) {
            float w = sW[kk * 385 + t];
            ull wp = pk2(w, w);
            const ulonglong2* xp = (const ulonglong2*)&sYT[(k0 + kk) * 20];
            ulonglong2 x0 = xp[0], x1 = xp[1];
            ulonglong2 x2 = xp[2], x3 = xp[3];
            ulonglong2 x4 = xp[4];
            acc[0] = fma2(wp, x0.x, acc[0]);
            acc[1] = fma2(wp, x0.y, acc[1]);
            acc[2] = fma2(wp, x1.x, acc[2]);
            acc[3] = fma2(wp, x1.y, acc[3]);
            acc[4] = fma2(wp, x2.x, acc[4]);
            acc[5] = fma2(wp, x2.y, acc[5]);
            acc[6] = fma2(wp, x3.x, acc[6]);
            acc[7] = fma2(wp, x3.y, acc[7]);
            acc[8] = fma2(wp, x4.x, acc[8]);
            acc[9] = fma2(wp, x4.y, acc[9]);
        }
    }
    float bb = bs2[t];
#pragma unroll
    for (int c = 0; c < 10; c++) {
        float a0, a1;
        unpk2(acc[c], a0, a1);
        g_nrm[(size_t)(nb + 2 * c) * 384 + t]     = silu_f(a0 + bb);
        g_nrm[(size_t)(nb + 2 * c + 1) * 384 + t] = silu_f(a1 + bb);
    }
}

// ---------------- k5: Wt transforms + output (2g x 2nl tile) ----
__global__ __launch_bounds__(256, 2) void k5_out(
    const float* __restrict__ Wt1, const float* __restrict__ Wt2,
    const float* __restrict__ Wt3, float* __restrict__ out) {
    extern __shared__ float sm[];
    float* sAcc = sm;                // [8][128][12]
    float* sWt  = sm + 8 * HD * AS;  // [8][390]
    int t  = threadIdx.x;
    int nb = blockIdx.x * 8;
    {
        float4* gsrc = (float4*)&g_acc[(size_t)nb * HD * AS];
        float4* dst = (float4*)sAcc;
        for (int i = t; i < 8 * HD * 3; i += 256) dst[i] = gsrc[i];
        __syncthreads();
        float4 zz = make_float4(0.f, 0.f, 0.f, 0.f);
        for (int i = t; i < 8 * HD * 3; i += 256) gsrc[i] = zz;
    }

    const int g0 = (t & 63) * 2;
    const int n0 = (t >> 6) * 2;

    ull acc[2][2][5];
#pragma unroll
    for (int gi = 0; gi < 2; gi++)
#pragma unroll
        for (int ni = 0; ni < 2; ni++)
#pragma unroll
            for (int c = 0; c < 5; c++) acc[gi][ni][c] = 0ull;

    for (int h0 = 0; h0 < HD; h0 += 8) {
        __syncthreads();
#pragma unroll
        for (int r = 0; r < 12; r++) {
            int i = t + 256 * r;
            int m = i >> 10;
            int rr = i & 1023;
            int gg = rr >> 3, hh = rr & 7;
            const float* W = (m == 0) ? Wt1 : ((m == 1) ? Wt2 : Wt3);
            sWt[hh * 390 + m * 128 + gg] = W[gg * HD + h0 + hh];
        }
        __syncthreads();
#pragma unroll
        for (int hh = 0; hh < 8; hh++) {
            const float* wrow = &sWt[hh * 390];
            float2 w1 = *(const float2*)&wrow[g0];
            float2 w2 = *(const float2*)&wrow[128 + g0];
            float2 w3 = *(const float2*)&wrow[256 + g0];
            ull pw12a = pk2(w1.x, w2.x), pw22a = pk2(w2.x, w2.x), pw33a = pk2(w3.x, w3.x);
            ull pw12b = pk2(w1.y, w2.y), pw22b = pk2(w2.y, w2.y), pw33b = pk2(w3.y, w3.y);
#pragma unroll
            for (int ni = 0; ni < 2; ni++) {
                const ull* ap = (const ull*)&sAcc[((n0 + ni) * HD + h0 + hh) * AS];
                ulonglong2 q0 = *(const ulonglong2*)ap;
                ulonglong2 q1 = *(const ulonglong2*)(ap + 2);
                ull q2 = ap[4];
                acc[0][ni][0] = fma2(pw12a, q0.x, acc[0][ni][0]);
                acc[0][ni][1] = fma2(pw22a, q0.y, acc[0][ni][1]);
                acc[0][ni][2] = fma2(pw33a, q1.x, acc[0][ni][2]);
                acc[0][ni][3] = fma2(pw33a, q1.y, acc[0][ni][3]);
                acc[0][ni][4] = fma2(pw33a, q2,   acc[0][ni][4]);
                acc[1][ni][0] = fma2(pw12b, q0.x, acc[1][ni][0]);
                acc[1][ni][1] = fma2(pw22b, q0.y, acc[1][ni][1]);
                acc[1][ni][2] = fma2(pw33b, q1.x, acc[1][ni][2]);
                acc[1][ni][3] = fma2(pw33b, q1.y, acc[1][ni][3]);
                acc[1][ni][4] = fma2(pw33b, q2,   acc[1][ni][4]);
            }
        }
    }

#pragma unroll
    for (int gi = 0; gi < 2; gi++)
#pragma unroll
    for (int ni = 0; ni < 2; ni++) {
        int n = nb + n0 + ni;
        int g = g0 + gi;
        float nr0 = g_nrm[(size_t)n * 384 + g * 3 + 0];
        float nr1 = g_nrm[(size_t)n * 384 + g * 3 + 1];
        float nr2 = g_nrm[(size_t)n * 384 + g * 3 + 2];
        float s1, wx, wy, wz, mxx, mxy, mxz, myy, myz, mzz;
        unpk2(acc[gi][ni][0], s1, wx);
        unpk2(acc[gi][ni][1], wy, wz);
        unpk2(acc[gi][ni][2], mxx, mxy);
        unpk2(acc[gi][ni][3], mxz, myy);
        unpk2(acc[gi][ni][4], myz, mzz);
        float tr3 = (mxx + myy + mzz) * (1.0f / 3.0f);
        float dI = nr0 * s1;
        float* o = out + ((size_t)n * HD + g) * 9;
        o[0] = dI + nr2 * (mxx - tr3);
        o[1] = -nr1 * wz + nr2 * mxy;
        o[2] =  nr1 * wy + nr2 * mxz;
        o[3] =  nr1 * wz + nr2 * mxy;
        o[4] = dI + nr2 * (myy - tr3);
        o[5] = -nr1 * wx + nr2 * myz;
        o[6] = -nr1 * wy + nr2 * mxz;
        o[7] =  nr1 * wx + nr2 * myz;
        o[8] = dI + nr2 * (mzz - tr3);
    }
}

#define K4B_SMEM ((256 * 20 + 16 * 385) * 4)
#define K5_SMEM ((8 * HD * AS + 8 * 390) * 4)

extern "C" void kernel_launch(void* const* d_in, const int* in_sizes, int n_in,
                              void* d_out, int out_size) {
    (void)in_sizes; (void)n_in; (void)out_size;
    const int*   z      = (const int*)d_in[0];
    const int*   ei     = (const int*)d_in[1];
    const float* ew     = (const float*)d_in[2];
    const float* evec   = (const float*)d_in[3];
    const float* eattr  = (const float*)d_in[4];
    const float* emb    = (const float*)d_in[5];
    const float* W_emb2 = (const float*)d_in[6];
    const float* b_emb2 = (const float*)d_in[7];
    const float* Wd1 = (const float*)d_in[8],  *bd1 = (const float*)d_in[9];
    const float* Wd2 = (const float*)d_in[10], *bd2 = (const float*)d_in[11];
    const float* Wd3 = (const float*)d_in[12], *bd3 = (const float*)d_in[13];
    const float* Wt1 = (const float*)d_in[14], *Wt2 = (const float*)d_in[15];
    const float* Wt3 = (const float*)d_in[16];
    const float* Ws1 = (const float*)d_in[17], *bs1 = (const float*)d_in[18];
    const float* Ws2 = (const float*)d_in[19], *bs2 = (const float*)d_in[20];
    const float* ln_g = (const float*)d_in[21], *ln_b = (const float*)d_in[22];
    float* out = (float*)d_out;

    cudaFuncSetAttribute(k4b_gemm, cudaFuncAttributeMaxDynamicSharedMemorySize, K4B_SMEM);
    cudaFuncSetAttribute(k5_out,   cudaFuncAttributeMaxDynamicSharedMemorySize, K5_SMEM);

    khist<<<(NE + 511) / 512, 512>>>(ei);                               // 1
    ks_scan<<<1, 1024>>>();                                             // 2
    kT_trans<<<dim3(8, 4), dim3(32, 32)>>>(W_emb2);                     // 3
    kg_hmma<<<dim3(NE / 128, 3), 256>>>(eattr, Wd1, Wd2, Wd3);          // 4 <- PROFILED
    k1z_tab<<<MZ, 256>>>(emb);                                          // 5
    ks_scatter<<<(NE + 511) / 512, 512>>>(ei);                          // 6
    ke_epi<<<NE / 64, 512>>>(ei, ew, evec, z, b_emb2, bd1, bd2, bd3);   // 7
    k3_tnln<<<NN, 128>>>(ln_g, ln_b);                                   // 8
    k4a_gemm<<<NN / 20, 256>>>(Ws1, bs1);                               // 9
    k4b_gemm<<<NN / 20, 384, K4B_SMEM>>>(Ws2, bs2);                     // 10
    k5_out<<<NN / 8, 256, K5_SMEM>>>(Wt1, Wt2, Wt3, out);               // 11
}

// round 12
// speedup vs baseline: 3.1917x; 1.2069x over previous
#include <cuda_runtime.h>
#include <cuda_fp16.h>
#include <math.h>
#include <stdint.h>

#define NN 5000
#define NE 80000
#define HD 128
#define NR 64
#define AS 12
#define MZ 128

#define PI_OVER_CUT 0.6283185307179586f

typedef unsigned long long ull;

__device__ __align__(16) float g_WT[256 * 256];
__device__ __align__(16) float g_ZPt[MZ * HD];
__device__ __align__(16) float g_ZQt[MZ * HD];
__device__ __align__(16) float g_acc[(size_t)NN * HD * AS];  // zero-init; re-zeroed by k5
__device__ __align__(16) float g_ln[NN * HD];
__device__ __align__(16) __half g_y1h[NN * 256];
__device__ __align__(16) __half g_ws2h[384 * 256];
__device__ __align__(16) float g_nrm[NN * HD * 3];
__device__ __align__(16) __half g_fh[(size_t)NE * 384];
__device__ int g_hist[NN];                           // zero-init; re-zeroed by kg y==2
__device__ int g_cur[NN];
__device__ int g_perm[NE];

__device__ __forceinline__ void red4(float* p, float a, float b, float c, float d) {
    asm volatile("red.global.add.v4.f32 [%0], {%1,%2,%3,%4};"
                 :: "l"(p), "f"(a), "f"(b), "f"(c), "f"(d) : "memory");
}
__device__ __forceinline__ void red2(float* p, float a, float b) {
    asm volatile("red.global.add.v2.f32 [%0], {%1,%2};"
                 :: "l"(p), "f"(a), "f"(b) : "memory");
}
__device__ __forceinline__ ull pk2(float a, float b) {
    ull r;
    asm("mov.b64 %0, {%1,%2};" : "=l"(r) : "f"(a), "f"(b));
    return r;
}
__device__ __forceinline__ void unpk2(ull v, float& a, float& b) {
    asm("mov.b64 {%0,%1}, %2;" : "=f"(a), "=f"(b) : "l"(v));
}
__device__ __forceinline__ ull fma2(ull a, ull b, ull c) {
    ull d;
    asm("fma.rn.f32x2 %0, %1, %2, %3;" : "=l"(d) : "l"(a), "l"(b), "l"(c));
    return d;
}
__device__ __forceinline__ float silu_f(float x) { return x / (1.0f + expf(-x)); }
__device__ __forceinline__ uint32_t smem_u32(const void* p) {
    uint32_t a;
    asm("{ .reg .u64 tmp; cvta.to.shared.u64 tmp, %1; cvt.u32.u64 %0, tmp; }"
        : "=r"(a) : "l"(p));
    return a;
}

// ---------------- 1. kA: khist (blocks 0..156) + W_emb2 transpose (157..188) ----
__global__ __launch_bounds__(512) void kA_histT(const int* __restrict__ ei,
                                                const float* __restrict__ W) {
    const int t = threadIdx.x;
    if (blockIdx.x < 157) {
        int e = blockIdx.x * 512 + t;
        if (e < NE) atomicAdd(&g_hist[ei[e]], 1);
    } else {
        __shared__ float s[32][33];
        int tb = blockIdx.x - 157;          // 0..31
        int c0 = (tb & 7) * 32, h0 = (tb >> 3) * 32;
        int tx = t & 31, ty0 = t >> 5;      // ty0 0..15
        s[ty0][tx]      = W[(h0 + ty0) * 256 + c0 + tx];
        s[ty0 + 16][tx] = W[(h0 + ty0 + 16) * 256 + c0 + tx];
        __syncthreads();
        int k0 = (c0 < 128) ? c0 : c0 - 128;
        int j0 = (c0 < 128) ? h0 : 128 + h0;
        g_WT[(k0 + ty0) * 256 + j0 + tx]      = s[tx][ty0];
        g_WT[(k0 + ty0 + 16) * 256 + j0 + tx] = s[tx][ty0 + 16];
    }
}

// ---------------- 2. kB: scan (blk 0) + k1z tables (1..32) + Ws2->fp16 (33..56) ----
__global__ __launch_bounds__(1024) void kB_multi(const float* __restrict__ emb,
                                                 const float* __restrict__ Ws2) {
    const int t = threadIdx.x;
    if (blockIdx.x == 0) {
        __shared__ int wsum[32];
        __shared__ int carry;
        int lane = t & 31, wid = t >> 5;
        if (t == 0) carry = 0;
        __syncthreads();
        for (int c = 0; c < 5; c++) {
            int idx = c * 1024 + t;
            int v = (idx < NN) ? g_hist[idx] : 0;
            int x = v;
#pragma unroll
            for (int o = 1; o < 32; o <<= 1) {
                int y = __shfl_up_sync(0xffffffffu, x, o);
                if (lane >= o) x += y;
            }
            if (lane == 31) wsum[wid] = x;
            __syncthreads();
            if (wid == 0) {
                int s = wsum[lane];
#pragma unroll
                for (int o = 1; o < 32; o <<= 1) {
                    int y = __shfl_up_sync(0xffffffffu, s, o);
                    if (lane >= o) s += y;
                }
                wsum[lane] = s;
            }
            __syncthreads();
            int pref = carry + (wid ? wsum[wid - 1] : 0) + x - v;
            if (idx < NN) g_cur[idx] = pref;
            __syncthreads();
            if (t == 0) carry += wsum[31];
            __syncthreads();
        }
    } else if (blockIdx.x <= 32) {
        __shared__ float sE[4 * 128];
        int zb = (blockIdx.x - 1) * 4;
        if (t < 4 * 128) sE[t] = emb[(size_t)zb * HD + t];
        __syncthreads();
        int g = t >> 8, j = t & 255;   // g 0..3, j 0..255
        int zz = zb + g;
        float a0 = 0.f, a1 = 0.f;
#pragma unroll 8
        for (int k = 0; k < 128; k += 2) {
            a0 += g_WT[k * 256 + j] * sE[g * 128 + k];
            a1 += g_WT[(k + 1) * 256 + j] * sE[g * 128 + k + 1];
        }
        float acc = a0 + a1;
        if (j < 128) g_ZPt[zz * HD + j] = acc;
        else         g_ZQt[zz * HD + j - 128] = acc;
    } else {
        int base = (blockIdx.x - 33) * 4096 + t;   // float2 units? use 2-float units
        const float2* src = (const float2*)Ws2;
        __half2* dst = (__half2*)g_ws2h;
        // 384*256/2 = 49152 float2; 24 blocks * 2048 = 49152
        int i = (blockIdx.x - 33) * 2048 + t;
        if (t < 1024) {
            dst[i] = __float22half2_rn(src[i]);
            dst[i + 1024] = __float22half2_rn(src[i + 1024]);
        }
    }
}

// ---------------- 3. kg_hmma: edge GEMM + scatter(y==1) + hist-zero(y==2) ----------
#define SROW 72
__global__ __launch_bounds__(256) void kg_hmma(
    const float* __restrict__ eattr,
    const float* __restrict__ Wd1, const float* __restrict__ Wd2,
    const float* __restrict__ Wd3, const int* __restrict__ ei) {
    __shared__ __half sA[128 * SROW];
    __shared__ __half sW[128 * SROW];
    const int t = threadIdx.x;
    const int warp = t >> 5, lane = t & 31;
    const int e0 = blockIdx.x * 128;
    const int y = blockIdx.y;
    const float* W = (y == 0) ? Wd1 : ((y == 1) ? Wd2 : Wd3);

    if (y == 1) {
        int e = blockIdx.x * 256 + t;
        if (e < NE) {
            int s = ei[e];
            int p = atomicAdd(&g_cur[s], 1);
            g_perm[p] = e;
        }
    } else if (y == 2) {
        int i = blockIdx.x * 256 + t;
        if (i < NN) g_hist[i] = 0;
    }

    {
        const float2* srcA = (const float2*)(eattr + (size_t)e0 * NR);
        const float2* srcW = (const float2*)W;
#pragma unroll
        for (int r = 0; r < 16; r++) {
            int i = t + 256 * r;
            int row = i >> 5, c2 = i & 31;
            *(__half2*)&sA[row * SROW + c2 * 2] = __float22half2_rn(srcA[i]);
            *(__half2*)&sW[row * SROW + c2 * 2] = __float22half2_rn(srcW[i]);
        }
    }
    __syncthreads();

    const uint32_t sAb = smem_u32(sA);
    const uint32_t sWb = smem_u32(sW);

    uint32_t af[4][4];
#pragma unroll
    for (int ks = 0; ks < 4; ks++) {
        uint32_t addr = sAb +
            2 * ((uint32_t)(warp * 16 + (lane & 15)) * SROW + ks * 16 + (lane >> 4) * 8);
        asm volatile("ldmatrix.sync.aligned.m8n8.x4.shared.b16 {%0,%1,%2,%3}, [%4];"
                     : "=r"(af[ks][0]), "=r"(af[ks][1]), "=r"(af[ks][2]), "=r"(af[ks][3])
                     : "r"(addr));
    }

    float d[16][4];
#pragma unroll
    for (int n = 0; n < 16; n++)
#pragma unroll
        for (int c = 0; c < 4; c++) d[n][c] = 0.f;

#pragma unroll
    for (int n = 0; n < 16; n++) {
#pragma unroll
        for (int ks = 0; ks < 4; ks++) {
            uint32_t b0, b1;
            uint32_t addr = sWb +
                2 * ((uint32_t)(n * 8 + (lane & 7)) * SROW + ks * 16 + ((lane >> 3) & 1) * 8);
            asm volatile("ldmatrix.sync.aligned.m8n8.x2.shared.b16 {%0,%1}, [%2];"
                         : "=r"(b0), "=r"(b1) : "r"(addr));
            asm volatile(
                "mma.sync.aligned.m16n8k16.row.col.f32.f16.f16.f32 "
                "{%0,%1,%2,%3}, {%4,%5,%6,%7}, {%8,%9}, {%0,%1,%2,%3};"
                : "+f"(d[n][0]), "+f"(d[n][1]), "+f"(d[n][2]), "+f"(d[n][3])
                : "r"(af[ks][0]), "r"(af[ks][1]), "r"(af[ks][2]), "r"(af[ks][3]),
                  "r"(b0), "r"(b1));
        }
    }

    {
        int r0 = lane >> 2, cb = (lane & 3) * 2;
        size_t base0 = (size_t)(e0 + warp * 16 + r0) * 384 + y * 128;
        size_t base1 = (size_t)(e0 + warp * 16 + r0 + 8) * 384 + y * 128;
#pragma unroll
        for (int n = 0; n < 16; n++) {
            *(__half2*)&g_fh[base0 + n * 8 + cb] = __floats2half2_rn(d[n][0], d[n][1]);
            *(__half2*)&g_fh[base1 + n * 8 + cb] = __floats2half2_rn(d[n][2], d[n][3]);
        }
    }
}

// ---------------- 4. ke: epilogue — PROFILED ----------------
__global__ __launch_bounds__(512) void ke_epi(
    const int* __restrict__ ei, const float* __restrict__ ew,
    const float* __restrict__ evec, const int* __restrict__ z,
    const float* __restrict__ b_emb2,
    const float* __restrict__ bd1, const float* __restrict__ bd2,
    const float* __restrict__ bd3) {
    __shared__ float sCut[64], sVx[64], sVy[64], sVz[64];
    __shared__ int sSrc[64], sZs[64], sZd[64], sPe[64];
    const int tid = threadIdx.x;
    const int e0 = blockIdx.x * 64;
    if (tid < 64) {
        int pe = g_perm[e0 + tid];
        sPe[tid] = pe;
        int s = ei[pe], d = ei[NE + pe];
        sSrc[tid] = s;
        sZs[tid] = z[s];
        sZd[tid] = z[d];
        float w = ew[pe];
        sCut[tid] = (w < 5.0f) ? 0.5f * (cosf(w * PI_OVER_CUT) + 1.0f) : 0.0f;
        sVx[tid] = evec[3 * pe + 0];
        sVy[tid] = evec[3 * pe + 1];
        sVz[tid] = evec[3 * pe + 2];
    }
    __syncthreads();

    const int h = tid & 127;
    const int grp = tid >> 7;
    const float bemb = b_emb2[h];
    const float b1 = bd1[h], b2 = bd2[h], b3 = bd3[h];

    float racc[10];
#pragma unroll
    for (int c = 0; c < 10; c++) racc[c] = 0.f;
    int cur = sSrc[grp * 16];

#define FLUSH()                                                  \
    do {                                                         \
        float* p_ = &g_acc[((size_t)cur * HD + h) * AS];         \
        red4(p_, racc[0], racc[1], racc[2], racc[3]);            \
        red4(p_ + 4, racc[4], racc[5], racc[6], racc[7]);        \
        red2(p_ + 8, racc[8], racc[9]);                          \
    } while (0)

#pragma unroll 2
    for (int i = 0; i < 16; i++) {
        int e = grp * 16 + i;
        int pe = sPe[e];
        int s = sSrc[e];
        const __half* fp = &g_fh[(size_t)pe * 384 + h];
        float f1 = __half2float(fp[0]);
        float f2 = __half2float(fp[128]);
        float f3 = __half2float(fp[256]);
        float C = sCut[e] * (g_ZPt[sZs[e] * HD + h] + g_ZQt[sZd[e] * HD + h] + bemb);
        f1 = (f1 + b1) * C;
        f2 = (f2 + b2) * C;
        f3 = (f3 + b3) * C;
        if (s != cur) {
            FLUSH();
#pragma unroll
            for (int c = 0; c < 10; c++) racc[c] = 0.f;
            cur = s;
        }
        float vx = sVx[e], vy = sVy[e], vz = sVz[e];
        racc[0] += f1;
        racc[1] += f2 * vx; racc[2] += f2 * vy; racc[3] += f2 * vz;
        float f3x = f3 * vx, f3y = f3 * vy, f3z = f3 * vz;
        racc[4] += f3x * vx; racc[5] += f3x * vy; racc[6] += f3x * vz;
        racc[7] += f3y * vy; racc[8] += f3y * vz; racc[9] += f3z * vz;
    }
    FLUSH();
#undef FLUSH
}

// ---------------- 5. k3: tn + LayerNorm ----------------
__global__ void k3_tnln(const float* __restrict__ ln_g, const float* __restrict__ ln_b) {
    __shared__ float sred[4];
    __shared__ float sval;
    int n = blockIdx.x, h = threadIdx.x;
    const float* a = &g_acc[((size_t)n * HD + h) * AS];
    float4 p0 = *(const float4*)a;
    float4 p1 = *(const float4*)(a + 4);
    float2 p2 = *(const float2*)(a + 8);
    float s1 = p0.x, wx = p0.y, wy = p0.z, wz = p0.w;
    float mxx = p1.x, mxy = p1.y, mxz = p1.z, myy = p1.w, myz = p2.x, mzz = p2.y;
    float tr3 = (mxx + myy + mzz) * (1.0f / 3.0f);
    float dxx = s1 + mxx - tr3, dyy = s1 + myy - tr3, dzz = s1 + mzz - tr3;
    float t01 = mxy - wz, t10 = mxy + wz, t02 = mxz + wy;
    float t20 = mxz - wy, t12 = myz - wx, t21 = myz + wx;
    float tn = dxx * dxx + dyy * dyy + dzz * dzz + t01 * t01 + t10 * t10 +
               t02 * t02 + t20 * t20 + t12 * t12 + t21 * t21;

    float v = tn;
#pragma unroll
    for (int o = 16; o; o >>= 1) v += __shfl_xor_sync(0xffffffffu, v, o);
    if ((h & 31) == 0) sred[h >> 5] = v;
    __syncthreads();
    if (h == 0) sval = (sred[0] + sred[1] + sred[2] + sred[3]) * (1.0f / HD);
    __syncthreads();
    float mu = sval;
    float dv = tn - mu;
    v = dv * dv;
#pragma unroll
    for (int o = 16; o; o >>= 1) v += __shfl_xor_sync(0xffffffffu, v, o);
    __syncthreads();
    if ((h & 31) == 0) sred[h >> 5] = v;
    __syncthreads();
    if (h == 0) sval = rsqrtf((sred[0] + sred[1] + sred[2] + sred[3]) * (1.0f / HD) + 1e-5f);
    __syncthreads();
    g_ln[(size_t)n * HD + h] = dv * sval * ln_g[h] + ln_b[h];
}

// ---------------- 6. k4a: y1h = silu(Ws1 @ ln + bs1) [20 nodes/blk] ----
__global__ __launch_bounds__(256, 3) void k4a_gemm(
    const float* __restrict__ Ws1, const float* __restrict__ bs1) {
    __shared__ float sXT[HD * 20];
    __shared__ float sW[16 * 257];
    const int t = threadIdx.x;
    const int nb = blockIdx.x * 20;
    for (int i = t; i < 20 * HD; i += 256) {
        int nl = i >> 7, hh = i & 127;
        sXT[hh * 20 + nl] = g_ln[(size_t)(nb + nl) * HD + hh];
    }
    ull acc[10];
#pragma unroll
    for (int c = 0; c < 10; c++) acc[c] = 0ull;

    for (int h0 = 0; h0 < HD; h0 += 16) {
        __syncthreads();
#pragma unroll
        for (int r = 0; r < 16; r++) {
            int i = t + 256 * r;
            int j = i >> 4, hh = i & 15;
            sW[hh * 257 + j] = Ws1[j * HD + h0 + hh];
        }
        __syncthreads();
#pragma unroll 4
        for (int hh = 0; hh < 16; hh++) {
            float w = sW[hh * 257 + t];
            ull wp = pk2(w, w);
            const ulonglong2* xp = (const ulonglong2*)&sXT[(h0 + hh) * 20];
            ulonglong2 x0 = xp[0], x1 = xp[1];
            ulonglong2 x2 = xp[2], x3 = xp[3];
            ulonglong2 x4 = xp[4];
            acc[0] = fma2(wp, x0.x, acc[0]);
            acc[1] = fma2(wp, x0.y, acc[1]);
            acc[2] = fma2(wp, x1.x, acc[2]);
            acc[3] = fma2(wp, x1.y, acc[3]);
            acc[4] = fma2(wp, x2.x, acc[4]);
            acc[5] = fma2(wp, x2.y, acc[5]);
            acc[6] = fma2(wp, x3.x, acc[6]);
            acc[7] = fma2(wp, x3.y, acc[7]);
            acc[8] = fma2(wp, x4.x, acc[8]);
            acc[9] = fma2(wp, x4.y, acc[9]);
        }
    }
    float bb = bs1[t];
#pragma unroll
    for (int c = 0; c < 10; c++) {
        float a0, a1;
        unpk2(acc[c], a0, a1);
        g_y1h[(size_t)(nb + 2 * c) * 256 + t]     = __float2half(silu_f(a0 + bb));
        g_y1h[(size_t)(nb + 2 * c + 1) * 256 + t] = __float2half(silu_f(a1 + bb));
    }
}

// ---------------- 7. k4b_hmma: nrm = silu(Ws2 @ y1 + bs2) via HMMA ----------------
// grid (40, 3): x = node tile (128), y = j tile (128). K = 256 in 4 chunks.
__global__ __launch_bounds__(256) void k4b_hmma(const float* __restrict__ bs2) {
    __shared__ __half sA[128 * SROW];   // Ws2 j x k chunk
    __shared__ __half sB[128 * SROW];   // y1 node x k chunk
    const int t = threadIdx.x;
    const int warp = t >> 5, lane = t & 31;
    const int nt0 = blockIdx.x * 128;
    const int jt0 = blockIdx.y * 128;

    const uint32_t sAb = smem_u32(sA);
    const uint32_t sBb = smem_u32(sB);

    float d[16][4];
#pragma unroll
    for (int n = 0; n < 16; n++)
#pragma unroll
        for (int c = 0; c < 4; c++) d[n][c] = 0.f;

    for (int kc = 0; kc < 4; kc++) {
        __syncthreads();
#pragma unroll
        for (int r = 0; r < 4; r++) {
            int i = t + 256 * r;           // uint4 units (8 halves), 0..1023
            int row = i >> 3, c8 = (i & 7) * 8;
            *(uint4*)&sA[row * SROW + c8] =
                *(const uint4*)&g_ws2h[(size_t)(jt0 + row) * 256 + kc * 64 + c8];
            int node = nt0 + row;
            uint4 v = make_uint4(0u, 0u, 0u, 0u);
            if (node < NN)
                v = *(const uint4*)&g_y1h[(size_t)node * 256 + kc * 64 + c8];
            *(uint4*)&sB[row * SROW + c8] = v;
        }
        __syncthreads();

#pragma unroll
        for (int ks = 0; ks < 4; ks++) {
            uint32_t af[4];
            uint32_t addr = sAb +
                2 * ((uint32_t)(warp * 16 + (lane & 15)) * SROW + ks * 16 + (lane >> 4) * 8);
            asm volatile("ldmatrix.sync.aligned.m8n8.x4.shared.b16 {%0,%1,%2,%3}, [%4];"
                         : "=r"(af[0]), "=r"(af[1]), "=r"(af[2]), "=r"(af[3]) : "r"(addr));
#pragma unroll
            for (int n = 0; n < 16; n++) {
                uint32_t b0, b1;
                uint32_t baddr = sBb +
                    2 * ((uint32_t)(n * 8 + (lane & 7)) * SROW + ks * 16 + ((lane >> 3) & 1) * 8);
                asm volatile("ldmatrix.sync.aligned.m8n8.x2.shared.b16 {%0,%1}, [%2];"
                             : "=r"(b0), "=r"(b1) : "r"(baddr));
                asm volatile(
                    "mma.sync.aligned.m16n8k16.row.col.f32.f16.f16.f32 "
                    "{%0,%1,%2,%3}, {%4,%5,%6,%7}, {%8,%9}, {%0,%1,%2,%3};"
                    : "+f"(d[n][0]), "+f"(d[n][1]), "+f"(d[n][2]), "+f"(d[n][3])
                    : "r"(af[0]), "r"(af[1]), "r"(af[2]), "r"(af[3]), "r"(b0), "r"(b1));
            }
        }
    }

    // epilogue: d[n][0]=(j0,node0) d[n][1]=(j0,node0+1) d[n][2]=(j0+8,node0) d[n][3]=(j0+8,node0+1)
    {
        int r0 = lane >> 2, cb = (lane & 3) * 2;
        int j0 = jt0 + warp * 16 + r0;
        float bb0 = bs2[j0], bb1 = bs2[j0 + 8];
#pragma unroll
        for (int n = 0; n < 16; n++) {
            int node0 = nt0 + n * 8 + cb;
            if (node0 < NN) {
                g_nrm[(size_t)node0 * 384 + j0]     = silu_f(d[n][0] + bb0);
                g_nrm[(size_t)node0 * 384 + j0 + 8] = silu_f(d[n][2] + bb1);
            }
            if (node0 + 1 < NN) {
                g_nrm[(size_t)(node0 + 1) * 384 + j0]     = silu_f(d[n][1] + bb0);
                g_nrm[(size_t)(node0 + 1) * 384 + j0 + 8] = silu_f(d[n][3] + bb1);
            }
        }
    }
}

// ---------------- 8. k5: Wt transforms + output (2g x 2nl tile) ----
__global__ __launch_bounds__(256, 2) void k5_out(
    const float* __restrict__ Wt1, const float* __restrict__ Wt2,
    const float* __restrict__ Wt3, float* __restrict__ out) {
    extern __shared__ float sm[];
    float* sAcc = sm;                // [8][128][12]
    float* sWt  = sm + 8 * HD * AS;  // [8][390]
    int t  = threadIdx.x;
    int nb = blockIdx.x * 8;
    {
        float4* gsrc = (float4*)&g_acc[(size_t)nb * HD * AS];
        float4* dst = (float4*)sAcc;
        for (int i = t; i < 8 * HD * 3; i += 256) dst[i] = gsrc[i];
        __syncthreads();
        float4 zz = make_float4(0.f, 0.f, 0.f, 0.f);
        for (int i = t; i < 8 * HD * 3; i += 256) gsrc[i] = zz;
    }

    const int g0 = (t & 63) * 2;
    const int n0 = (t >> 6) * 2;

    ull acc[2][2][5];
#pragma unroll
    for (int gi = 0; gi < 2; gi++)
#pragma unroll
        for (int ni = 0; ni < 2; ni++)
#pragma unroll
            for (int c = 0; c < 5; c++) acc[gi][ni][c] = 0ull;

    for (int h0 = 0; h0 < HD; h0 += 8) {
        __syncthreads();
#pragma unroll
        for (int r = 0; r < 12; r++) {
            int i = t + 256 * r;
            int m = i >> 10;
            int rr = i & 1023;
            int gg = rr >> 3, hh = rr & 7;
            const float* W = (m == 0) ? Wt1 : ((m == 1) ? Wt2 : Wt3);
            sWt[hh * 390 + m * 128 + gg] = W[gg * HD + h0 + hh];
        }
        __syncthreads();
#pragma unroll
        for (int hh = 0; hh < 8; hh++) {
            const float* wrow = &sWt[hh * 390];
            float2 w1 = *(const float2*)&wrow[g0];
            float2 w2 = *(const float2*)&wrow[128 + g0];
            float2 w3 = *(const float2*)&wrow[256 + g0];
            ull pw12a = pk2(w1.x, w2.x), pw22a = pk2(w2.x, w2.x), pw33a = pk2(w3.x, w3.x);
            ull pw12b = pk2(w1.y, w2.y), pw22b = pk2(w2.y, w2.y), pw33b = pk2(w3.y, w3.y);
#pragma unroll
            for (int ni = 0; ni < 2; ni++) {
                const ull* ap = (const ull*)&sAcc[((n0 + ni) * HD + h0 + hh) * AS];
                ulonglong2 q0 = *(const ulonglong2*)ap;
                ulonglong2 q1 = *(const ulonglong2*)(ap + 2);
                ull q2 = ap[4];
                acc[0][ni][0] = fma2(pw12a, q0.x, acc[0][ni][0]);
                acc[0][ni][1] = fma2(pw22a, q0.y, acc[0][ni][1]);
                acc[0][ni][2] = fma2(pw33a, q1.x, acc[0][ni][2]);
                acc[0][ni][3] = fma2(pw33a, q1.y, acc[0][ni][3]);
                acc[0][ni][4] = fma2(pw33a, q2,   acc[0][ni][4]);
                acc[1][ni][0] = fma2(pw12b, q0.x, acc[1][ni][0]);
                acc[1][ni][1] = fma2(pw22b, q0.y, acc[1][ni][1]);
                acc[1][ni][2] = fma2(pw33b, q1.x, acc[1][ni][2]);
                acc[1][ni][3] = fma2(pw33b, q1.y, acc[1][ni][3]);
                acc[1][ni][4] = fma2(pw33b, q2,   acc[1][ni][4]);
            }
        }
    }

#pragma unroll
    for (int gi = 0; gi < 2; gi++)
#pragma unroll
    for (int ni = 0; ni < 2; ni++) {
        int n = nb + n0 + ni;
        int g = g0 + gi;
        float nr0 = g_nrm[(size_t)n * 384 + g * 3 + 0];
        float nr1 = g_nrm[(size_t)n * 384 + g * 3 + 1];
        float nr2 = g_nrm[(size_t)n * 384 + g * 3 + 2];
        float s1, wx, wy, wz, mxx, mxy, mxz, myy, myz, mzz;
        unpk2(acc[gi][ni][0], s1, wx);
        unpk2(acc[gi][ni][1], wy, wz);
        unpk2(acc[gi][ni][2], mxx, mxy);
        unpk2(acc[gi][ni][3], mxz, myy);
        unpk2(acc[gi][ni][4], myz, mzz);
        float tr3 = (mxx + myy + mzz) * (1.0f / 3.0f);
        float dI = nr0 * s1;
        float* o = out + ((size_t)n * HD + g) * 9;
        o[0] = dI + nr2 * (mxx - tr3);
        o[1] = -nr1 * wz + nr2 * mxy;
        o[2] =  nr1 * wy + nr2 * mxz;
        o[3] =  nr1 * wz + nr2 * mxy;
        o[4] = dI + nr2 * (myy - tr3);
        o[5] = -nr1 * wx + nr2 * myz;
        o[6] = -nr1 * wy + nr2 * mxz;
        o[7] =  nr1 * wx + nr2 * myz;
        o[8] = dI + nr2 * (mzz - tr3);
    }
}

#define K5_SMEM ((8 * HD * AS + 8 * 390) * 4)

extern "C" void kernel_launch(void* const* d_in, const int* in_sizes, int n_in,
                              void* d_out, int out_size) {
    (void)in_sizes; (void)n_in; (void)out_size;
    const int*   z      = (const int*)d_in[0];
    const int*   ei     = (const int*)d_in[1];
    const float* ew     = (const float*)d_in[2];
    const float* evec   = (const float*)d_in[3];
    const float* eattr  = (const float*)d_in[4];
    const float* emb    = (const float*)d_in[5];
    const float* W_emb2 = (const float*)d_in[6];
    const float* b_emb2 = (const float*)d_in[7];
    const float* Wd1 = (const float*)d_in[8],  *bd1 = (const float*)d_in[9];
    const float* Wd2 = (const float*)d_in[10], *bd2 = (const float*)d_in[11];
    const float* Wd3 = (const float*)d_in[12], *bd3 = (const float*)d_in[13];
    const float* Wt1 = (const float*)d_in[14], *Wt2 = (const float*)d_in[15];
    const float* Wt3 = (const float*)d_in[16];
    const float* Ws1 = (const float*)d_in[17], *bs1 = (const float*)d_in[18];
    const float* Ws2 = (const float*)d_in[19], *bs2 = (const float*)d_in[20];
    const float* ln_g = (const float*)d_in[21], *ln_b = (const float*)d_in[22];
    float* out = (float*)d_out;

    cudaFuncSetAttribute(k5_out, cudaFuncAttributeMaxDynamicSharedMemorySize, K5_SMEM);

    kA_histT<<<189, 512>>>(ei, W_emb2);                                 // 1
    kB_multi<<<57, 1024>>>(emb, Ws2);                                   // 2
    kg_hmma<<<dim3(NE / 128, 3), 256>>>(eattr, Wd1, Wd2, Wd3, ei);      // 3
    ke_epi<<<NE / 64, 512>>>(ei, ew, evec, z, b_emb2, bd1, bd2, bd3);   // 4 <- PROFILED
    k3_tnln<<<NN, 128>>>(ln_g, ln_b);                                   // 5
    k4a_gemm<<<NN / 20, 256>>>(Ws1, bs1);                               // 6
    k4b_hmma<<<dim3(40, 3), 256>>>(bs2);                                // 7
    k5_out<<<NN / 8, 256, K5_SMEM>>>(Wt1, Wt2, Wt3, out);               // 8
}